// round 12
// baseline (speedup 1.0000x reference)
#include <cuda_runtime.h>
#include <cuda_fp16.h>
#include <math.h>
#include <stdint.h>

#define BATCH   2
#define SEQ     1024
#define NROWS   (BATCH * SEQ)
#define DMODEL  1024
#define NHEAD   16
#define HDIM    64
#define TDIM    1024
#define FFDIM   4096
#define NLAYER  8
#define VOCAB   32000

#define WU16  0
#define WO16  25165824u
#define F116  33554432u
#define F216  67108864u
#define EMB16 100663296u
#define W16_TOTAL 133431296u

__device__ float  g_x [NROWS * DMODEL];
__device__ float2 g_rope[SEQ * 32];
__device__ __half g_u16 [NROWS * 3 * TDIM];
__device__ __half g_xn16[NROWS * DMODEL];
__device__ __half g_at16[NROWS * TDIM];
__device__ __half g_h16 [NROWS * FFDIM];
__device__ __half g_w16 [W16_TOTAL];

__device__ __forceinline__ float gelu_exact(float v) {
    return 0.5f * v * (1.0f + erff(v * 0.70710678118654752440f));
}
__device__ __forceinline__ uint32_t s2u(const void* p) {
    uint32_t a;
    asm("{ .reg .u64 t; cvta.to.shared.u64 t, %1; cvt.u32.u64 %0, t; }" : "=r"(a) : "l"(p));
    return a;
}
__device__ __forceinline__ void cp16(uint32_t s, const void* g) {
    asm volatile("cp.async.cg.shared.global [%0], [%1], 16;" :: "r"(s), "l"(g));
}
__device__ __forceinline__ void ldsm4(unsigned* r, uint32_t a) {
    asm volatile("ldmatrix.sync.aligned.m8n8.x4.shared.b16 {%0,%1,%2,%3}, [%4];"
        : "=r"(r[0]), "=r"(r[1]), "=r"(r[2]), "=r"(r[3]) : "r"(a));
}
__device__ __forceinline__ void ldsm4t(unsigned* r, uint32_t a) {
    asm volatile("ldmatrix.sync.aligned.m8n8.x4.trans.shared.b16 {%0,%1,%2,%3}, [%4];"
        : "=r"(r[0]), "=r"(r[1]), "=r"(r[2]), "=r"(r[3]) : "r"(a));
}
__device__ __forceinline__ void mma_f16(float* c, const unsigned* a, const unsigned* b) {
    asm volatile(
        "mma.sync.aligned.m16n8k16.row.col.f32.f16.f16.f32 "
        "{%0,%1,%2,%3},{%4,%5,%6,%7},{%8,%9},{%0,%1,%2,%3};"
        : "+f"(c[0]), "+f"(c[1]), "+f"(c[2]), "+f"(c[3])
        : "r"(a[0]), "r"(a[1]), "r"(a[2]), "r"(a[3]), "r"(b[0]), "r"(b[1]));
}
__device__ __forceinline__ void rot(float& a, float& b, float2 cs) {
    const float t0 = a * cs.x - b * cs.y;
    b = b * cs.x + a * cs.y;
    a = t0;
}
__device__ __forceinline__ unsigned packh2(float a, float b) {
    __half2 h = __floats2half2_rn(a, b);
    return *(unsigned*)&h;
}

// ---------------------------------------------------------------------------
// fp16 GEMM 128x128 (proven config): C = A @ B^T
// MODE 0: fp32 C   MODE 1: gelu(acc+bias)->fp16   MODE 2: acc(+bias)+resid->fp32
// MODE 3: rope(acc) via table -> fp16 C16 (QKV)
// ---------------------------------------------------------------------------
template<int MODE>
__global__ __launch_bounds__(256)
void gemm_f16(const __half* __restrict__ A, const __half* __restrict__ B,
              const float* __restrict__ bias, const float* __restrict__ resid,
              float* __restrict__ C, __half* __restrict__ C16,
              const float2* __restrict__ tab, int N, int K)
{
    extern __shared__ __align__(128) char smem[];
    const uint32_t sb = s2u(smem);
    const int tid = threadIdx.x, warp = tid >> 5, lane = tid & 31;
    const int bm = blockIdx.y * 128, bn = blockIdx.x * 128;
    const int moff = (warp & 3) * 32, noff = (warp >> 2) * 64;
    const int g = lane >> 2, t = lane & 3;
    const int nk = K >> 5;
    const int lrow = tid >> 2, lc = tid & 3;

    float acc[2][8][4];
#pragma unroll
    for (int mi = 0; mi < 2; mi++)
#pragma unroll
        for (int ni = 0; ni < 8; ni++)
#pragma unroll
            for (int e = 0; e < 4; e++) acc[mi][ni][e] = 0.0f;

#define LOADST(st, ks) do { \
    const uint32_t so = sb + (uint32_t)(st) * 20480u; \
    const __half* gA = A + (size_t)(bm + lrow) * K + (ks) * 32 + lc * 8; \
    const __half* gB = B + (size_t)(bn + lrow) * K + (ks) * 32 + lc * 8; \
    const uint32_t sA = so + lrow * 80 + lc * 16; \
    const uint32_t sB = sA + 10240u; \
    cp16(sA, gA); cp16(sB, gB); \
    cp16(sA + 64 * 80, gA + (size_t)64 * K); \
    cp16(sB + 64 * 80, gB + (size_t)64 * K); \
} while (0)

    LOADST(0, 0);
    asm volatile("cp.async.commit_group;" ::: "memory");
    if (nk > 1) LOADST(1, 1);
    asm volatile("cp.async.commit_group;" ::: "memory");

    const uint32_t aoff = (uint32_t)((moff + (lane & 15)) * 80 + ((lane >> 4) & 1) * 16);
    const uint32_t boff = 10240u +
        (uint32_t)((noff + (lane & 7) + ((lane >> 4) & 1) * 8) * 80 + ((lane >> 3) & 1) * 16);

    for (int ks = 0; ks < nk; ks++) {
        asm volatile("cp.async.wait_group %0;" :: "n"(1) : "memory");
        __syncthreads();
        if (ks + 2 < nk) { LOADST((ks + 2) % 3, ks + 2); }
        asm volatile("cp.async.commit_group;" ::: "memory");

        const uint32_t so = sb + (uint32_t)(ks % 3) * 20480u;
#pragma unroll
        for (int kk = 0; kk < 2; kk++) {
            unsigned a0[4], a1[4], b[4][4];
            ldsm4(a0, so + aoff + kk * 32);
            ldsm4(a1, so + aoff + 16 * 80 + kk * 32);
#pragma unroll
            for (int nj = 0; nj < 4; nj++)
                ldsm4(b[nj], so + boff + nj * 16 * 80 + kk * 32);
#pragma unroll
            for (int nj = 0; nj < 4; nj++) {
                mma_f16(acc[0][2 * nj],     a0, &b[nj][0]);
                mma_f16(acc[0][2 * nj + 1], a0, &b[nj][2]);
                mma_f16(acc[1][2 * nj],     a1, &b[nj][0]);
                mma_f16(acc[1][2 * nj + 1], a1, &b[nj][2]);
            }
        }
    }
#undef LOADST

    if (MODE == 3) {
        const int region = (bn + noff) >> 10;
        if (region < 2) {
#pragma unroll
            for (int mi = 0; mi < 2; mi++) {
                const int r0 = bm + moff + 16 * mi + g;
                const int s0 = r0 & (SEQ - 1);
#pragma unroll
                for (int ni = 0; ni < 4; ni++) {
                    const int i0 = 8 * ni + 2 * t;
                    const float2 c00 = tab[s0 * 32 + i0];
                    const float2 c01 = tab[s0 * 32 + i0 + 1];
                    const float2 c10 = tab[(s0 + 8) * 32 + i0];
                    const float2 c11 = tab[(s0 + 8) * 32 + i0 + 1];
                    rot(acc[mi][ni][0], acc[mi][ni + 4][0], c00);
                    rot(acc[mi][ni][1], acc[mi][ni + 4][1], c01);
                    rot(acc[mi][ni][2], acc[mi][ni + 4][2], c10);
                    rot(acc[mi][ni][3], acc[mi][ni + 4][3], c11);
                }
            }
        }
    }

#pragma unroll
    for (int mi = 0; mi < 2; mi++) {
        const int r0 = bm + moff + 16 * mi + g;
#pragma unroll
        for (int ni = 0; ni < 8; ni++) {
            const int c = bn + noff + 8 * ni + 2 * t;
            float v00 = acc[mi][ni][0], v01 = acc[mi][ni][1];
            float v10 = acc[mi][ni][2], v11 = acc[mi][ni][3];
            if (MODE == 1 || MODE == 3) {
                if (MODE == 1) {
                    const float b0 = bias[c], b1 = bias[c + 1];
                    v00 = gelu_exact(v00 + b0); v01 = gelu_exact(v01 + b1);
                    v10 = gelu_exact(v10 + b0); v11 = gelu_exact(v11 + b1);
                }
                *(__half2*)(C16 + (size_t)r0 * N + c)       = __floats2half2_rn(v00, v01);
                *(__half2*)(C16 + (size_t)(r0 + 8) * N + c) = __floats2half2_rn(v10, v11);
            } else {
                if (MODE == 2) {
                    if (bias) {
                        const float b0 = bias[c], b1 = bias[c + 1];
                        v00 += b0; v01 += b1; v10 += b0; v11 += b1;
                    }
                    const float2 rr0 = *(const float2*)(resid + (size_t)r0 * N + c);
                    const float2 rr1 = *(const float2*)(resid + (size_t)(r0 + 8) * N + c);
                    v00 += rr0.x; v01 += rr0.y; v10 += rr1.x; v11 += rr1.y;
                }
                float2 o0; o0.x = v00; o0.y = v01;
                float2 o1; o1.x = v10; o1.y = v11;
                *(float2*)(C + (size_t)r0 * N + c) = o0;
                *(float2*)(C + (size_t)(r0 + 8) * N + c) = o1;
            }
        }
    }
}
#define GEMM_SMEM (3 * 20480)

// ---------------------------------------------------------------------------
// fp16 GEMM 64x128 (wave-quantization fix for N=1024 GEMMs, MODE2 semantics):
// C = A @ B^T (+bias) + resid -> fp32. Tile 64x128, warp tile 16x64.
// grid (N/128, M/64), 256 threads. Same per-element math as gemm_f16.
// ---------------------------------------------------------------------------
#define G64_STAGE 15360u
#define G64_SMEM  (3 * 15360)
__global__ __launch_bounds__(256)
void gemm64(const __half* __restrict__ A, const __half* __restrict__ B,
            const float* __restrict__ bias, const float* __restrict__ resid,
            float* __restrict__ C, int N, int K)
{
    extern __shared__ __align__(128) char smem[];
    const uint32_t sb = s2u(smem);
    const int tid = threadIdx.x, warp = tid >> 5, lane = tid & 31;
    const int bm = blockIdx.y * 64, bn = blockIdx.x * 128;
    const int wm = warp & 3, wn = warp >> 2;
    const int g = lane >> 2, t = lane & 3;
    const int nk = K >> 5;
    const int lrow = tid >> 2, lc = tid & 3;

    float acc[8][4];
#pragma unroll
    for (int ni = 0; ni < 8; ni++)
#pragma unroll
        for (int e = 0; e < 4; e++) acc[ni][e] = 0.0f;

#define LOADST64(st, ks) do { \
    const uint32_t so = sb + (uint32_t)(st) * G64_STAGE; \
    const __half* gA = A + (size_t)(bm + lrow) * K + (ks) * 32 + lc * 8; \
    const __half* gB = B + (size_t)(bn + lrow) * K + (ks) * 32 + lc * 8; \
    const uint32_t sA = so + lrow * 80 + lc * 16; \
    const uint32_t sB = so + 5120u + lrow * 80 + lc * 16; \
    cp16(sA, gA); \
    cp16(sB, gB); \
    cp16(sB + 64 * 80, gB + (size_t)64 * K); \
} while (0)

    LOADST64(0, 0);
    asm volatile("cp.async.commit_group;" ::: "memory");
    if (nk > 1) LOADST64(1, 1);
    asm volatile("cp.async.commit_group;" ::: "memory");

    const uint32_t aoff = (uint32_t)((wm * 16 + (lane & 15)) * 80 + ((lane >> 4) & 1) * 16);
    const uint32_t boff = 5120u +
        (uint32_t)((wn * 64 + (lane & 7) + ((lane >> 4) & 1) * 8) * 80 + ((lane >> 3) & 1) * 16);

    for (int ks = 0; ks < nk; ks++) {
        asm volatile("cp.async.wait_group %0;" :: "n"(1) : "memory");
        __syncthreads();
        if (ks + 2 < nk) { LOADST64((ks + 2) % 3, ks + 2); }
        asm volatile("cp.async.commit_group;" ::: "memory");

        const uint32_t so = sb + (uint32_t)(ks % 3) * G64_STAGE;
#pragma unroll
        for (int kk = 0; kk < 2; kk++) {
            unsigned a0[4], b[4][4];
            ldsm4(a0, so + aoff + kk * 32);
#pragma unroll
            for (int nj = 0; nj < 4; nj++)
                ldsm4(b[nj], so + boff + nj * 16 * 80 + kk * 32);
#pragma unroll
            for (int nj = 0; nj < 4; nj++) {
                mma_f16(acc[2 * nj],     a0, &b[nj][0]);
                mma_f16(acc[2 * nj + 1], a0, &b[nj][2]);
            }
        }
    }
#undef LOADST64

    const int r0 = bm + wm * 16 + g;
#pragma unroll
    for (int ni = 0; ni < 8; ni++) {
        const int c = bn + wn * 64 + 8 * ni + 2 * t;
        float v00 = acc[ni][0], v01 = acc[ni][1];
        float v10 = acc[ni][2], v11 = acc[ni][3];
        if (bias) {
            const float b0 = bias[c], b1 = bias[c + 1];
            v00 += b0; v01 += b1; v10 += b0; v11 += b1;
        }
        const float2 rr0 = *(const float2*)(resid + (size_t)r0 * N + c);
        const float2 rr1 = *(const float2*)(resid + (size_t)(r0 + 8) * N + c);
        v00 += rr0.x; v01 += rr0.y; v10 += rr1.x; v11 += rr1.y;
        float2 o0; o0.x = v00; o0.y = v01;
        float2 o1; o1.x = v10; o1.y = v11;
        *(float2*)(C + (size_t)r0 * N + c) = o0;
        *(float2*)(C + (size_t)(r0 + 8) * N + c) = o1;
    }
}

// ---------------------------------------------------------------------------
// MMA flash attention v3 (unchanged)
// ---------------------------------------------------------------------------
#define ATTN_SMEM (128 * 144 + 4 * 64 * 144)
__global__ __launch_bounds__(256, 2)
void attn_mma(const __half* __restrict__ U, __half* __restrict__ O)
{
    const int q0 = blockIdx.x * 128, h = blockIdx.y, b = blockIdx.z;
    const int tid = threadIdx.x, warp = tid >> 5, lane = tid & 31;
    const int g = lane >> 2, t = lane & 3;

    extern __shared__ __align__(128) char asm_[];
    const uint32_t qb = s2u(asm_);
    const uint32_t kb0 = qb + 128 * 144;
    const uint32_t vb0 = kb0 + 2 * 64 * 144;

    const __half* Ub = U + (size_t)(b * SEQ) * 3072 + h * 64;

    {
        const int r = tid >> 1;
        const int sg = (tid & 1) * 64;
        const __half* gq = Ub + (size_t)(q0 + r) * 3072 + sg / 2;
        const uint32_t sq = qb + r * 144 + sg;
        cp16(sq, gq); cp16(sq + 16, gq + 8);
        cp16(sq + 32, gq + 16); cp16(sq + 48, gq + 24);
    }
    asm volatile("cp.async.commit_group;" ::: "memory");
    asm volatile("cp.async.wait_group 0;" ::: "memory");
    __syncthreads();

    unsigned qf[4][4];
    {
        const uint32_t qa = qb + (16 * warp + (lane & 15)) * 144 + ((lane >> 4) & 1) * 16;
        const __half2 sc = __floats2half2_rn(0.125f, 0.125f);
#pragma unroll
        for (int kk = 0; kk < 4; kk++) {
            ldsm4(qf[kk], qa + kk * 32);
#pragma unroll
            for (int e = 0; e < 4; e++) {
                __half2 v = *(__half2*)&qf[kk][e];
                v = __hmul2(v, sc);
                qf[kk][e] = *(unsigned*)&v;
            }
        }
    }

    float o[8][4];
#pragma unroll
    for (int d = 0; d < 8; d++)
#pragma unroll
        for (int e = 0; e < 4; e++) o[d][e] = 0.0f;
    float m0 = -1e30f, m1 = -1e30f, l0 = 0.0f, l1 = 0.0f;
    const int wbase = q0 + 16 * warp;
    const int row0 = wbase + g;
    const int nch = (q0 >> 6) + 2;

#define LOADKV(ci) do { \
    const int _c0 = (ci) * 64; \
    const int _bf = (ci) & 1; \
    const int tt = tid & 127; \
    const int r = tt >> 1, sgh = (tt & 1) * 32; \
    const __half* gp = Ub + (size_t)(_c0 + r) * 3072 + ((tid >= 128) ? 2048 : 1024) + sgh; \
    const uint32_t sp = ((tid >= 128) ? vb0 : kb0) + _bf * (64 * 144) + r * 144 + sgh * 2; \
    cp16(sp, gp); cp16(sp + 16, gp + 8); \
    cp16(sp + 32, gp + 16); cp16(sp + 48, gp + 24); \
} while (0)

    LOADKV(0);
    asm volatile("cp.async.commit_group;" ::: "memory");

    for (int ci = 0; ci < nch; ci++) {
        const int c0 = ci * 64;
        const bool pre = (ci + 1 < nch);
        if (pre) {
            LOADKV(ci + 1);
            asm volatile("cp.async.commit_group;" ::: "memory");
            asm volatile("cp.async.wait_group 1;" ::: "memory");
        } else {
            asm volatile("cp.async.wait_group 0;" ::: "memory");
        }
        __syncthreads();

        const uint32_t kb = kb0 + (ci & 1) * (64 * 144);
        const uint32_t vb = vb0 + (ci & 1) * (64 * 144);

        float s[8][4];
#pragma unroll
        for (int j = 0; j < 8; j++)
#pragma unroll
            for (int e = 0; e < 4; e++) s[j][e] = 0.0f;
#pragma unroll
        for (int kk = 0; kk < 4; kk++) {
            unsigned bf[4][4];
#pragma unroll
            for (int nj = 0; nj < 4; nj++)
                ldsm4(bf[nj], kb + (nj * 16 + (lane & 7) + ((lane >> 4) & 1) * 8) * 144
                                + ((lane >> 3) & 1) * 16 + kk * 32);
#pragma unroll
            for (int nj = 0; nj < 4; nj++) {
                mma_f16(s[2 * nj],     qf[kk], &bf[nj][0]);
                mma_f16(s[2 * nj + 1], qf[kk], &bf[nj][2]);
            }
        }

        if (c0 + 63 > wbase) {
#pragma unroll
            for (int j = 0; j < 8; j++) {
                const int cb = c0 + 8 * j + 2 * t;
                if (cb     > row0)     s[j][0] = -1e30f;
                if (cb + 1 > row0)     s[j][1] = -1e30f;
                if (cb     > row0 + 8) s[j][2] = -1e30f;
                if (cb + 1 > row0 + 8) s[j][3] = -1e30f;
            }
        }

        float cm0 = -1e30f, cm1 = -1e30f;
#pragma unroll
        for (int j = 0; j < 8; j++) {
            cm0 = fmaxf(cm0, fmaxf(s[j][0], s[j][1]));
            cm1 = fmaxf(cm1, fmaxf(s[j][2], s[j][3]));
        }
        cm0 = fmaxf(cm0, __shfl_xor_sync(0xffffffff, cm0, 1));
        cm0 = fmaxf(cm0, __shfl_xor_sync(0xffffffff, cm0, 2));
        cm1 = fmaxf(cm1, __shfl_xor_sync(0xffffffff, cm1, 1));
        cm1 = fmaxf(cm1, __shfl_xor_sync(0xffffffff, cm1, 2));
        const float nm0 = fmaxf(m0, cm0), nm1 = fmaxf(m1, cm1);
        const float f0 = __expf(m0 - nm0), f1 = __expf(m1 - nm1);
        m0 = nm0; m1 = nm1;

        unsigned pf[4][4];
        float sum0 = 0.0f, sum1 = 0.0f;
#pragma unroll
        for (int nj = 0; nj < 4; nj++) {
            const float pa0 = __expf(s[2 * nj][0] - nm0), pa1 = __expf(s[2 * nj][1] - nm0);
            const float pa2 = __expf(s[2 * nj][2] - nm1), pa3 = __expf(s[2 * nj][3] - nm1);
            const float pb0 = __expf(s[2 * nj + 1][0] - nm0), pb1 = __expf(s[2 * nj + 1][1] - nm0);
            const float pb2 = __expf(s[2 * nj + 1][2] - nm1), pb3 = __expf(s[2 * nj + 1][3] - nm1);
            sum0 += pa0 + pa1 + pb0 + pb1;
            sum1 += pa2 + pa3 + pb2 + pb3;
            pf[nj][0] = packh2(pa0, pa1);
            pf[nj][1] = packh2(pa2, pa3);
            pf[nj][2] = packh2(pb0, pb1);
            pf[nj][3] = packh2(pb2, pb3);
        }
        sum0 += __shfl_xor_sync(0xffffffff, sum0, 1);
        sum0 += __shfl_xor_sync(0xffffffff, sum0, 2);
        sum1 += __shfl_xor_sync(0xffffffff, sum1, 1);
        sum1 += __shfl_xor_sync(0xffffffff, sum1, 2);
        l0 = l0 * f0 + sum0;
        l1 = l1 * f1 + sum1;

#pragma unroll
        for (int d = 0; d < 8; d++) {
            o[d][0] *= f0; o[d][1] *= f0; o[d][2] *= f1; o[d][3] *= f1;
        }

#pragma unroll
        for (int kk = 0; kk < 4; kk++) {
            unsigned vf[4][4];
#pragma unroll
            for (int dj = 0; dj < 4; dj++)
                ldsm4t(vf[dj], vb + (kk * 16 + (lane & 7) + ((lane >> 3) & 1) * 8) * 144
                                 + (dj * 16 + ((lane >> 4) & 1) * 8) * 2);
#pragma unroll
            for (int dj = 0; dj < 4; dj++) {
                mma_f16(o[2 * dj],     pf[kk], &vf[dj][0]);
                mma_f16(o[2 * dj + 1], pf[kk], &vf[dj][2]);
            }
        }
        __syncthreads();
    }
#undef LOADKV

    const float il0 = 1.0f / l0, il1 = 1.0f / l1;
    __half* Ob = O + (size_t)(b * SEQ + row0) * TDIM + h * 64;
#pragma unroll
    for (int dj = 0; dj < 8; dj++) {
        const int c = 8 * dj + 2 * t;
        *(__half2*)(Ob + c)            = __floats2half2_rn(o[dj][0] * il0, o[dj][1] * il0);
        *(__half2*)(Ob + 8 * TDIM + c) = __floats2half2_rn(o[dj][2] * il1, o[dj][3] * il1);
    }
}

// ---------------------------------------------------------------------------
__global__ void conv16(const float* __restrict__ s, __half* __restrict__ d, int n4)
{
    for (int i = blockIdx.x * blockDim.x + threadIdx.x; i < n4; i += gridDim.x * blockDim.x) {
        const float4 v = ((const float4*)s)[i];
        ((__half2*)d)[2 * i]     = __floats2half2_rn(v.x, v.y);
        ((__half2*)d)[2 * i + 1] = __floats2half2_rn(v.z, v.w);
    }
}

__global__ void prep_kernel(const int* __restrict__ ids, const float* __restrict__ emb,
                            float* __restrict__ x, float2* __restrict__ tab,
                            const float* __restrict__ Wu, __half* __restrict__ wu16)
{
    if (blockIdx.x < NROWS) {
        ((float4*)(x + (size_t)blockIdx.x * DMODEL))[threadIdx.x] =
            ((const float4*)(emb + (size_t)ids[blockIdx.x] * DMODEL))[threadIdx.x];
    } else if (blockIdx.x < NROWS + 128) {
        const int idx = (blockIdx.x - NROWS) * 256 + threadIdx.x;
        const int s = idx >> 5, i = idx & 31;
        const float inv = exp2f(-(float)(2 * i) * (1.0f / 64.0f) * 13.287712379549449f);
        float sn, cs;
        sincosf((float)s * inv, &sn, &cs);
        tab[idx] = make_float2(cs, sn);
    } else {
        const int n4 = NLAYER * 3 * TDIM * DMODEL / 4;
        for (int i = (blockIdx.x - NROWS - 128) * 256 + threadIdx.x; i < n4; i += 2048 * 256) {
            const float4 v = ((const float4*)Wu)[i];
            ((__half2*)wu16)[2 * i]     = __floats2half2_rn(v.x, v.y);
            ((__half2*)wu16)[2 * i + 1] = __floats2half2_rn(v.z, v.w);
        }
    }
}

// warp-per-row LayerNorm -> fp16
__global__ __launch_bounds__(256)
void layernorm_kernel(const float* __restrict__ x, const float* __restrict__ w,
                      const float* __restrict__ b, __half* __restrict__ y16)
{
    const int warp = threadIdx.x >> 5, lane = threadIdx.x & 31;
    const int row = blockIdx.x * 8 + warp;
    const float4* xr = (const float4*)(x + (size_t)row * DMODEL);

    float4 v[8];
    float s = 0.0f;
#pragma unroll
    for (int j = 0; j < 8; j++) {
        v[j] = xr[lane + 32 * j];
        s += v[j].x + v[j].y + v[j].z + v[j].w;
    }
#pragma unroll
    for (int o = 16; o > 0; o >>= 1) s += __shfl_xor_sync(0xffffffff, s, o);
    const float mu = s * (1.0f / DMODEL);

    float q = 0.0f;
#pragma unroll
    for (int j = 0; j < 8; j++) {
        const float a = v[j].x - mu, b2 = v[j].y - mu, c = v[j].z - mu, d = v[j].w - mu;
        q += a * a + b2 * b2 + c * c + d * d;
    }
#pragma unroll
    for (int o = 16; o > 0; o >>= 1) q += __shfl_xor_sync(0xffffffff, q, o);
    const float rs = rsqrtf(q * (1.0f / DMODEL) + 1e-5f);

    uint2* yr = (uint2*)(y16 + (size_t)row * DMODEL);
#pragma unroll
    for (int j = 0; j < 8; j++) {
        const int idx = lane + 32 * j;
        const float4 wv = ((const float4*)w)[idx];
        const float4 bv = ((const float4*)b)[idx];
        const __half2 h0 = __floats2half2_rn((v[j].x - mu) * rs * wv.x + bv.x,
                                             (v[j].y - mu) * rs * wv.y + bv.y);
        const __half2 h1 = __floats2half2_rn((v[j].z - mu) * rs * wv.z + bv.z,
                                             (v[j].w - mu) * rs * wv.w + bv.w);
        uint2 o; o.x = *(const unsigned*)&h0; o.y = *(const unsigned*)&h1;
        yr[idx] = o;
    }
}

extern "C" void kernel_launch(void* const* d_in, const int* in_sizes, int n_in,
                              void* d_out, int out_size)
{
    (void)in_sizes; (void)n_in; (void)out_size;

    const int*   ids = (const int*)  d_in[0];
    const float* emb = (const float*)d_in[1];
    const float* Wu  = (const float*)d_in[2];
    const float* Wo  = (const float*)d_in[3];
    const float* n1w = (const float*)d_in[4];
    const float* n1b = (const float*)d_in[5];
    const float* n2w = (const float*)d_in[6];
    const float* n2b = (const float*)d_in[7];
    const float* f1w = (const float*)d_in[8];
    const float* f1b = (const float*)d_in[9];
    const float* f2w = (const float*)d_in[10];
    const float* f2b = (const float*)d_in[11];
    const float* fnw = (const float*)d_in[12];
    const float* fnb = (const float*)d_in[13];
    float* out = (float*)d_out;

    float *x; float2* tab; __half *u16, *xn16, *at16, *h16, *w16;
    cudaGetSymbolAddress((void**)&x,    g_x);
    cudaGetSymbolAddress((void**)&tab,  g_rope);
    cudaGetSymbolAddress((void**)&u16,  g_u16);
    cudaGetSymbolAddress((void**)&xn16, g_xn16);
    cudaGetSymbolAddress((void**)&at16, g_at16);
    cudaGetSymbolAddress((void**)&h16,  g_h16);
    cudaGetSymbolAddress((void**)&w16,  g_w16);

    cudaFuncSetAttribute(gemm_f16<0>, cudaFuncAttributeMaxDynamicSharedMemorySize, GEMM_SMEM);
    cudaFuncSetAttribute(gemm_f16<1>, cudaFuncAttributeMaxDynamicSharedMemorySize, GEMM_SMEM);
    cudaFuncSetAttribute(gemm_f16<3>, cudaFuncAttributeMaxDynamicSharedMemorySize, GEMM_SMEM);
    cudaFuncSetAttribute(gemm64,      cudaFuncAttributeMaxDynamicSharedMemorySize, G64_SMEM);
    cudaFuncSetAttribute(attn_mma,    cudaFuncAttributeMaxDynamicSharedMemorySize, ATTN_SMEM);

    static cudaStream_t s2 = nullptr;
    static cudaEvent_t evF = nullptr, evD = nullptr;
    if (!s2) {
        cudaStreamCreateWithFlags(&s2, cudaStreamNonBlocking);
        cudaEventCreateWithFlags(&evF, cudaEventDisableTiming);
        cudaEventCreateWithFlags(&evD, cudaEventDisableTiming);
    }

    // 1: prep   2: LN   3: conv emb   4: QKV GEMM (ncu anchor)
    prep_kernel<<<NROWS + 128 + 2048, 256>>>(ids, emb, x, tab, Wu, w16 + WU16);
    layernorm_kernel<<<NROWS / 8, 256>>>(x, n1w, n1b, xn16);
    conv16<<<2048, 256>>>(emb, w16 + EMB16, VOCAB * DMODEL / 4);
    gemm_f16<3><<<dim3(3 * TDIM / 128, NROWS / 128), 256, GEMM_SMEM>>>(
        xn16, w16 + WU16, nullptr, nullptr, nullptr, u16, tab, 3 * TDIM, DMODEL);

    cudaEventRecord(evF, 0);
    cudaStreamWaitEvent(s2, evF, 0);
    conv16<<<2048, 256, 0, s2>>>(Wo,  w16 + WO16,  NLAYER * DMODEL * TDIM / 4);
    conv16<<<2048, 256, 0, s2>>>(f1w, w16 + F116,  NLAYER * FFDIM * DMODEL / 4);
    conv16<<<2048, 256, 0, s2>>>(f2w, w16 + F216,  NLAYER * DMODEL * FFDIM / 4);
    cudaEventRecord(evD, s2);

    attn_mma<<<dim3(SEQ / 128, NHEAD, BATCH), 256, ATTN_SMEM>>>(u16, at16);
    cudaStreamWaitEvent(0, evD, 0);

    for (int l = 0; l < NLAYER; l++) {
        const __half* Wu_l = w16 + WU16 + (size_t)l * 3 * TDIM * DMODEL;
        const __half* Wo_l = w16 + WO16 + (size_t)l * DMODEL * TDIM;
        const __half* f1_l = w16 + F116 + (size_t)l * FFDIM * DMODEL;
        const __half* f2_l = w16 + F216 + (size_t)l * DMODEL * FFDIM;

        if (l > 0) {
            layernorm_kernel<<<NROWS / 8, 256>>>(x, n1w + l * DMODEL, n1b + l * DMODEL, xn16);
            gemm_f16<3><<<dim3(3 * TDIM / 128, NROWS / 128), 256, GEMM_SMEM>>>(
                xn16, Wu_l, nullptr, nullptr, nullptr, u16, tab, 3 * TDIM, DMODEL);
            attn_mma<<<dim3(SEQ / 128, NHEAD, BATCH), 256, ATTN_SMEM>>>(u16, at16);
        }

        gemm64<<<dim3(DMODEL / 128, NROWS / 64), 256, G64_SMEM>>>(
            at16, Wo_l, nullptr, x, x, DMODEL, TDIM);

        layernorm_kernel<<<NROWS / 8, 256>>>(x, n2w + l * DMODEL, n2b + l * DMODEL, xn16);

        gemm_f16<1><<<dim3(FFDIM / 128, NROWS / 128), 256, GEMM_SMEM>>>(
            xn16, f1_l, f1b + (size_t)l * FFDIM, nullptr, nullptr, h16, nullptr, FFDIM, DMODEL);

        gemm64<<<dim3(DMODEL / 128, NROWS / 64), 256, G64_SMEM>>>(
            h16, f2_l, f2b + (size_t)l * DMODEL, x, x, DMODEL, FFDIM);
    }

    layernorm_kernel<<<NROWS / 8, 256>>>(x, fnw, fnb, xn16);

    gemm_f16<0><<<dim3(VOCAB / 128, NROWS / 128), 256, GEMM_SMEM>>>(
        xn16, w16 + EMB16, nullptr, nullptr, out, nullptr, nullptr, VOCAB, DMODEL);
}

// round 13
// speedup vs baseline: 1.0355x; 1.0355x over previous
#include <cuda_runtime.h>
#include <cuda_fp16.h>
#include <math.h>
#include <stdint.h>

#define BATCH   2
#define SEQ     1024
#define NROWS   (BATCH * SEQ)
#define DMODEL  1024
#define NHEAD   16
#define HDIM    64
#define TDIM    1024
#define FFDIM   4096
#define NLAYER  8
#define VOCAB   32000

#define WU16  0
#define WO16  25165824u
#define F116  33554432u
#define F216  67108864u
#define EMB16 100663296u
#define W16_TOTAL 133431296u

__device__ float  g_x [NROWS * DMODEL];
__device__ float2 g_rope[SEQ * 32];
__device__ __half g_u16 [NROWS * 3 * TDIM];
__device__ __half g_xn16[NROWS * DMODEL];
__device__ __half g_at16[NROWS * TDIM];
__device__ __half g_h16 [NROWS * FFDIM];
__device__ __half g_w16 [W16_TOTAL];

__device__ __forceinline__ float gelu_exact(float v) {
    return 0.5f * v * (1.0f + erff(v * 0.70710678118654752440f));
}
__device__ __forceinline__ uint32_t s2u(const void* p) {
    uint32_t a;
    asm("{ .reg .u64 t; cvta.to.shared.u64 t, %1; cvt.u32.u64 %0, t; }" : "=r"(a) : "l"(p));
    return a;
}
__device__ __forceinline__ void cp16(uint32_t s, const void* g) {
    asm volatile("cp.async.cg.shared.global [%0], [%1], 16;" :: "r"(s), "l"(g));
}
__device__ __forceinline__ void ldsm4(unsigned* r, uint32_t a) {
    asm volatile("ldmatrix.sync.aligned.m8n8.x4.shared.b16 {%0,%1,%2,%3}, [%4];"
        : "=r"(r[0]), "=r"(r[1]), "=r"(r[2]), "=r"(r[3]) : "r"(a));
}
__device__ __forceinline__ void ldsm4t(unsigned* r, uint32_t a) {
    asm volatile("ldmatrix.sync.aligned.m8n8.x4.trans.shared.b16 {%0,%1,%2,%3}, [%4];"
        : "=r"(r[0]), "=r"(r[1]), "=r"(r[2]), "=r"(r[3]) : "r"(a));
}
__device__ __forceinline__ void mma_f16(float* c, const unsigned* a, const unsigned* b) {
    asm volatile(
        "mma.sync.aligned.m16n8k16.row.col.f32.f16.f16.f32 "
        "{%0,%1,%2,%3},{%4,%5,%6,%7},{%8,%9},{%0,%1,%2,%3};"
        : "+f"(c[0]), "+f"(c[1]), "+f"(c[2]), "+f"(c[3])
        : "r"(a[0]), "r"(a[1]), "r"(a[2]), "r"(a[3]), "r"(b[0]), "r"(b[1]));
}
__device__ __forceinline__ void rot(float& a, float& b, float2 cs) {
    const float t0 = a * cs.x - b * cs.y;
    b = b * cs.x + a * cs.y;
    a = t0;
}
__device__ __forceinline__ unsigned packh2(float a, float b) {
    __half2 h = __floats2half2_rn(a, b);
    return *(unsigned*)&h;
}

// ---------------------------------------------------------------------------
// fp16 GEMM 128x128: C = A @ B^T
// MODE 0: fp32 C   MODE 1: gelu(acc+bias)->fp16   MODE 2: acc(+bias)+resid->fp32
// MODE 3: rope(acc) via table -> fp16 C16 (QKV)
// SWAP=1: blockIdx.x indexes M (M-fastest block order, for DRAM-heavy B)
// ---------------------------------------------------------------------------
template<int MODE, int SWAP>
__global__ __launch_bounds__(256)
void gemm_f16(const __half* __restrict__ A, const __half* __restrict__ B,
              const float* __restrict__ bias, const float* __restrict__ resid,
              float* __restrict__ C, __half* __restrict__ C16,
              const float2* __restrict__ tab, int N, int K)
{
    extern __shared__ __align__(128) char smem[];
    const uint32_t sb = s2u(smem);
    const int tid = threadIdx.x, warp = tid >> 5, lane = tid & 31;
    const int bm = (SWAP ? blockIdx.x : blockIdx.y) * 128;
    const int bn = (SWAP ? blockIdx.y : blockIdx.x) * 128;
    const int moff = (warp & 3) * 32, noff = (warp >> 2) * 64;
    const int g = lane >> 2, t = lane & 3;
    const int nk = K >> 5;
    const int lrow = tid >> 2, lc = tid & 3;

    float acc[2][8][4];
#pragma unroll
    for (int mi = 0; mi < 2; mi++)
#pragma unroll
        for (int ni = 0; ni < 8; ni++)
#pragma unroll
            for (int e = 0; e < 4; e++) acc[mi][ni][e] = 0.0f;

#define LOADST(st, ks) do { \
    const uint32_t so = sb + (uint32_t)(st) * 20480u; \
    const __half* gA = A + (size_t)(bm + lrow) * K + (ks) * 32 + lc * 8; \
    const __half* gB = B + (size_t)(bn + lrow) * K + (ks) * 32 + lc * 8; \
    const uint32_t sA = so + lrow * 80 + lc * 16; \
    const uint32_t sB = sA + 10240u; \
    cp16(sA, gA); cp16(sB, gB); \
    cp16(sA + 64 * 80, gA + (size_t)64 * K); \
    cp16(sB + 64 * 80, gB + (size_t)64 * K); \
} while (0)

    LOADST(0, 0);
    asm volatile("cp.async.commit_group;" ::: "memory");
    if (nk > 1) LOADST(1, 1);
    asm volatile("cp.async.commit_group;" ::: "memory");

    const uint32_t aoff = (uint32_t)((moff + (lane & 15)) * 80 + ((lane >> 4) & 1) * 16);
    const uint32_t boff = 10240u +
        (uint32_t)((noff + (lane & 7) + ((lane >> 4) & 1) * 8) * 80 + ((lane >> 3) & 1) * 16);

    for (int ks = 0; ks < nk; ks++) {
        asm volatile("cp.async.wait_group %0;" :: "n"(1) : "memory");
        __syncthreads();
        if (ks + 2 < nk) { LOADST((ks + 2) % 3, ks + 2); }
        asm volatile("cp.async.commit_group;" ::: "memory");

        const uint32_t so = sb + (uint32_t)(ks % 3) * 20480u;
#pragma unroll
        for (int kk = 0; kk < 2; kk++) {
            unsigned a0[4], a1[4], b[4][4];
            ldsm4(a0, so + aoff + kk * 32);
            ldsm4(a1, so + aoff + 16 * 80 + kk * 32);
#pragma unroll
            for (int nj = 0; nj < 4; nj++)
                ldsm4(b[nj], so + boff + nj * 16 * 80 + kk * 32);
#pragma unroll
            for (int nj = 0; nj < 4; nj++) {
                mma_f16(acc[0][2 * nj],     a0, &b[nj][0]);
                mma_f16(acc[0][2 * nj + 1], a0, &b[nj][2]);
                mma_f16(acc[1][2 * nj],     a1, &b[nj][0]);
                mma_f16(acc[1][2 * nj + 1], a1, &b[nj][2]);
            }
        }
    }
#undef LOADST

    if (MODE == 3) {
        const int region = (bn + noff) >> 10;
        if (region < 2) {
#pragma unroll
            for (int mi = 0; mi < 2; mi++) {
                const int r0 = bm + moff + 16 * mi + g;
                const int s0 = r0 & (SEQ - 1);
#pragma unroll
                for (int ni = 0; ni < 4; ni++) {
                    const int i0 = 8 * ni + 2 * t;
                    const float2 c00 = tab[s0 * 32 + i0];
                    const float2 c01 = tab[s0 * 32 + i0 + 1];
                    const float2 c10 = tab[(s0 + 8) * 32 + i0];
                    const float2 c11 = tab[(s0 + 8) * 32 + i0 + 1];
                    rot(acc[mi][ni][0], acc[mi][ni + 4][0], c00);
                    rot(acc[mi][ni][1], acc[mi][ni + 4][1], c01);
                    rot(acc[mi][ni][2], acc[mi][ni + 4][2], c10);
                    rot(acc[mi][ni][3], acc[mi][ni + 4][3], c11);
                }
            }
        }
    }

#pragma unroll
    for (int mi = 0; mi < 2; mi++) {
        const int r0 = bm + moff + 16 * mi + g;
#pragma unroll
        for (int ni = 0; ni < 8; ni++) {
            const int c = bn + noff + 8 * ni + 2 * t;
            float v00 = acc[mi][ni][0], v01 = acc[mi][ni][1];
            float v10 = acc[mi][ni][2], v11 = acc[mi][ni][3];
            if (MODE == 1 || MODE == 3) {
                if (MODE == 1) {
                    const float b0 = bias[c], b1 = bias[c + 1];
                    v00 = gelu_exact(v00 + b0); v01 = gelu_exact(v01 + b1);
                    v10 = gelu_exact(v10 + b0); v11 = gelu_exact(v11 + b1);
                }
                *(__half2*)(C16 + (size_t)r0 * N + c)       = __floats2half2_rn(v00, v01);
                *(__half2*)(C16 + (size_t)(r0 + 8) * N + c) = __floats2half2_rn(v10, v11);
            } else {
                if (MODE == 2) {
                    if (bias) {
                        const float b0 = bias[c], b1 = bias[c + 1];
                        v00 += b0; v01 += b1; v10 += b0; v11 += b1;
                    }
                    const float2 rr0 = *(const float2*)(resid + (size_t)r0 * N + c);
                    const float2 rr1 = *(const float2*)(resid + (size_t)(r0 + 8) * N + c);
                    v00 += rr0.x; v01 += rr0.y; v10 += rr1.x; v11 += rr1.y;
                }
                float2 o0; o0.x = v00; o0.y = v01;
                float2 o1; o1.x = v10; o1.y = v11;
                *(float2*)(C + (size_t)r0 * N + c) = o0;
                *(float2*)(C + (size_t)(r0 + 8) * N + c) = o1;
            }
        }
    }
}
#define GEMM_SMEM (3 * 20480)

// ---------------------------------------------------------------------------
// MMA flash attention v3 (unchanged)
// ---------------------------------------------------------------------------
#define ATTN_SMEM (128 * 144 + 4 * 64 * 144)
__global__ __launch_bounds__(256, 2)
void attn_mma(const __half* __restrict__ U, __half* __restrict__ O)
{
    const int q0 = blockIdx.x * 128, h = blockIdx.y, b = blockIdx.z;
    const int tid = threadIdx.x, warp = tid >> 5, lane = tid & 31;
    const int g = lane >> 2, t = lane & 3;

    extern __shared__ __align__(128) char asm_[];
    const uint32_t qb = s2u(asm_);
    const uint32_t kb0 = qb + 128 * 144;
    const uint32_t vb0 = kb0 + 2 * 64 * 144;

    const __half* Ub = U + (size_t)(b * SEQ) * 3072 + h * 64;

    {
        const int r = tid >> 1;
        const int sg = (tid & 1) * 64;
        const __half* gq = Ub + (size_t)(q0 + r) * 3072 + sg / 2;
        const uint32_t sq = qb + r * 144 + sg;
        cp16(sq, gq); cp16(sq + 16, gq + 8);
        cp16(sq + 32, gq + 16); cp16(sq + 48, gq + 24);
    }
    asm volatile("cp.async.commit_group;" ::: "memory");
    asm volatile("cp.async.wait_group 0;" ::: "memory");
    __syncthreads();

    unsigned qf[4][4];
    {
        const uint32_t qa = qb + (16 * warp + (lane & 15)) * 144 + ((lane >> 4) & 1) * 16;
        const __half2 sc = __floats2half2_rn(0.125f, 0.125f);
#pragma unroll
        for (int kk = 0; kk < 4; kk++) {
            ldsm4(qf[kk], qa + kk * 32);
#pragma unroll
            for (int e = 0; e < 4; e++) {
                __half2 v = *(__half2*)&qf[kk][e];
                v = __hmul2(v, sc);
                qf[kk][e] = *(unsigned*)&v;
            }
        }
    }

    float o[8][4];
#pragma unroll
    for (int d = 0; d < 8; d++)
#pragma unroll
        for (int e = 0; e < 4; e++) o[d][e] = 0.0f;
    float m0 = -1e30f, m1 = -1e30f, l0 = 0.0f, l1 = 0.0f;
    const int wbase = q0 + 16 * warp;
    const int row0 = wbase + g;
    const int nch = (q0 >> 6) + 2;

#define LOADKV(ci) do { \
    const int _c0 = (ci) * 64; \
    const int _bf = (ci) & 1; \
    const int tt = tid & 127; \
    const int r = tt >> 1, sgh = (tt & 1) * 32; \
    const __half* gp = Ub + (size_t)(_c0 + r) * 3072 + ((tid >= 128) ? 2048 : 1024) + sgh; \
    const uint32_t sp = ((tid >= 128) ? vb0 : kb0) + _bf * (64 * 144) + r * 144 + sgh * 2; \
    cp16(sp, gp); cp16(sp + 16, gp + 8); \
    cp16(sp + 32, gp + 16); cp16(sp + 48, gp + 24); \
} while (0)

    LOADKV(0);
    asm volatile("cp.async.commit_group;" ::: "memory");

    for (int ci = 0; ci < nch; ci++) {
        const int c0 = ci * 64;
        const bool pre = (ci + 1 < nch);
        if (pre) {
            LOADKV(ci + 1);
            asm volatile("cp.async.commit_group;" ::: "memory");
            asm volatile("cp.async.wait_group 1;" ::: "memory");
        } else {
            asm volatile("cp.async.wait_group 0;" ::: "memory");
        }
        __syncthreads();

        const uint32_t kb = kb0 + (ci & 1) * (64 * 144);
        const uint32_t vb = vb0 + (ci & 1) * (64 * 144);

        float s[8][4];
#pragma unroll
        for (int j = 0; j < 8; j++)
#pragma unroll
            for (int e = 0; e < 4; e++) s[j][e] = 0.0f;
#pragma unroll
        for (int kk = 0; kk < 4; kk++) {
            unsigned bf[4][4];
#pragma unroll
            for (int nj = 0; nj < 4; nj++)
                ldsm4(bf[nj], kb + (nj * 16 + (lane & 7) + ((lane >> 4) & 1) * 8) * 144
                                + ((lane >> 3) & 1) * 16 + kk * 32);
#pragma unroll
            for (int nj = 0; nj < 4; nj++) {
                mma_f16(s[2 * nj],     qf[kk], &bf[nj][0]);
                mma_f16(s[2 * nj + 1], qf[kk], &bf[nj][2]);
            }
        }

        if (c0 + 63 > wbase) {
#pragma unroll
            for (int j = 0; j < 8; j++) {
                const int cb = c0 + 8 * j + 2 * t;
                if (cb     > row0)     s[j][0] = -1e30f;
                if (cb + 1 > row0)     s[j][1] = -1e30f;
                if (cb     > row0 + 8) s[j][2] = -1e30f;
                if (cb + 1 > row0 + 8) s[j][3] = -1e30f;
            }
        }

        float cm0 = -1e30f, cm1 = -1e30f;
#pragma unroll
        for (int j = 0; j < 8; j++) {
            cm0 = fmaxf(cm0, fmaxf(s[j][0], s[j][1]));
            cm1 = fmaxf(cm1, fmaxf(s[j][2], s[j][3]));
        }
        cm0 = fmaxf(cm0, __shfl_xor_sync(0xffffffff, cm0, 1));
        cm0 = fmaxf(cm0, __shfl_xor_sync(0xffffffff, cm0, 2));
        cm1 = fmaxf(cm1, __shfl_xor_sync(0xffffffff, cm1, 1));
        cm1 = fmaxf(cm1, __shfl_xor_sync(0xffffffff, cm1, 2));
        const float nm0 = fmaxf(m0, cm0), nm1 = fmaxf(m1, cm1);
        const float f0 = __expf(m0 - nm0), f1 = __expf(m1 - nm1);
        m0 = nm0; m1 = nm1;

        unsigned pf[4][4];
        float sum0 = 0.0f, sum1 = 0.0f;
#pragma unroll
        for (int nj = 0; nj < 4; nj++) {
            const float pa0 = __expf(s[2 * nj][0] - nm0), pa1 = __expf(s[2 * nj][1] - nm0);
            const float pa2 = __expf(s[2 * nj][2] - nm1), pa3 = __expf(s[2 * nj][3] - nm1);
            const float pb0 = __expf(s[2 * nj + 1][0] - nm0), pb1 = __expf(s[2 * nj + 1][1] - nm0);
            const float pb2 = __expf(s[2 * nj + 1][2] - nm1), pb3 = __expf(s[2 * nj + 1][3] - nm1);
            sum0 += pa0 + pa1 + pb0 + pb1;
            sum1 += pa2 + pa3 + pb2 + pb3;
            pf[nj][0] = packh2(pa0, pa1);
            pf[nj][1] = packh2(pa2, pa3);
            pf[nj][2] = packh2(pb0, pb1);
            pf[nj][3] = packh2(pb2, pb3);
        }
        sum0 += __shfl_xor_sync(0xffffffff, sum0, 1);
        sum0 += __shfl_xor_sync(0xffffffff, sum0, 2);
        sum1 += __shfl_xor_sync(0xffffffff, sum1, 1);
        sum1 += __shfl_xor_sync(0xffffffff, sum1, 2);
        l0 = l0 * f0 + sum0;
        l1 = l1 * f1 + sum1;

#pragma unroll
        for (int d = 0; d < 8; d++) {
            o[d][0] *= f0; o[d][1] *= f0; o[d][2] *= f1; o[d][3] *= f1;
        }

#pragma unroll
        for (int kk = 0; kk < 4; kk++) {
            unsigned vf[4][4];
#pragma unroll
            for (int dj = 0; dj < 4; dj++)
                ldsm4t(vf[dj], vb + (kk * 16 + (lane & 7) + ((lane >> 3) & 1) * 8) * 144
                                 + (dj * 16 + ((lane >> 4) & 1) * 8) * 2);
#pragma unroll
            for (int dj = 0; dj < 4; dj++) {
                mma_f16(o[2 * dj],     pf[kk], &vf[dj][0]);
                mma_f16(o[2 * dj + 1], pf[kk], &vf[dj][2]);
            }
        }
        __syncthreads();
    }
#undef LOADKV

    const float il0 = 1.0f / l0, il1 = 1.0f / l1;
    __half* Ob = O + (size_t)(b * SEQ + row0) * TDIM + h * 64;
#pragma unroll
    for (int dj = 0; dj < 8; dj++) {
        const int c = 8 * dj + 2 * t;
        *(__half2*)(Ob + c)            = __floats2half2_rn(o[dj][0] * il0, o[dj][1] * il0);
        *(__half2*)(Ob + 8 * TDIM + c) = __floats2half2_rn(o[dj][2] * il1, o[dj][3] * il1);
    }
}

// ---------------------------------------------------------------------------
__global__ void conv16(const float* __restrict__ s, __half* __restrict__ d, int n4)
{
    for (int i = blockIdx.x * blockDim.x + threadIdx.x; i < n4; i += gridDim.x * blockDim.x) {
        const float4 v = ((const float4*)s)[i];
        ((__half2*)d)[2 * i]     = __floats2half2_rn(v.x, v.y);
        ((__half2*)d)[2 * i + 1] = __floats2half2_rn(v.z, v.w);
    }
}

__global__ void prep_kernel(const int* __restrict__ ids, const float* __restrict__ emb,
                            float* __restrict__ x, float2* __restrict__ tab,
                            const float* __restrict__ Wu, __half* __restrict__ wu16)
{
    if (blockIdx.x < NROWS) {
        ((float4*)(x + (size_t)blockIdx.x * DMODEL))[threadIdx.x] =
            ((const float4*)(emb + (size_t)ids[blockIdx.x] * DMODEL))[threadIdx.x];
    } else if (blockIdx.x < NROWS + 128) {
        const int idx = (blockIdx.x - NROWS) * 256 + threadIdx.x;
        const int s = idx >> 5, i = idx & 31;
        const float inv = exp2f(-(float)(2 * i) * (1.0f / 64.0f) * 13.287712379549449f);
        float sn, cs;
        sincosf((float)s * inv, &sn, &cs);
        tab[idx] = make_float2(cs, sn);
    } else {
        const int n4 = NLAYER * 3 * TDIM * DMODEL / 4;
        for (int i = (blockIdx.x - NROWS - 128) * 256 + threadIdx.x; i < n4; i += 2048 * 256) {
            const float4 v = ((const float4*)Wu)[i];
            ((__half2*)wu16)[2 * i]     = __floats2half2_rn(v.x, v.y);
            ((__half2*)wu16)[2 * i + 1] = __floats2half2_rn(v.z, v.w);
        }
    }
}

// warp-per-row LayerNorm -> fp16
__global__ __launch_bounds__(256)
void layernorm_kernel(const float* __restrict__ x, const float* __restrict__ w,
                      const float* __restrict__ b, __half* __restrict__ y16)
{
    const int warp = threadIdx.x >> 5, lane = threadIdx.x & 31;
    const int row = blockIdx.x * 8 + warp;
    const float4* xr = (const float4*)(x + (size_t)row * DMODEL);

    float4 v[8];
    float s = 0.0f;
#pragma unroll
    for (int j = 0; j < 8; j++) {
        v[j] = xr[lane + 32 * j];
        s += v[j].x + v[j].y + v[j].z + v[j].w;
    }
#pragma unroll
    for (int o = 16; o > 0; o >>= 1) s += __shfl_xor_sync(0xffffffff, s, o);
    const float mu = s * (1.0f / DMODEL);

    float q = 0.0f;
#pragma unroll
    for (int j = 0; j < 8; j++) {
        const float a = v[j].x - mu, b2 = v[j].y - mu, c = v[j].z - mu, d = v[j].w - mu;
        q += a * a + b2 * b2 + c * c + d * d;
    }
#pragma unroll
    for (int o = 16; o > 0; o >>= 1) q += __shfl_xor_sync(0xffffffff, q, o);
    const float rs = rsqrtf(q * (1.0f / DMODEL) + 1e-5f);

    uint2* yr = (uint2*)(y16 + (size_t)row * DMODEL);
#pragma unroll
    for (int j = 0; j < 8; j++) {
        const int idx = lane + 32 * j;
        const float4 wv = ((const float4*)w)[idx];
        const float4 bv = ((const float4*)b)[idx];
        const __half2 h0 = __floats2half2_rn((v[j].x - mu) * rs * wv.x + bv.x,
                                             (v[j].y - mu) * rs * wv.y + bv.y);
        const __half2 h1 = __floats2half2_rn((v[j].z - mu) * rs * wv.z + bv.z,
                                             (v[j].w - mu) * rs * wv.w + bv.w);
        uint2 o; o.x = *(const unsigned*)&h0; o.y = *(const unsigned*)&h1;
        yr[idx] = o;
    }
}

extern "C" void kernel_launch(void* const* d_in, const int* in_sizes, int n_in,
                              void* d_out, int out_size)
{
    (void)in_sizes; (void)n_in; (void)out_size;

    const int*   ids = (const int*)  d_in[0];
    const float* emb = (const float*)d_in[1];
    const float* Wu  = (const float*)d_in[2];
    const float* Wo  = (const float*)d_in[3];
    const float* n1w = (const float*)d_in[4];
    const float* n1b = (const float*)d_in[5];
    const float* n2w = (const float*)d_in[6];
    const float* n2b = (const float*)d_in[7];
    const float* f1w = (const float*)d_in[8];
    const float* f1b = (const float*)d_in[9];
    const float* f2w = (const float*)d_in[10];
    const float* f2b = (const float*)d_in[11];
    const float* fnw = (const float*)d_in[12];
    const float* fnb = (const float*)d_in[13];
    float* out = (float*)d_out;

    float *x; float2* tab; __half *u16, *xn16, *at16, *h16, *w16;
    cudaGetSymbolAddress((void**)&x,    g_x);
    cudaGetSymbolAddress((void**)&tab,  g_rope);
    cudaGetSymbolAddress((void**)&u16,  g_u16);
    cudaGetSymbolAddress((void**)&xn16, g_xn16);
    cudaGetSymbolAddress((void**)&at16, g_at16);
    cudaGetSymbolAddress((void**)&h16,  g_h16);
    cudaGetSymbolAddress((void**)&w16,  g_w16);

    cudaFuncSetAttribute((gemm_f16<0,1>), cudaFuncAttributeMaxDynamicSharedMemorySize, GEMM_SMEM);
    cudaFuncSetAttribute((gemm_f16<1,0>), cudaFuncAttributeMaxDynamicSharedMemorySize, GEMM_SMEM);
    cudaFuncSetAttribute((gemm_f16<2,0>), cudaFuncAttributeMaxDynamicSharedMemorySize, GEMM_SMEM);
    cudaFuncSetAttribute((gemm_f16<3,0>), cudaFuncAttributeMaxDynamicSharedMemorySize, GEMM_SMEM);
    cudaFuncSetAttribute(attn_mma,        cudaFuncAttributeMaxDynamicSharedMemorySize, ATTN_SMEM);

    static cudaStream_t s2 = nullptr;
    static cudaEvent_t evF = nullptr, evD = nullptr;
    if (!s2) {
        cudaStreamCreateWithFlags(&s2, cudaStreamNonBlocking);
        cudaEventCreateWithFlags(&evF, cudaEventDisableTiming);
        cudaEventCreateWithFlags(&evD, cudaEventDisableTiming);
    }

    // 1: prep   2: LN   3: conv emb   4: QKV GEMM (ncu anchor)
    prep_kernel<<<NROWS + 128 + 2048, 256>>>(ids, emb, x, tab, Wu, w16 + WU16);
    layernorm_kernel<<<NROWS / 8, 256>>>(x, n1w, n1b, xn16);
    conv16<<<2048, 256>>>(emb, w16 + EMB16, VOCAB * DMODEL / 4);
    gemm_f16<3,0><<<dim3(3 * TDIM / 128, NROWS / 128), 256, GEMM_SMEM>>>(
        xn16, w16 + WU16, nullptr, nullptr, nullptr, u16, tab, 3 * TDIM, DMODEL);

    cudaEventRecord(evF, 0);
    cudaStreamWaitEvent(s2, evF, 0);
    conv16<<<2048, 256, 0, s2>>>(Wo,  w16 + WO16,  NLAYER * DMODEL * TDIM / 4);
    conv16<<<2048, 256, 0, s2>>>(f1w, w16 + F116,  NLAYER * FFDIM * DMODEL / 4);
    conv16<<<2048, 256, 0, s2>>>(f2w, w16 + F216,  NLAYER * DMODEL * FFDIM / 4);
    cudaEventRecord(evD, s2);

    attn_mma<<<dim3(SEQ / 128, NHEAD, BATCH), 256, ATTN_SMEM>>>(u16, at16);
    cudaStreamWaitEvent(0, evD, 0);

    for (int l = 0; l < NLAYER; l++) {
        const __half* Wu_l = w16 + WU16 + (size_t)l * 3 * TDIM * DMODEL;
        const __half* Wo_l = w16 + WO16 + (size_t)l * DMODEL * TDIM;
        const __half* f1_l = w16 + F116 + (size_t)l * FFDIM * DMODEL;
        const __half* f2_l = w16 + F216 + (size_t)l * DMODEL * FFDIM;

        if (l > 0) {
            layernorm_kernel<<<NROWS / 8, 256>>>(x, n1w + l * DMODEL, n1b + l * DMODEL, xn16);
            gemm_f16<3,0><<<dim3(3 * TDIM / 128, NROWS / 128), 256, GEMM_SMEM>>>(
                xn16, Wu_l, nullptr, nullptr, nullptr, u16, tab, 3 * TDIM, DMODEL);
            attn_mma<<<dim3(SEQ / 128, NHEAD, BATCH), 256, ATTN_SMEM>>>(u16, at16);
        }

        gemm_f16<2,0><<<dim3(DMODEL / 128, NROWS / 128), 256, GEMM_SMEM>>>(
            at16, Wo_l, nullptr, x, x, nullptr, nullptr, DMODEL, TDIM);

        layernorm_kernel<<<NROWS / 8, 256>>>(x, n2w + l * DMODEL, n2b + l * DMODEL, xn16);

        gemm_f16<1,0><<<dim3(FFDIM / 128, NROWS / 128), 256, GEMM_SMEM>>>(
            xn16, f1_l, f1b + (size_t)l * FFDIM, nullptr, nullptr, h16, nullptr, FFDIM, DMODEL);

        gemm_f16<2,0><<<dim3(DMODEL / 128, NROWS / 128), 256, GEMM_SMEM>>>(
            h16, f2_l, f2b + (size_t)l * DMODEL, x, x, nullptr, nullptr, DMODEL, FFDIM);
    }

    layernorm_kernel<<<NROWS / 8, 256>>>(x, fnw, fnb, xn16);

    // logits: M-fastest block order -> emb (64 MB) streamed once, A L2-resident
    gemm_f16<0,1><<<dim3(NROWS / 128, VOCAB / 128), 256, GEMM_SMEM>>>(
        xn16, w16 + EMB16, nullptr, nullptr, out, nullptr, nullptr, VOCAB, DMODEL);
}

// round 14
// speedup vs baseline: 1.0441x; 1.0083x over previous
#include <cuda_runtime.h>
#include <cuda_fp16.h>
#include <math.h>
#include <stdint.h>

#define BATCH   2
#define SEQ     1024
#define NROWS   (BATCH * SEQ)
#define DMODEL  1024
#define NHEAD   16
#define HDIM    64
#define TDIM    1024
#define FFDIM   4096
#define NLAYER  8
#define VOCAB   32000

#define WU16  0
#define WO16  25165824u
#define F116  33554432u
#define F216  67108864u
#define EMB16 100663296u
#define W16_TOTAL 133431296u

__device__ float  g_x [NROWS * DMODEL];
__device__ float  g_part[2 * NROWS * DMODEL];
__device__ float2 g_rope[SEQ * 32];
__device__ __half g_u16 [NROWS * 3 * TDIM];
__device__ __half g_xn16[NROWS * DMODEL];
__device__ __half g_at16[NROWS * TDIM];
__device__ __half g_h16 [NROWS * FFDIM];
__device__ __half g_w16 [W16_TOTAL];

__device__ __forceinline__ float gelu_exact(float v) {
    return 0.5f * v * (1.0f + erff(v * 0.70710678118654752440f));
}
__device__ __forceinline__ uint32_t s2u(const void* p) {
    uint32_t a;
    asm("{ .reg .u64 t; cvta.to.shared.u64 t, %1; cvt.u32.u64 %0, t; }" : "=r"(a) : "l"(p));
    return a;
}
__device__ __forceinline__ void cp16(uint32_t s, const void* g) {
    asm volatile("cp.async.cg.shared.global [%0], [%1], 16;" :: "r"(s), "l"(g));
}
__device__ __forceinline__ void ldsm4(unsigned* r, uint32_t a) {
    asm volatile("ldmatrix.sync.aligned.m8n8.x4.shared.b16 {%0,%1,%2,%3}, [%4];"
        : "=r"(r[0]), "=r"(r[1]), "=r"(r[2]), "=r"(r[3]) : "r"(a));
}
__device__ __forceinline__ void ldsm4t(unsigned* r, uint32_t a) {
    asm volatile("ldmatrix.sync.aligned.m8n8.x4.trans.shared.b16 {%0,%1,%2,%3}, [%4];"
        : "=r"(r[0]), "=r"(r[1]), "=r"(r[2]), "=r"(r[3]) : "r"(a));
}
__device__ __forceinline__ void mma_f16(float* c, const unsigned* a, const unsigned* b) {
    asm volatile(
        "mma.sync.aligned.m16n8k16.row.col.f32.f16.f16.f32 "
        "{%0,%1,%2,%3},{%4,%5,%6,%7},{%8,%9},{%0,%1,%2,%3};"
        : "+f"(c[0]), "+f"(c[1]), "+f"(c[2]), "+f"(c[3])
        : "r"(a[0]), "r"(a[1]), "r"(a[2]), "r"(a[3]), "r"(b[0]), "r"(b[1]));
}
__device__ __forceinline__ void rot(float& a, float& b, float2 cs) {
    const float t0 = a * cs.x - b * cs.y;
    b = b * cs.x + a * cs.y;
    a = t0;
}
__device__ __forceinline__ unsigned packh2(float a, float b) {
    __half2 h = __floats2half2_rn(a, b);
    return *(unsigned*)&h;
}

// ---------------------------------------------------------------------------
// fp16 GEMM 128x128: C = A @ B^T
// MODE 0: fp32 C   MODE 1: gelu(acc+bias)->fp16   MODE 2: acc(+bias)+resid->fp32
// MODE 3: rope(acc) via table -> fp16 C16 (QKV)
// SWAP=1: blockIdx.x indexes M (for DRAM-heavy B, logits)
// ---------------------------------------------------------------------------
template<int MODE, int SWAP>
__global__ __launch_bounds__(256)
void gemm_f16(const __half* __restrict__ A, const __half* __restrict__ B,
              const float* __restrict__ bias, const float* __restrict__ resid,
              float* __restrict__ C, __half* __restrict__ C16,
              const float2* __restrict__ tab, int N, int K)
{
    extern __shared__ __align__(128) char smem[];
    const uint32_t sb = s2u(smem);
    const int tid = threadIdx.x, warp = tid >> 5, lane = tid & 31;
    const int bm = (SWAP ? blockIdx.x : blockIdx.y) * 128;
    const int bn = (SWAP ? blockIdx.y : blockIdx.x) * 128;
    const int moff = (warp & 3) * 32, noff = (warp >> 2) * 64;
    const int g = lane >> 2, t = lane & 3;
    const int nk = K >> 5;
    const int lrow = tid >> 2, lc = tid & 3;

    float acc[2][8][4];
#pragma unroll
    for (int mi = 0; mi < 2; mi++)
#pragma unroll
        for (int ni = 0; ni < 8; ni++)
#pragma unroll
            for (int e = 0; e < 4; e++) acc[mi][ni][e] = 0.0f;

#define LOADST(st, ks) do { \
    const uint32_t so = sb + (uint32_t)(st) * 20480u; \
    const __half* gA = A + (size_t)(bm + lrow) * K + (ks) * 32 + lc * 8; \
    const __half* gB = B + (size_t)(bn + lrow) * K + (ks) * 32 + lc * 8; \
    const uint32_t sA = so + lrow * 80 + lc * 16; \
    const uint32_t sB = sA + 10240u; \
    cp16(sA, gA); cp16(sB, gB); \
    cp16(sA + 64 * 80, gA + (size_t)64 * K); \
    cp16(sB + 64 * 80, gB + (size_t)64 * K); \
} while (0)

    LOADST(0, 0);
    asm volatile("cp.async.commit_group;" ::: "memory");
    if (nk > 1) LOADST(1, 1);
    asm volatile("cp.async.commit_group;" ::: "memory");

    const uint32_t aoff = (uint32_t)((moff + (lane & 15)) * 80 + ((lane >> 4) & 1) * 16);
    const uint32_t boff = 10240u +
        (uint32_t)((noff + (lane & 7) + ((lane >> 4) & 1) * 8) * 80 + ((lane >> 3) & 1) * 16);

    for (int ks = 0; ks < nk; ks++) {
        asm volatile("cp.async.wait_group %0;" :: "n"(1) : "memory");
        __syncthreads();
        if (ks + 2 < nk) { LOADST((ks + 2) % 3, ks + 2); }
        asm volatile("cp.async.commit_group;" ::: "memory");

        const uint32_t so = sb + (uint32_t)(ks % 3) * 20480u;
#pragma unroll
        for (int kk = 0; kk < 2; kk++) {
            unsigned a0[4], a1[4], b[4][4];
            ldsm4(a0, so + aoff + kk * 32);
            ldsm4(a1, so + aoff + 16 * 80 + kk * 32);
#pragma unroll
            for (int nj = 0; nj < 4; nj++)
                ldsm4(b[nj], so + boff + nj * 16 * 80 + kk * 32);
#pragma unroll
            for (int nj = 0; nj < 4; nj++) {
                mma_f16(acc[0][2 * nj],     a0, &b[nj][0]);
                mma_f16(acc[0][2 * nj + 1], a0, &b[nj][2]);
                mma_f16(acc[1][2 * nj],     a1, &b[nj][0]);
                mma_f16(acc[1][2 * nj + 1], a1, &b[nj][2]);
            }
        }
    }
#undef LOADST

    if (MODE == 3) {
        const int region = (bn + noff) >> 10;
        if (region < 2) {
#pragma unroll
            for (int mi = 0; mi < 2; mi++) {
                const int r0 = bm + moff + 16 * mi + g;
                const int s0 = r0 & (SEQ - 1);
#pragma unroll
                for (int ni = 0; ni < 4; ni++) {
                    const int i0 = 8 * ni + 2 * t;
                    const float2 c00 = tab[s0 * 32 + i0];
                    const float2 c01 = tab[s0 * 32 + i0 + 1];
                    const float2 c10 = tab[(s0 + 8) * 32 + i0];
                    const float2 c11 = tab[(s0 + 8) * 32 + i0 + 1];
                    rot(acc[mi][ni][0], acc[mi][ni + 4][0], c00);
                    rot(acc[mi][ni][1], acc[mi][ni + 4][1], c01);
                    rot(acc[mi][ni][2], acc[mi][ni + 4][2], c10);
                    rot(acc[mi][ni][3], acc[mi][ni + 4][3], c11);
                }
            }
        }
    }

#pragma unroll
    for (int mi = 0; mi < 2; mi++) {
        const int r0 = bm + moff + 16 * mi + g;
#pragma unroll
        for (int ni = 0; ni < 8; ni++) {
            const int c = bn + noff + 8 * ni + 2 * t;
            float v00 = acc[mi][ni][0], v01 = acc[mi][ni][1];
            float v10 = acc[mi][ni][2], v11 = acc[mi][ni][3];
            if (MODE == 1 || MODE == 3) {
                if (MODE == 1) {
                    const float b0 = bias[c], b1 = bias[c + 1];
                    v00 = gelu_exact(v00 + b0); v01 = gelu_exact(v01 + b1);
                    v10 = gelu_exact(v10 + b0); v11 = gelu_exact(v11 + b1);
                }
                *(__half2*)(C16 + (size_t)r0 * N + c)       = __floats2half2_rn(v00, v01);
                *(__half2*)(C16 + (size_t)(r0 + 8) * N + c) = __floats2half2_rn(v10, v11);
            } else {
                if (MODE == 2) {
                    if (bias) {
                        const float b0 = bias[c], b1 = bias[c + 1];
                        v00 += b0; v01 += b1; v10 += b0; v11 += b1;
                    }
                    const float2 rr0 = *(const float2*)(resid + (size_t)r0 * N + c);
                    const float2 rr1 = *(const float2*)(resid + (size_t)(r0 + 8) * N + c);
                    v00 += rr0.x; v01 += rr0.y; v10 += rr1.x; v11 += rr1.y;
                }
                float2 o0; o0.x = v00; o0.y = v01;
                float2 o1; o1.x = v10; o1.y = v11;
                *(float2*)(C + (size_t)r0 * N + c) = o0;
                *(float2*)(C + (size_t)(r0 + 8) * N + c) = o1;
            }
        }
    }
}
#define GEMM_SMEM (3 * 20480)

// ---------------------------------------------------------------------------
// Split-K GEMM: blockIdx.z = K-half. Partials -> P[kh * NROWS*N + ...] (fp32).
// Same 128x128 tile & warp layout; row stride = full K.
// ---------------------------------------------------------------------------
__global__ __launch_bounds__(256)
void gemm_sk(const __half* __restrict__ A, const __half* __restrict__ B,
             float* __restrict__ P, int N, int Kfull)
{
    extern __shared__ __align__(128) char smem[];
    const uint32_t sb = s2u(smem);
    const int tid = threadIdx.x, warp = tid >> 5, lane = tid & 31;
    const int bm = blockIdx.y * 128, bn = blockIdx.x * 128;
    const int kh = blockIdx.z;
    const int Kh = Kfull >> 1;
    const int koff = kh * Kh;
    const int moff = (warp & 3) * 32, noff = (warp >> 2) * 64;
    const int g = lane >> 2, t = lane & 3;
    const int nk = Kh >> 5;
    const int lrow = tid >> 2, lc = tid & 3;

    float acc[2][8][4];
#pragma unroll
    for (int mi = 0; mi < 2; mi++)
#pragma unroll
        for (int ni = 0; ni < 8; ni++)
#pragma unroll
            for (int e = 0; e < 4; e++) acc[mi][ni][e] = 0.0f;

#define LOADSK(st, ks) do { \
    const uint32_t so = sb + (uint32_t)(st) * 20480u; \
    const __half* gA = A + (size_t)(bm + lrow) * Kfull + koff + (ks) * 32 + lc * 8; \
    const __half* gB = B + (size_t)(bn + lrow) * Kfull + koff + (ks) * 32 + lc * 8; \
    const uint32_t sA = so + lrow * 80 + lc * 16; \
    const uint32_t sB = sA + 10240u; \
    cp16(sA, gA); cp16(sB, gB); \
    cp16(sA + 64 * 80, gA + (size_t)64 * Kfull); \
    cp16(sB + 64 * 80, gB + (size_t)64 * Kfull); \
} while (0)

    LOADSK(0, 0);
    asm volatile("cp.async.commit_group;" ::: "memory");
    if (nk > 1) LOADSK(1, 1);
    asm volatile("cp.async.commit_group;" ::: "memory");

    const uint32_t aoff = (uint32_t)((moff + (lane & 15)) * 80 + ((lane >> 4) & 1) * 16);
    const uint32_t boff = 10240u +
        (uint32_t)((noff + (lane & 7) + ((lane >> 4) & 1) * 8) * 80 + ((lane >> 3) & 1) * 16);

    for (int ks = 0; ks < nk; ks++) {
        asm volatile("cp.async.wait_group %0;" :: "n"(1) : "memory");
        __syncthreads();
        if (ks + 2 < nk) { LOADSK((ks + 2) % 3, ks + 2); }
        asm volatile("cp.async.commit_group;" ::: "memory");

        const uint32_t so = sb + (uint32_t)(ks % 3) * 20480u;
#pragma unroll
        for (int kk = 0; kk < 2; kk++) {
            unsigned a0[4], a1[4], b[4][4];
            ldsm4(a0, so + aoff + kk * 32);
            ldsm4(a1, so + aoff + 16 * 80 + kk * 32);
#pragma unroll
            for (int nj = 0; nj < 4; nj++)
                ldsm4(b[nj], so + boff + nj * 16 * 80 + kk * 32);
#pragma unroll
            for (int nj = 0; nj < 4; nj++) {
                mma_f16(acc[0][2 * nj],     a0, &b[nj][0]);
                mma_f16(acc[0][2 * nj + 1], a0, &b[nj][2]);
                mma_f16(acc[1][2 * nj],     a1, &b[nj][0]);
                mma_f16(acc[1][2 * nj + 1], a1, &b[nj][2]);
            }
        }
    }
#undef LOADSK

    float* Pb = P + (size_t)kh * NROWS * N;
#pragma unroll
    for (int mi = 0; mi < 2; mi++) {
        const int r0 = bm + moff + 16 * mi + g;
#pragma unroll
        for (int ni = 0; ni < 8; ni++) {
            const int c = bn + noff + 8 * ni + 2 * t;
            float2 o0; o0.x = acc[mi][ni][0]; o0.y = acc[mi][ni][1];
            float2 o1; o1.x = acc[mi][ni][2]; o1.y = acc[mi][ni][3];
            *(float2*)(Pb + (size_t)r0 * N + c) = o0;
            *(float2*)(Pb + (size_t)(r0 + 8) * N + c) = o1;
        }
    }
}

// x[row] += p0 + p1 (+ bias)  (N = DMODEL)
__global__ __launch_bounds__(256)
void reduce_kernel(const float* __restrict__ P, const float* __restrict__ bias,
                   float* __restrict__ x)
{
    const int row = blockIdx.x, tid = threadIdx.x;
    const size_t o = (size_t)row * DMODEL / 4 + tid;
    const float4 a = ((const float4*)P)[o];
    const float4 b = ((const float4*)P)[o + (size_t)NROWS * DMODEL / 4];
    float4 v = ((float4*)x)[o];
    v.x += a.x + b.x; v.y += a.y + b.y; v.z += a.z + b.z; v.w += a.w + b.w;
    if (bias) {
        const float4 bb = ((const float4*)bias)[tid];
        v.x += bb.x; v.y += bb.y; v.z += bb.z; v.w += bb.w;
    }
    ((float4*)x)[o] = v;
}

// ---------------------------------------------------------------------------
// MMA flash attention v3 (unchanged)
// ---------------------------------------------------------------------------
#define ATTN_SMEM (128 * 144 + 4 * 64 * 144)
__global__ __launch_bounds__(256, 2)
void attn_mma(const __half* __restrict__ U, __half* __restrict__ O)
{
    const int q0 = blockIdx.x * 128, h = blockIdx.y, b = blockIdx.z;
    const int tid = threadIdx.x, warp = tid >> 5, lane = tid & 31;
    const int g = lane >> 2, t = lane & 3;

    extern __shared__ __align__(128) char asm_[];
    const uint32_t qb = s2u(asm_);
    const uint32_t kb0 = qb + 128 * 144;
    const uint32_t vb0 = kb0 + 2 * 64 * 144;

    const __half* Ub = U + (size_t)(b * SEQ) * 3072 + h * 64;

    {
        const int r = tid >> 1;
        const int sg = (tid & 1) * 64;
        const __half* gq = Ub + (size_t)(q0 + r) * 3072 + sg / 2;
        const uint32_t sq = qb + r * 144 + sg;
        cp16(sq, gq); cp16(sq + 16, gq + 8);
        cp16(sq + 32, gq + 16); cp16(sq + 48, gq + 24);
    }
    asm volatile("cp.async.commit_group;" ::: "memory");
    asm volatile("cp.async.wait_group 0;" ::: "memory");
    __syncthreads();

    unsigned qf[4][4];
    {
        const uint32_t qa = qb + (16 * warp + (lane & 15)) * 144 + ((lane >> 4) & 1) * 16;
        const __half2 sc = __floats2half2_rn(0.125f, 0.125f);
#pragma unroll
        for (int kk = 0; kk < 4; kk++) {
            ldsm4(qf[kk], qa + kk * 32);
#pragma unroll
            for (int e = 0; e < 4; e++) {
                __half2 v = *(__half2*)&qf[kk][e];
                v = __hmul2(v, sc);
                qf[kk][e] = *(unsigned*)&v;
            }
        }
    }

    float o[8][4];
#pragma unroll
    for (int d = 0; d < 8; d++)
#pragma unroll
        for (int e = 0; e < 4; e++) o[d][e] = 0.0f;
    float m0 = -1e30f, m1 = -1e30f, l0 = 0.0f, l1 = 0.0f;
    const int wbase = q0 + 16 * warp;
    const int row0 = wbase + g;
    const int nch = (q0 >> 6) + 2;

#define LOADKV(ci) do { \
    const int _c0 = (ci) * 64; \
    const int _bf = (ci) & 1; \
    const int tt = tid & 127; \
    const int r = tt >> 1, sgh = (tt & 1) * 32; \
    const __half* gp = Ub + (size_t)(_c0 + r) * 3072 + ((tid >= 128) ? 2048 : 1024) + sgh; \
    const uint32_t sp = ((tid >= 128) ? vb0 : kb0) + _bf * (64 * 144) + r * 144 + sgh * 2; \
    cp16(sp, gp); cp16(sp + 16, gp + 8); \
    cp16(sp + 32, gp + 16); cp16(sp + 48, gp + 24); \
} while (0)

    LOADKV(0);
    asm volatile("cp.async.commit_group;" ::: "memory");

    for (int ci = 0; ci < nch; ci++) {
        const int c0 = ci * 64;
        const bool pre = (ci + 1 < nch);
        if (pre) {
            LOADKV(ci + 1);
            asm volatile("cp.async.commit_group;" ::: "memory");
            asm volatile("cp.async.wait_group 1;" ::: "memory");
        } else {
            asm volatile("cp.async.wait_group 0;" ::: "memory");
        }
        __syncthreads();

        const uint32_t kb = kb0 + (ci & 1) * (64 * 144);
        const uint32_t vb = vb0 + (ci & 1) * (64 * 144);

        float s[8][4];
#pragma unroll
        for (int j = 0; j < 8; j++)
#pragma unroll
            for (int e = 0; e < 4; e++) s[j][e] = 0.0f;
#pragma unroll
        for (int kk = 0; kk < 4; kk++) {
            unsigned bf[4][4];
#pragma unroll
            for (int nj = 0; nj < 4; nj++)
                ldsm4(bf[nj], kb + (nj * 16 + (lane & 7) + ((lane >> 4) & 1) * 8) * 144
                                + ((lane >> 3) & 1) * 16 + kk * 32);
#pragma unroll
            for (int nj = 0; nj < 4; nj++) {
                mma_f16(s[2 * nj],     qf[kk], &bf[nj][0]);
                mma_f16(s[2 * nj + 1], qf[kk], &bf[nj][2]);
            }
        }

        if (c0 + 63 > wbase) {
#pragma unroll
            for (int j = 0; j < 8; j++) {
                const int cb = c0 + 8 * j + 2 * t;
                if (cb     > row0)     s[j][0] = -1e30f;
                if (cb + 1 > row0)     s[j][1] = -1e30f;
                if (cb     > row0 + 8) s[j][2] = -1e30f;
                if (cb + 1 > row0 + 8) s[j][3] = -1e30f;
            }
        }

        float cm0 = -1e30f, cm1 = -1e30f;
#pragma unroll
        for (int j = 0; j < 8; j++) {
            cm0 = fmaxf(cm0, fmaxf(s[j][0], s[j][1]));
            cm1 = fmaxf(cm1, fmaxf(s[j][2], s[j][3]));
        }
        cm0 = fmaxf(cm0, __shfl_xor_sync(0xffffffff, cm0, 1));
        cm0 = fmaxf(cm0, __shfl_xor_sync(0xffffffff, cm0, 2));
        cm1 = fmaxf(cm1, __shfl_xor_sync(0xffffffff, cm1, 1));
        cm1 = fmaxf(cm1, __shfl_xor_sync(0xffffffff, cm1, 2));
        const float nm0 = fmaxf(m0, cm0), nm1 = fmaxf(m1, cm1);
        const float f0 = __expf(m0 - nm0), f1 = __expf(m1 - nm1);
        m0 = nm0; m1 = nm1;

        unsigned pf[4][4];
        float sum0 = 0.0f, sum1 = 0.0f;
#pragma unroll
        for (int nj = 0; nj < 4; nj++) {
            const float pa0 = __expf(s[2 * nj][0] - nm0), pa1 = __expf(s[2 * nj][1] - nm0);
            const float pa2 = __expf(s[2 * nj][2] - nm1), pa3 = __expf(s[2 * nj][3] - nm1);
            const float pb0 = __expf(s[2 * nj + 1][0] - nm0), pb1 = __expf(s[2 * nj + 1][1] - nm0);
            const float pb2 = __expf(s[2 * nj + 1][2] - nm1), pb3 = __expf(s[2 * nj + 1][3] - nm1);
            sum0 += pa0 + pa1 + pb0 + pb1;
            sum1 += pa2 + pa3 + pb2 + pb3;
            pf[nj][0] = packh2(pa0, pa1);
            pf[nj][1] = packh2(pa2, pa3);
            pf[nj][2] = packh2(pb0, pb1);
            pf[nj][3] = packh2(pb2, pb3);
        }
        sum0 += __shfl_xor_sync(0xffffffff, sum0, 1);
        sum0 += __shfl_xor_sync(0xffffffff, sum0, 2);
        sum1 += __shfl_xor_sync(0xffffffff, sum1, 1);
        sum1 += __shfl_xor_sync(0xffffffff, sum1, 2);
        l0 = l0 * f0 + sum0;
        l1 = l1 * f1 + sum1;

#pragma unroll
        for (int d = 0; d < 8; d++) {
            o[d][0] *= f0; o[d][1] *= f0; o[d][2] *= f1; o[d][3] *= f1;
        }

#pragma unroll
        for (int kk = 0; kk < 4; kk++) {
            unsigned vf[4][4];
#pragma unroll
            for (int dj = 0; dj < 4; dj++)
                ldsm4t(vf[dj], vb + (kk * 16 + (lane & 7) + ((lane >> 3) & 1) * 8) * 144
                                 + (dj * 16 + ((lane >> 4) & 1) * 8) * 2);
#pragma unroll
            for (int dj = 0; dj < 4; dj++) {
                mma_f16(o[2 * dj],     pf[kk], &vf[dj][0]);
                mma_f16(o[2 * dj + 1], pf[kk], &vf[dj][2]);
            }
        }
        __syncthreads();
    }
#undef LOADKV

    const float il0 = 1.0f / l0, il1 = 1.0f / l1;
    __half* Ob = O + (size_t)(b * SEQ + row0) * TDIM + h * 64;
#pragma unroll
    for (int dj = 0; dj < 8; dj++) {
        const int c = 8 * dj + 2 * t;
        *(__half2*)(Ob + c)            = __floats2half2_rn(o[dj][0] * il0, o[dj][1] * il0);
        *(__half2*)(Ob + 8 * TDIM + c) = __floats2half2_rn(o[dj][2] * il1, o[dj][3] * il1);
    }
}

// ---------------------------------------------------------------------------
__global__ void conv16(const float* __restrict__ s, __half* __restrict__ d, int n4)
{
    for (int i = blockIdx.x * blockDim.x + threadIdx.x; i < n4; i += gridDim.x * blockDim.x) {
        const float4 v = ((const float4*)s)[i];
        ((__half2*)d)[2 * i]     = __floats2half2_rn(v.x, v.y);
        ((__half2*)d)[2 * i + 1] = __floats2half2_rn(v.z, v.w);
    }
}

__global__ void prep_kernel(const int* __restrict__ ids, const float* __restrict__ emb,
                            float* __restrict__ x, float2* __restrict__ tab,
                            const float* __restrict__ Wu, __half* __restrict__ wu16)
{
    if (blockIdx.x < NROWS) {
        ((float4*)(x + (size_t)blockIdx.x * DMODEL))[threadIdx.x] =
            ((const float4*)(emb + (size_t)ids[blockIdx.x] * DMODEL))[threadIdx.x];
    } else if (blockIdx.x < NROWS + 128) {
        const int idx = (blockIdx.x - NROWS) * 256 + threadIdx.x;
        const int s = idx >> 5, i = idx & 31;
        const float inv = exp2f(-(float)(2 * i) * (1.0f / 64.0f) * 13.287712379549449f);
        float sn, cs;
        sincosf((float)s * inv, &sn, &cs);
        tab[idx] = make_float2(cs, sn);
    } else {
        const int n4 = NLAYER * 3 * TDIM * DMODEL / 4;
        for (int i = (blockIdx.x - NROWS - 128) * 256 + threadIdx.x; i < n4; i += 2048 * 256) {
            const float4 v = ((const float4*)Wu)[i];
            ((__half2*)wu16)[2 * i]     = __floats2half2_rn(v.x, v.y);
            ((__half2*)wu16)[2 * i + 1] = __floats2half2_rn(v.z, v.w);
        }
    }
}

// warp-per-row LayerNorm -> fp16
__global__ __launch_bounds__(256)
void layernorm_kernel(const float* __restrict__ x, const float* __restrict__ w,
                      const float* __restrict__ b, __half* __restrict__ y16)
{
    const int warp = threadIdx.x >> 5, lane = threadIdx.x & 31;
    const int row = blockIdx.x * 8 + warp;
    const float4* xr = (const float4*)(x + (size_t)row * DMODEL);

    float4 v[8];
    float s = 0.0f;
#pragma unroll
    for (int j = 0; j < 8; j++) {
        v[j] = xr[lane + 32 * j];
        s += v[j].x + v[j].y + v[j].z + v[j].w;
    }
#pragma unroll
    for (int o = 16; o > 0; o >>= 1) s += __shfl_xor_sync(0xffffffff, s, o);
    const float mu = s * (1.0f / DMODEL);

    float q = 0.0f;
#pragma unroll
    for (int j = 0; j < 8; j++) {
        const float a = v[j].x - mu, b2 = v[j].y - mu, c = v[j].z - mu, d = v[j].w - mu;
        q += a * a + b2 * b2 + c * c + d * d;
    }
#pragma unroll
    for (int o = 16; o > 0; o >>= 1) q += __shfl_xor_sync(0xffffffff, q, o);
    const float rs = rsqrtf(q * (1.0f / DMODEL) + 1e-5f);

    uint2* yr = (uint2*)(y16 + (size_t)row * DMODEL);
#pragma unroll
    for (int j = 0; j < 8; j++) {
        const int idx = lane + 32 * j;
        const float4 wv = ((const float4*)w)[idx];
        const float4 bv = ((const float4*)b)[idx];
        const __half2 h0 = __floats2half2_rn((v[j].x - mu) * rs * wv.x + bv.x,
                                             (v[j].y - mu) * rs * wv.y + bv.y);
        const __half2 h1 = __floats2half2_rn((v[j].z - mu) * rs * wv.z + bv.z,
                                             (v[j].w - mu) * rs * wv.w + bv.w);
        uint2 o; o.x = *(const unsigned*)&h0; o.y = *(const unsigned*)&h1;
        yr[idx] = o;
    }
}

extern "C" void kernel_launch(void* const* d_in, const int* in_sizes, int n_in,
                              void* d_out, int out_size)
{
    (void)in_sizes; (void)n_in; (void)out_size;

    const int*   ids = (const int*)  d_in[0];
    const float* emb = (const float*)d_in[1];
    const float* Wu  = (const float*)d_in[2];
    const float* Wo  = (const float*)d_in[3];
    const float* n1w = (const float*)d_in[4];
    const float* n1b = (const float*)d_in[5];
    const float* n2w = (const float*)d_in[6];
    const float* n2b = (const float*)d_in[7];
    const float* f1w = (const float*)d_in[8];
    const float* f1b = (const float*)d_in[9];
    const float* f2w = (const float*)d_in[10];
    const float* f2b = (const float*)d_in[11];
    const float* fnw = (const float*)d_in[12];
    const float* fnb = (const float*)d_in[13];
    float* out = (float*)d_out;

    float *x, *part; float2* tab; __half *u16, *xn16, *at16, *h16, *w16;
    cudaGetSymbolAddress((void**)&x,    g_x);
    cudaGetSymbolAddress((void**)&part, g_part);
    cudaGetSymbolAddress((void**)&tab,  g_rope);
    cudaGetSymbolAddress((void**)&u16,  g_u16);
    cudaGetSymbolAddress((void**)&xn16, g_xn16);
    cudaGetSymbolAddress((void**)&at16, g_at16);
    cudaGetSymbolAddress((void**)&h16,  g_h16);
    cudaGetSymbolAddress((void**)&w16,  g_w16);

    cudaFuncSetAttribute((gemm_f16<0,1>), cudaFuncAttributeMaxDynamicSharedMemorySize, GEMM_SMEM);
    cudaFuncSetAttribute((gemm_f16<1,0>), cudaFuncAttributeMaxDynamicSharedMemorySize, GEMM_SMEM);
    cudaFuncSetAttribute((gemm_f16<3,0>), cudaFuncAttributeMaxDynamicSharedMemorySize, GEMM_SMEM);
    cudaFuncSetAttribute(gemm_sk,         cudaFuncAttributeMaxDynamicSharedMemorySize, GEMM_SMEM);
    cudaFuncSetAttribute(attn_mma,        cudaFuncAttributeMaxDynamicSharedMemorySize, ATTN_SMEM);

    static cudaStream_t s2 = nullptr;
    static cudaEvent_t evF = nullptr, evD = nullptr;
    if (!s2) {
        cudaStreamCreateWithFlags(&s2, cudaStreamNonBlocking);
        cudaEventCreateWithFlags(&evF, cudaEventDisableTiming);
        cudaEventCreateWithFlags(&evD, cudaEventDisableTiming);
    }

    // 1: prep   2: LN   3: conv emb   4: QKV GEMM (ncu anchor)
    prep_kernel<<<NROWS + 128 + 2048, 256>>>(ids, emb, x, tab, Wu, w16 + WU16);
    layernorm_kernel<<<NROWS / 8, 256>>>(x, n1w, n1b, xn16);
    conv16<<<2048, 256>>>(emb, w16 + EMB16, VOCAB * DMODEL / 4);
    gemm_f16<3,0><<<dim3(3 * TDIM / 128, NROWS / 128), 256, GEMM_SMEM>>>(
        xn16, w16 + WU16, nullptr, nullptr, nullptr, u16, tab, 3 * TDIM, DMODEL);

    cudaEventRecord(evF, 0);
    cudaStreamWaitEvent(s2, evF, 0);
    conv16<<<2048, 256, 0, s2>>>(Wo,  w16 + WO16,  NLAYER * DMODEL * TDIM / 4);
    conv16<<<2048, 256, 0, s2>>>(f1w, w16 + F116,  NLAYER * FFDIM * DMODEL / 4);
    conv16<<<2048, 256, 0, s2>>>(f2w, w16 + F216,  NLAYER * DMODEL * FFDIM / 4);
    cudaEventRecord(evD, s2);

    attn_mma<<<dim3(SEQ / 128, NHEAD, BATCH), 256, ATTN_SMEM>>>(u16, at16);
    cudaStreamWaitEvent(0, evD, 0);

    for (int l = 0; l < NLAYER; l++) {
        const __half* Wu_l = w16 + WU16 + (size_t)l * 3 * TDIM * DMODEL;
        const __half* Wo_l = w16 + WO16 + (size_t)l * DMODEL * TDIM;
        const __half* f1_l = w16 + F116 + (size_t)l * FFDIM * DMODEL;
        const __half* f2_l = w16 + F216 + (size_t)l * DMODEL * FFDIM;

        if (l > 0) {
            layernorm_kernel<<<NROWS / 8, 256>>>(x, n1w + l * DMODEL, n1b + l * DMODEL, xn16);
            gemm_f16<3,0><<<dim3(3 * TDIM / 128, NROWS / 128), 256, GEMM_SMEM>>>(
                xn16, Wu_l, nullptr, nullptr, nullptr, u16, tab, 3 * TDIM, DMODEL);
            attn_mma<<<dim3(SEQ / 128, NHEAD, BATCH), 256, ATTN_SMEM>>>(u16, at16);
        }

        // Wo: split-K2 (256 blocks = full wave) + reduce into residual
        gemm_sk<<<dim3(DMODEL / 128, NROWS / 128, 2), 256, GEMM_SMEM>>>(
            at16, Wo_l, part, DMODEL, TDIM);
        reduce_kernel<<<NROWS, 256>>>(part, nullptr, x);

        layernorm_kernel<<<NROWS / 8, 256>>>(x, n2w + l * DMODEL, n2b + l * DMODEL, xn16);

        gemm_f16<1,0><<<dim3(FFDIM / 128, NROWS / 128), 256, GEMM_SMEM>>>(
            xn16, f1_l, f1b + (size_t)l * FFDIM, nullptr, nullptr, h16, nullptr, FFDIM, DMODEL);

        // FFN2: split-K2 + reduce (bias + residual)
        gemm_sk<<<dim3(DMODEL / 128, NROWS / 128, 2), 256, GEMM_SMEM>>>(
            h16, f2_l, part, DMODEL, FFDIM);
        reduce_kernel<<<NROWS, 256>>>(part, f2b + (size_t)l * DMODEL, x);

        (void)Wo; (void)f2w;
    }

    layernorm_kernel<<<NROWS / 8, 256>>>(x, fnw, fnb, xn16);

    gemm_f16<0,1><<<dim3(NROWS / 128, VOCAB / 128), 256, GEMM_SMEM>>>(
        xn16, w16 + EMB16, nullptr, nullptr, out, nullptr, nullptr, VOCAB, DMODEL);
}

// round 15
// speedup vs baseline: 1.0682x; 1.0231x over previous
#include <cuda_runtime.h>
#include <cuda_fp16.h>
#include <math.h>
#include <stdint.h>

#define BATCH   2
#define SEQ     1024
#define NROWS   (BATCH * SEQ)
#define DMODEL  1024
#define NHEAD   16
#define HDIM    64
#define TDIM    1024
#define FFDIM   4096
#define NLAYER  8
#define VOCAB   32000

#define WU16  0
#define WO16  25165824u
#define F116  33554432u
#define F216  67108864u
#define EMB16 100663296u
#define W16_TOTAL 133431296u

__device__ float  g_x [NROWS * DMODEL];
__device__ float  g_part[2 * NROWS * DMODEL];
__device__ float2 g_rope[SEQ * 32];
__device__ __half g_u16 [NROWS * 3 * TDIM];
__device__ __half g_xn16[NROWS * DMODEL];
__device__ __half g_at16[NROWS * TDIM];
__device__ __half g_h16 [NROWS * FFDIM];
__device__ __half g_w16 [W16_TOTAL];

__device__ __forceinline__ float gelu_exact(float v) {
    return 0.5f * v * (1.0f + erff(v * 0.70710678118654752440f));
}
__device__ __forceinline__ uint32_t s2u(const void* p) {
    uint32_t a;
    asm("{ .reg .u64 t; cvta.to.shared.u64 t, %1; cvt.u32.u64 %0, t; }" : "=r"(a) : "l"(p));
    return a;
}
__device__ __forceinline__ void cp16(uint32_t s, const void* g) {
    asm volatile("cp.async.cg.shared.global [%0], [%1], 16;" :: "r"(s), "l"(g));
}
__device__ __forceinline__ void ldsm4(unsigned* r, uint32_t a) {
    asm volatile("ldmatrix.sync.aligned.m8n8.x4.shared.b16 {%0,%1,%2,%3}, [%4];"
        : "=r"(r[0]), "=r"(r[1]), "=r"(r[2]), "=r"(r[3]) : "r"(a));
}
__device__ __forceinline__ void ldsm4t(unsigned* r, uint32_t a) {
    asm volatile("ldmatrix.sync.aligned.m8n8.x4.trans.shared.b16 {%0,%1,%2,%3}, [%4];"
        : "=r"(r[0]), "=r"(r[1]), "=r"(r[2]), "=r"(r[3]) : "r"(a));
}
__device__ __forceinline__ void mma_f16(float* c, const unsigned* a, const unsigned* b) {
    asm volatile(
        "mma.sync.aligned.m16n8k16.row.col.f32.f16.f16.f32 "
        "{%0,%1,%2,%3},{%4,%5,%6,%7},{%8,%9},{%0,%1,%2,%3};"
        : "+f"(c[0]), "+f"(c[1]), "+f"(c[2]), "+f"(c[3])
        : "r"(a[0]), "r"(a[1]), "r"(a[2]), "r"(a[3]), "r"(b[0]), "r"(b[1]));
}
__device__ __forceinline__ void rot(float& a, float& b, float2 cs) {
    const float t0 = a * cs.x - b * cs.y;
    b = b * cs.x + a * cs.y;
    a = t0;
}
__device__ __forceinline__ unsigned packh2(float a, float b) {
    __half2 h = __floats2half2_rn(a, b);
    return *(unsigned*)&h;
}

// ---------------------------------------------------------------------------
// fp16 GEMM 128x128: C = A @ B^T
// MODE 0: fp32 C   MODE 1: gelu(acc+bias)->fp16   MODE 3: rope->fp16 (QKV)
// SWAP=1: blockIdx.x indexes M (logits)
// ---------------------------------------------------------------------------
template<int MODE, int SWAP>
__global__ __launch_bounds__(256)
void gemm_f16(const __half* __restrict__ A, const __half* __restrict__ B,
              const float* __restrict__ bias, float* __restrict__ C,
              __half* __restrict__ C16, const float2* __restrict__ tab,
              int N, int K)
{
    extern __shared__ __align__(128) char smem[];
    const uint32_t sb = s2u(smem);
    const int tid = threadIdx.x, warp = tid >> 5, lane = tid & 31;
    const int bm = (SWAP ? blockIdx.x : blockIdx.y) * 128;
    const int bn = (SWAP ? blockIdx.y : blockIdx.x) * 128;
    const int moff = (warp & 3) * 32, noff = (warp >> 2) * 64;
    const int g = lane >> 2, t = lane & 3;
    const int nk = K >> 5;
    const int lrow = tid >> 2, lc = tid & 3;

    float acc[2][8][4];
#pragma unroll
    for (int mi = 0; mi < 2; mi++)
#pragma unroll
        for (int ni = 0; ni < 8; ni++)
#pragma unroll
            for (int e = 0; e < 4; e++) acc[mi][ni][e] = 0.0f;

#define LOADST(st, ks) do { \
    const uint32_t so = sb + (uint32_t)(st) * 20480u; \
    const __half* gA = A + (size_t)(bm + lrow) * K + (ks) * 32 + lc * 8; \
    const __half* gB = B + (size_t)(bn + lrow) * K + (ks) * 32 + lc * 8; \
    const uint32_t sA = so + lrow * 80 + lc * 16; \
    const uint32_t sB = sA + 10240u; \
    cp16(sA, gA); cp16(sB, gB); \
    cp16(sA + 64 * 80, gA + (size_t)64 * K); \
    cp16(sB + 64 * 80, gB + (size_t)64 * K); \
} while (0)

    LOADST(0, 0);
    asm volatile("cp.async.commit_group;" ::: "memory");
    if (nk > 1) LOADST(1, 1);
    asm volatile("cp.async.commit_group;" ::: "memory");

    const uint32_t aoff = (uint32_t)((moff + (lane & 15)) * 80 + ((lane >> 4) & 1) * 16);
    const uint32_t boff = 10240u +
        (uint32_t)((noff + (lane & 7) + ((lane >> 4) & 1) * 8) * 80 + ((lane >> 3) & 1) * 16);

    for (int ks = 0; ks < nk; ks++) {
        asm volatile("cp.async.wait_group %0;" :: "n"(1) : "memory");
        __syncthreads();
        if (ks + 2 < nk) { LOADST((ks + 2) % 3, ks + 2); }
        asm volatile("cp.async.commit_group;" ::: "memory");

        const uint32_t so = sb + (uint32_t)(ks % 3) * 20480u;
#pragma unroll
        for (int kk = 0; kk < 2; kk++) {
            unsigned a0[4], a1[4], b[4][4];
            ldsm4(a0, so + aoff + kk * 32);
            ldsm4(a1, so + aoff + 16 * 80 + kk * 32);
#pragma unroll
            for (int nj = 0; nj < 4; nj++)
                ldsm4(b[nj], so + boff + nj * 16 * 80 + kk * 32);
#pragma unroll
            for (int nj = 0; nj < 4; nj++) {
                mma_f16(acc[0][2 * nj],     a0, &b[nj][0]);
                mma_f16(acc[0][2 * nj + 1], a0, &b[nj][2]);
                mma_f16(acc[1][2 * nj],     a1, &b[nj][0]);
                mma_f16(acc[1][2 * nj + 1], a1, &b[nj][2]);
            }
        }
    }
#undef LOADST

    if (MODE == 3) {
        const int region = (bn + noff) >> 10;
        if (region < 2) {
#pragma unroll
            for (int mi = 0; mi < 2; mi++) {
                const int r0 = bm + moff + 16 * mi + g;
                const int s0 = r0 & (SEQ - 1);
#pragma unroll
                for (int ni = 0; ni < 4; ni++) {
                    const int i0 = 8 * ni + 2 * t;
                    const float2 c00 = tab[s0 * 32 + i0];
                    const float2 c01 = tab[s0 * 32 + i0 + 1];
                    const float2 c10 = tab[(s0 + 8) * 32 + i0];
                    const float2 c11 = tab[(s0 + 8) * 32 + i0 + 1];
                    rot(acc[mi][ni][0], acc[mi][ni + 4][0], c00);
                    rot(acc[mi][ni][1], acc[mi][ni + 4][1], c01);
                    rot(acc[mi][ni][2], acc[mi][ni + 4][2], c10);
                    rot(acc[mi][ni][3], acc[mi][ni + 4][3], c11);
                }
            }
        }
    }

#pragma unroll
    for (int mi = 0; mi < 2; mi++) {
        const int r0 = bm + moff + 16 * mi + g;
#pragma unroll
        for (int ni = 0; ni < 8; ni++) {
            const int c = bn + noff + 8 * ni + 2 * t;
            float v00 = acc[mi][ni][0], v01 = acc[mi][ni][1];
            float v10 = acc[mi][ni][2], v11 = acc[mi][ni][3];
            if (MODE == 1 || MODE == 3) {
                if (MODE == 1) {
                    const float b0 = bias[c], b1 = bias[c + 1];
                    v00 = gelu_exact(v00 + b0); v01 = gelu_exact(v01 + b1);
                    v10 = gelu_exact(v10 + b0); v11 = gelu_exact(v11 + b1);
                }
                *(__half2*)(C16 + (size_t)r0 * N + c)       = __floats2half2_rn(v00, v01);
                *(__half2*)(C16 + (size_t)(r0 + 8) * N + c) = __floats2half2_rn(v10, v11);
            } else {
                float2 o0; o0.x = v00; o0.y = v01;
                float2 o1; o1.x = v10; o1.y = v11;
                *(float2*)(C + (size_t)r0 * N + c) = o0;
                *(float2*)(C + (size_t)(r0 + 8) * N + c) = o1;
            }
        }
    }
}
#define GEMM_SMEM (3 * 20480)

// ---------------------------------------------------------------------------
// Split-K GEMM (partials to P, fp32)
// ---------------------------------------------------------------------------
__global__ __launch_bounds__(256)
void gemm_sk(const __half* __restrict__ A, const __half* __restrict__ B,
             float* __restrict__ P, int N, int Kfull)
{
    extern __shared__ __align__(128) char smem[];
    const uint32_t sb = s2u(smem);
    const int tid = threadIdx.x, warp = tid >> 5, lane = tid & 31;
    const int bm = blockIdx.y * 128, bn = blockIdx.x * 128;
    const int kh = blockIdx.z;
    const int Kh = Kfull >> 1;
    const int koff = kh * Kh;
    const int moff = (warp & 3) * 32, noff = (warp >> 2) * 64;
    const int g = lane >> 2, t = lane & 3;
    const int nk = Kh >> 5;
    const int lrow = tid >> 2, lc = tid & 3;

    float acc[2][8][4];
#pragma unroll
    for (int mi = 0; mi < 2; mi++)
#pragma unroll
        for (int ni = 0; ni < 8; ni++)
#pragma unroll
            for (int e = 0; e < 4; e++) acc[mi][ni][e] = 0.0f;

#define LOADSK(st, ks) do { \
    const uint32_t so = sb + (uint32_t)(st) * 20480u; \
    const __half* gA = A + (size_t)(bm + lrow) * Kfull + koff + (ks) * 32 + lc * 8; \
    const __half* gB = B + (size_t)(bn + lrow) * Kfull + koff + (ks) * 32 + lc * 8; \
    const uint32_t sA = so + lrow * 80 + lc * 16; \
    const uint32_t sB = sA + 10240u; \
    cp16(sA, gA); cp16(sB, gB); \
    cp16(sA + 64 * 80, gA + (size_t)64 * Kfull); \
    cp16(sB + 64 * 80, gB + (size_t)64 * Kfull); \
} while (0)

    LOADSK(0, 0);
    asm volatile("cp.async.commit_group;" ::: "memory");
    if (nk > 1) LOADSK(1, 1);
    asm volatile("cp.async.commit_group;" ::: "memory");

    const uint32_t aoff = (uint32_t)((moff + (lane & 15)) * 80 + ((lane >> 4) & 1) * 16);
    const uint32_t boff = 10240u +
        (uint32_t)((noff + (lane & 7) + ((lane >> 4) & 1) * 8) * 80 + ((lane >> 3) & 1) * 16);

    for (int ks = 0; ks < nk; ks++) {
        asm volatile("cp.async.wait_group %0;" :: "n"(1) : "memory");
        __syncthreads();
        if (ks + 2 < nk) { LOADSK((ks + 2) % 3, ks + 2); }
        asm volatile("cp.async.commit_group;" ::: "memory");

        const uint32_t so = sb + (uint32_t)(ks % 3) * 20480u;
#pragma unroll
        for (int kk = 0; kk < 2; kk++) {
            unsigned a0[4], a1[4], b[4][4];
            ldsm4(a0, so + aoff + kk * 32);
            ldsm4(a1, so + aoff + 16 * 80 + kk * 32);
#pragma unroll
            for (int nj = 0; nj < 4; nj++)
                ldsm4(b[nj], so + boff + nj * 16 * 80 + kk * 32);
#pragma unroll
            for (int nj = 0; nj < 4; nj++) {
                mma_f16(acc[0][2 * nj],     a0, &b[nj][0]);
                mma_f16(acc[0][2 * nj + 1], a0, &b[nj][2]);
                mma_f16(acc[1][2 * nj],     a1, &b[nj][0]);
                mma_f16(acc[1][2 * nj + 1], a1, &b[nj][2]);
            }
        }
    }
#undef LOADSK

    float* Pb = P + (size_t)kh * NROWS * N;
#pragma unroll
    for (int mi = 0; mi < 2; mi++) {
        const int r0 = bm + moff + 16 * mi + g;
#pragma unroll
        for (int ni = 0; ni < 8; ni++) {
            const int c = bn + noff + 8 * ni + 2 * t;
            float2 o0; o0.x = acc[mi][ni][0]; o0.y = acc[mi][ni][1];
            float2 o1; o1.x = acc[mi][ni][2]; o1.y = acc[mi][ni][3];
            *(float2*)(Pb + (size_t)r0 * N + c) = o0;
            *(float2*)(Pb + (size_t)(r0 + 8) * N + c) = o1;
        }
    }
}

// ---------------------------------------------------------------------------
// fused: x += p0 + p1 (+bias); then LayerNorm(x) -> fp16 (warp-per-row)
// ---------------------------------------------------------------------------
__global__ __launch_bounds__(256)
void reduce_ln(const float* __restrict__ P, const float* __restrict__ bias,
               float* __restrict__ x, const float* __restrict__ w,
               const float* __restrict__ b, __half* __restrict__ y16)
{
    const int warp = threadIdx.x >> 5, lane = threadIdx.x & 31;
    const int row = blockIdx.x * 8 + warp;
    const size_t ro = (size_t)row * (DMODEL / 4);
    const float4* p0 = (const float4*)P + ro;
    const float4* p1 = (const float4*)P + ro + (size_t)NROWS * (DMODEL / 4);
    float4* xr = (float4*)x + ro;

    float4 v[8];
    float s = 0.0f;
#pragma unroll
    for (int j = 0; j < 8; j++) {
        const int idx = lane + 32 * j;
        float4 a = p0[idx];
        const float4 c = p1[idx];
        float4 xv = xr[idx];
        a.x += c.x; a.y += c.y; a.z += c.z; a.w += c.w;
        if (bias) {
            const float4 bb = ((const float4*)bias)[idx];
            a.x += bb.x; a.y += bb.y; a.z += bb.z; a.w += bb.w;
        }
        xv.x += a.x; xv.y += a.y; xv.z += a.z; xv.w += a.w;
        xr[idx] = xv;
        v[j] = xv;
        s += xv.x + xv.y + xv.z + xv.w;
    }
#pragma unroll
    for (int o = 16; o > 0; o >>= 1) s += __shfl_xor_sync(0xffffffff, s, o);
    const float mu = s * (1.0f / DMODEL);

    float q = 0.0f;
#pragma unroll
    for (int j = 0; j < 8; j++) {
        const float a = v[j].x - mu, b2 = v[j].y - mu, c = v[j].z - mu, d = v[j].w - mu;
        q += a * a + b2 * b2 + c * c + d * d;
    }
#pragma unroll
    for (int o = 16; o > 0; o >>= 1) q += __shfl_xor_sync(0xffffffff, q, o);
    const float rs = rsqrtf(q * (1.0f / DMODEL) + 1e-5f);

    uint2* yr = (uint2*)(y16 + (size_t)row * DMODEL);
#pragma unroll
    for (int j = 0; j < 8; j++) {
        const int idx = lane + 32 * j;
        const float4 wv = ((const float4*)w)[idx];
        const float4 bv = ((const float4*)b)[idx];
        const __half2 h0 = __floats2half2_rn((v[j].x - mu) * rs * wv.x + bv.x,
                                             (v[j].y - mu) * rs * wv.y + bv.y);
        const __half2 h1 = __floats2half2_rn((v[j].z - mu) * rs * wv.z + bv.z,
                                             (v[j].w - mu) * rs * wv.w + bv.w);
        uint2 o; o.x = *(const unsigned*)&h0; o.y = *(const unsigned*)&h1;
        yr[idx] = o;
    }
}

// warp-per-row LayerNorm -> fp16 (prologue only)
__global__ __launch_bounds__(256)
void layernorm_kernel(const float* __restrict__ x, const float* __restrict__ w,
                      const float* __restrict__ b, __half* __restrict__ y16)
{
    const int warp = threadIdx.x >> 5, lane = threadIdx.x & 31;
    const int row = blockIdx.x * 8 + warp;
    const float4* xr = (const float4*)(x + (size_t)row * DMODEL);

    float4 v[8];
    float s = 0.0f;
#pragma unroll
    for (int j = 0; j < 8; j++) {
        v[j] = xr[lane + 32 * j];
        s += v[j].x + v[j].y + v[j].z + v[j].w;
    }
#pragma unroll
    for (int o = 16; o > 0; o >>= 1) s += __shfl_xor_sync(0xffffffff, s, o);
    const float mu = s * (1.0f / DMODEL);

    float q = 0.0f;
#pragma unroll
    for (int j = 0; j < 8; j++) {
        const float a = v[j].x - mu, b2 = v[j].y - mu, c = v[j].z - mu, d = v[j].w - mu;
        q += a * a + b2 * b2 + c * c + d * d;
    }
#pragma unroll
    for (int o = 16; o > 0; o >>= 1) q += __shfl_xor_sync(0xffffffff, q, o);
    const float rs = rsqrtf(q * (1.0f / DMODEL) + 1e-5f);

    uint2* yr = (uint2*)(y16 + (size_t)row * DMODEL);
#pragma unroll
    for (int j = 0; j < 8; j++) {
        const int idx = lane + 32 * j;
        const float4 wv = ((const float4*)w)[idx];
        const float4 bv = ((const float4*)b)[idx];
        const __half2 h0 = __floats2half2_rn((v[j].x - mu) * rs * wv.x + bv.x,
                                             (v[j].y - mu) * rs * wv.y + bv.y);
        const __half2 h1 = __floats2half2_rn((v[j].z - mu) * rs * wv.z + bv.z,
                                             (v[j].w - mu) * rs * wv.w + bv.w);
        uint2 o; o.x = *(const unsigned*)&h0; o.y = *(const unsigned*)&h1;
        yr[idx] = o;
    }
}

// ---------------------------------------------------------------------------
// MMA flash attention v3 (unchanged)
// ---------------------------------------------------------------------------
#define ATTN_SMEM (128 * 144 + 4 * 64 * 144)
__global__ __launch_bounds__(256, 2)
void attn_mma(const __half* __restrict__ U, __half* __restrict__ O)
{
    const int q0 = blockIdx.x * 128, h = blockIdx.y, b = blockIdx.z;
    const int tid = threadIdx.x, warp = tid >> 5, lane = tid & 31;
    const int g = lane >> 2, t = lane & 3;

    extern __shared__ __align__(128) char asm_[];
    const uint32_t qb = s2u(asm_);
    const uint32_t kb0 = qb + 128 * 144;
    const uint32_t vb0 = kb0 + 2 * 64 * 144;

    const __half* Ub = U + (size_t)(b * SEQ) * 3072 + h * 64;

    {
        const int r = tid >> 1;
        const int sg = (tid & 1) * 64;
        const __half* gq = Ub + (size_t)(q0 + r) * 3072 + sg / 2;
        const uint32_t sq = qb + r * 144 + sg;
        cp16(sq, gq); cp16(sq + 16, gq + 8);
        cp16(sq + 32, gq + 16); cp16(sq + 48, gq + 24);
    }
    asm volatile("cp.async.commit_group;" ::: "memory");
    asm volatile("cp.async.wait_group 0;" ::: "memory");
    __syncthreads();

    unsigned qf[4][4];
    {
        const uint32_t qa = qb + (16 * warp + (lane & 15)) * 144 + ((lane >> 4) & 1) * 16;
        const __half2 sc = __floats2half2_rn(0.125f, 0.125f);
#pragma unroll
        for (int kk = 0; kk < 4; kk++) {
            ldsm4(qf[kk], qa + kk * 32);
#pragma unroll
            for (int e = 0; e < 4; e++) {
                __half2 v = *(__half2*)&qf[kk][e];
                v = __hmul2(v, sc);
                qf[kk][e] = *(unsigned*)&v;
            }
        }
    }

    float o[8][4];
#pragma unroll
    for (int d = 0; d < 8; d++)
#pragma unroll
        for (int e = 0; e < 4; e++) o[d][e] = 0.0f;
    float m0 = -1e30f, m1 = -1e30f, l0 = 0.0f, l1 = 0.0f;
    const int wbase = q0 + 16 * warp;
    const int row0 = wbase + g;
    const int nch = (q0 >> 6) + 2;

#define LOADKV(ci) do { \
    const int _c0 = (ci) * 64; \
    const int _bf = (ci) & 1; \
    const int tt = tid & 127; \
    const int r = tt >> 1, sgh = (tt & 1) * 32; \
    const __half* gp = Ub + (size_t)(_c0 + r) * 3072 + ((tid >= 128) ? 2048 : 1024) + sgh; \
    const uint32_t sp = ((tid >= 128) ? vb0 : kb0) + _bf * (64 * 144) + r * 144 + sgh * 2; \
    cp16(sp, gp); cp16(sp + 16, gp + 8); \
    cp16(sp + 32, gp + 16); cp16(sp + 48, gp + 24); \
} while (0)

    LOADKV(0);
    asm volatile("cp.async.commit_group;" ::: "memory");

    for (int ci = 0; ci < nch; ci++) {
        const int c0 = ci * 64;
        const bool pre = (ci + 1 < nch);
        if (pre) {
            LOADKV(ci + 1);
            asm volatile("cp.async.commit_group;" ::: "memory");
            asm volatile("cp.async.wait_group 1;" ::: "memory");
        } else {
            asm volatile("cp.async.wait_group 0;" ::: "memory");
        }
        __syncthreads();

        const uint32_t kb = kb0 + (ci & 1) * (64 * 144);
        const uint32_t vb = vb0 + (ci & 1) * (64 * 144);

        float s[8][4];
#pragma unroll
        for (int j = 0; j < 8; j++)
#pragma unroll
            for (int e = 0; e < 4; e++) s[j][e] = 0.0f;
#pragma unroll
        for (int kk = 0; kk < 4; kk++) {
            unsigned bf[4][4];
#pragma unroll
            for (int nj = 0; nj < 4; nj++)
                ldsm4(bf[nj], kb + (nj * 16 + (lane & 7) + ((lane >> 4) & 1) * 8) * 144
                                + ((lane >> 3) & 1) * 16 + kk * 32);
#pragma unroll
            for (int nj = 0; nj < 4; nj++) {
                mma_f16(s[2 * nj],     qf[kk], &bf[nj][0]);
                mma_f16(s[2 * nj + 1], qf[kk], &bf[nj][2]);
            }
        }

        if (c0 + 63 > wbase) {
#pragma unroll
            for (int j = 0; j < 8; j++) {
                const int cb = c0 + 8 * j + 2 * t;
                if (cb     > row0)     s[j][0] = -1e30f;
                if (cb + 1 > row0)     s[j][1] = -1e30f;
                if (cb     > row0 + 8) s[j][2] = -1e30f;
                if (cb + 1 > row0 + 8) s[j][3] = -1e30f;
            }
        }

        float cm0 = -1e30f, cm1 = -1e30f;
#pragma unroll
        for (int j = 0; j < 8; j++) {
            cm0 = fmaxf(cm0, fmaxf(s[j][0], s[j][1]));
            cm1 = fmaxf(cm1, fmaxf(s[j][2], s[j][3]));
        }
        cm0 = fmaxf(cm0, __shfl_xor_sync(0xffffffff, cm0, 1));
        cm0 = fmaxf(cm0, __shfl_xor_sync(0xffffffff, cm0, 2));
        cm1 = fmaxf(cm1, __shfl_xor_sync(0xffffffff, cm1, 1));
        cm1 = fmaxf(cm1, __shfl_xor_sync(0xffffffff, cm1, 2));
        const float nm0 = fmaxf(m0, cm0), nm1 = fmaxf(m1, cm1);
        const float f0 = __expf(m0 - nm0), f1 = __expf(m1 - nm1);
        m0 = nm0; m1 = nm1;

        unsigned pf[4][4];
        float sum0 = 0.0f, sum1 = 0.0f;
#pragma unroll
        for (int nj = 0; nj < 4; nj++) {
            const float pa0 = __expf(s[2 * nj][0] - nm0), pa1 = __expf(s[2 * nj][1] - nm0);
            const float pa2 = __expf(s[2 * nj][2] - nm1), pa3 = __expf(s[2 * nj][3] - nm1);
            const float pb0 = __expf(s[2 * nj + 1][0] - nm0), pb1 = __expf(s[2 * nj + 1][1] - nm0);
            const float pb2 = __expf(s[2 * nj + 1][2] - nm1), pb3 = __expf(s[2 * nj + 1][3] - nm1);
            sum0 += pa0 + pa1 + pb0 + pb1;
            sum1 += pa2 + pa3 + pb2 + pb3;
            pf[nj][0] = packh2(pa0, pa1);
            pf[nj][1] = packh2(pa2, pa3);
            pf[nj][2] = packh2(pb0, pb1);
            pf[nj][3] = packh2(pb2, pb3);
        }
        sum0 += __shfl_xor_sync(0xffffffff, sum0, 1);
        sum0 += __shfl_xor_sync(0xffffffff, sum0, 2);
        sum1 += __shfl_xor_sync(0xffffffff, sum1, 1);
        sum1 += __shfl_xor_sync(0xffffffff, sum1, 2);
        l0 = l0 * f0 + sum0;
        l1 = l1 * f1 + sum1;

#pragma unroll
        for (int d = 0; d < 8; d++) {
            o[d][0] *= f0; o[d][1] *= f0; o[d][2] *= f1; o[d][3] *= f1;
        }

#pragma unroll
        for (int kk = 0; kk < 4; kk++) {
            unsigned vf[4][4];
#pragma unroll
            for (int dj = 0; dj < 4; dj++)
                ldsm4t(vf[dj], vb + (kk * 16 + (lane & 7) + ((lane >> 3) & 1) * 8) * 144
                                 + (dj * 16 + ((lane >> 4) & 1) * 8) * 2);
#pragma unroll
            for (int dj = 0; dj < 4; dj++) {
                mma_f16(o[2 * dj],     pf[kk], &vf[dj][0]);
                mma_f16(o[2 * dj + 1], pf[kk], &vf[dj][2]);
            }
        }
        __syncthreads();
    }
#undef LOADKV

    const float il0 = 1.0f / l0, il1 = 1.0f / l1;
    __half* Ob = O + (size_t)(b * SEQ + row0) * TDIM + h * 64;
#pragma unroll
    for (int dj = 0; dj < 8; dj++) {
        const int c = 8 * dj + 2 * t;
        *(__half2*)(Ob + c)            = __floats2half2_rn(o[dj][0] * il0, o[dj][1] * il0);
        *(__half2*)(Ob + 8 * TDIM + c) = __floats2half2_rn(o[dj][2] * il1, o[dj][3] * il1);
    }
}

// ---------------------------------------------------------------------------
__global__ void conv16(const float* __restrict__ s, __half* __restrict__ d, int n4)
{
    for (int i = blockIdx.x * blockDim.x + threadIdx.x; i < n4; i += gridDim.x * blockDim.x) {
        const float4 v = ((const float4*)s)[i];
        ((__half2*)d)[2 * i]     = __floats2half2_rn(v.x, v.y);
        ((__half2*)d)[2 * i + 1] = __floats2half2_rn(v.z, v.w);
    }
}

__global__ void prep_kernel(const int* __restrict__ ids, const float* __restrict__ emb,
                            float* __restrict__ x, float2* __restrict__ tab,
                            const float* __restrict__ Wu, __half* __restrict__ wu16)
{
    if (blockIdx.x < NROWS) {
        ((float4*)(x + (size_t)blockIdx.x * DMODEL))[threadIdx.x] =
            ((const float4*)(emb + (size_t)ids[blockIdx.x] * DMODEL))[threadIdx.x];
    } else if (blockIdx.x < NROWS + 128) {
        const int idx = (blockIdx.x - NROWS) * 256 + threadIdx.x;
        const int s = idx >> 5, i = idx & 31;
        const float inv = exp2f(-(float)(2 * i) * (1.0f / 64.0f) * 13.287712379549449f);
        float sn, cs;
        sincosf((float)s * inv, &sn, &cs);
        tab[idx] = make_float2(cs, sn);
    } else {
        const int n4 = NLAYER * 3 * TDIM * DMODEL / 4;
        for (int i = (blockIdx.x - NROWS - 128) * 256 + threadIdx.x; i < n4; i += 2048 * 256) {
            const float4 v = ((const float4*)Wu)[i];
            ((__half2*)wu16)[2 * i]     = __floats2half2_rn(v.x, v.y);
            ((__half2*)wu16)[2 * i + 1] = __floats2half2_rn(v.z, v.w);
        }
    }
}

extern "C" void kernel_launch(void* const* d_in, const int* in_sizes, int n_in,
                              void* d_out, int out_size)
{
    (void)in_sizes; (void)n_in; (void)out_size;

    const int*   ids = (const int*)  d_in[0];
    const float* emb = (const float*)d_in[1];
    const float* Wu  = (const float*)d_in[2];
    const float* Wo  = (const float*)d_in[3];
    const float* n1w = (const float*)d_in[4];
    const float* n1b = (const float*)d_in[5];
    const float* n2w = (const float*)d_in[6];
    const float* n2b = (const float*)d_in[7];
    const float* f1w = (const float*)d_in[8];
    const float* f1b = (const float*)d_in[9];
    const float* f2w = (const float*)d_in[10];
    const float* f2b = (const float*)d_in[11];
    const float* fnw = (const float*)d_in[12];
    const float* fnb = (const float*)d_in[13];
    float* out = (float*)d_out;

    float *x, *part; float2* tab; __half *u16, *xn16, *at16, *h16, *w16;
    cudaGetSymbolAddress((void**)&x,    g_x);
    cudaGetSymbolAddress((void**)&part, g_part);
    cudaGetSymbolAddress((void**)&tab,  g_rope);
    cudaGetSymbolAddress((void**)&u16,  g_u16);
    cudaGetSymbolAddress((void**)&xn16, g_xn16);
    cudaGetSymbolAddress((void**)&at16, g_at16);
    cudaGetSymbolAddress((void**)&h16,  g_h16);
    cudaGetSymbolAddress((void**)&w16,  g_w16);

    cudaFuncSetAttribute((gemm_f16<0,1>), cudaFuncAttributeMaxDynamicSharedMemorySize, GEMM_SMEM);
    cudaFuncSetAttribute((gemm_f16<1,0>), cudaFuncAttributeMaxDynamicSharedMemorySize, GEMM_SMEM);
    cudaFuncSetAttribute((gemm_f16<3,0>), cudaFuncAttributeMaxDynamicSharedMemorySize, GEMM_SMEM);
    cudaFuncSetAttribute(gemm_sk,         cudaFuncAttributeMaxDynamicSharedMemorySize, GEMM_SMEM);
    cudaFuncSetAttribute(attn_mma,        cudaFuncAttributeMaxDynamicSharedMemorySize, ATTN_SMEM);

    static cudaStream_t s2 = nullptr;
    static cudaEvent_t evF = nullptr, evD = nullptr;
    if (!s2) {
        cudaStreamCreateWithFlags(&s2, cudaStreamNonBlocking);
        cudaEventCreateWithFlags(&evF, cudaEventDisableTiming);
        cudaEventCreateWithFlags(&evD, cudaEventDisableTiming);
    }

    // 1: prep   2: LN   3: conv emb   4: QKV GEMM (ncu anchor)
    prep_kernel<<<NROWS + 128 + 2048, 256>>>(ids, emb, x, tab, Wu, w16 + WU16);
    layernorm_kernel<<<NROWS / 8, 256>>>(x, n1w, n1b, xn16);
    conv16<<<2048, 256>>>(emb, w16 + EMB16, VOCAB * DMODEL / 4);
    gemm_f16<3,0><<<dim3(3 * TDIM / 128, NROWS / 128), 256, GEMM_SMEM>>>(
        xn16, w16 + WU16, nullptr, nullptr, u16, tab, 3 * TDIM, DMODEL);

    cudaEventRecord(evF, 0);
    cudaStreamWaitEvent(s2, evF, 0);
    conv16<<<2048, 256, 0, s2>>>(Wo,  w16 + WO16,  NLAYER * DMODEL * TDIM / 4);
    conv16<<<2048, 256, 0, s2>>>(f1w, w16 + F116,  NLAYER * FFDIM * DMODEL / 4);
    conv16<<<2048, 256, 0, s2>>>(f2w, w16 + F216,  NLAYER * DMODEL * FFDIM / 4);
    cudaEventRecord(evD, s2);

    attn_mma<<<dim3(SEQ / 128, NHEAD, BATCH), 256, ATTN_SMEM>>>(u16, at16);
    cudaStreamWaitEvent(0, evD, 0);

    for (int l = 0; l < NLAYER; l++) {
        const __half* Wu_l = w16 + WU16 + (size_t)(l + 1) * 3 * TDIM * DMODEL;
        const __half* Wo_l = w16 + WO16 + (size_t)l * DMODEL * TDIM;
        const __half* f1_l = w16 + F116 + (size_t)l * FFDIM * DMODEL;
        const __half* f2_l = w16 + F216 + (size_t)l * DMODEL * FFDIM;

        // Wo split-K + fused reduce+LN2
        gemm_sk<<<dim3(DMODEL / 128, NROWS / 128, 2), 256, GEMM_SMEM>>>(
            at16, Wo_l, part, DMODEL, TDIM);
        reduce_ln<<<NROWS / 8, 256>>>(part, nullptr, x,
                                      n2w + l * DMODEL, n2b + l * DMODEL, xn16);

        gemm_f16<1,0><<<dim3(FFDIM / 128, NROWS / 128), 256, GEMM_SMEM>>>(
            xn16, f1_l, f1b + (size_t)l * FFDIM, nullptr, h16, nullptr, FFDIM, DMODEL);

        // FFN2 split-K + fused reduce+(LN1 of next layer | final LN)
        gemm_sk<<<dim3(DMODEL / 128, NROWS / 128, 2), 256, GEMM_SMEM>>>(
            h16, f2_l, part, DMODEL, FFDIM);
        if (l + 1 < NLAYER) {
            reduce_ln<<<NROWS / 8, 256>>>(part, f2b + (size_t)l * DMODEL, x,
                                          n1w + (l + 1) * DMODEL, n1b + (l + 1) * DMODEL, xn16);
            gemm_f16<3,0><<<dim3(3 * TDIM / 128, NROWS / 128), 256, GEMM_SMEM>>>(
                xn16, Wu_l, nullptr, nullptr, u16, tab, 3 * TDIM, DMODEL);
            attn_mma<<<dim3(SEQ / 128, NHEAD, BATCH), 256, ATTN_SMEM>>>(u16, at16);
        } else {
            reduce_ln<<<NROWS / 8, 256>>>(part, f2b + (size_t)l * DMODEL, x,
                                          fnw, fnb, xn16);
        }
    }

    gemm_f16<0,1><<<dim3(NROWS / 128, VOCAB / 128), 256, GEMM_SMEM>>>(
        xn16, w16 + EMB16, nullptr, out, nullptr, nullptr, VOCAB, DMODEL);
}

// round 16
// speedup vs baseline: 1.0849x; 1.0156x over previous
#include <cuda_runtime.h>
#include <cuda_fp16.h>
#include <math.h>
#include <stdint.h>

#define BATCH   2
#define SEQ     1024
#define NROWS   (BATCH * SEQ)
#define DMODEL  1024
#define NHEAD   16
#define HDIM    64
#define TDIM    1024
#define FFDIM   4096
#define NLAYER  8
#define VOCAB   32000

#define WU16  0
#define WO16  25165824u
#define F116  33554432u
#define F216  67108864u
#define EMB16 100663296u
#define W16_TOTAL 133431296u

__device__ float  g_x [NROWS * DMODEL];
__device__ float  g_part[2 * NROWS * DMODEL];
__device__ float  g_attp[2 * BATCH * NHEAD * SEQ * 64];   // split partials (o)
__device__ float  g_attml[2 * BATCH * NHEAD * SEQ * 2];   // split partials (m,l)
__device__ float2 g_rope[SEQ * 32];
__device__ __half g_u16 [NROWS * 3 * TDIM];
__device__ __half g_xn16[NROWS * DMODEL];
__device__ __half g_at16[NROWS * TDIM];
__device__ __half g_h16 [NROWS * FFDIM];
__device__ __half g_w16 [W16_TOTAL];

__device__ __forceinline__ float gelu_exact(float v) {
    return 0.5f * v * (1.0f + erff(v * 0.70710678118654752440f));
}
__device__ __forceinline__ uint32_t s2u(const void* p) {
    uint32_t a;
    asm("{ .reg .u64 t; cvta.to.shared.u64 t, %1; cvt.u32.u64 %0, t; }" : "=r"(a) : "l"(p));
    return a;
}
__device__ __forceinline__ void cp16(uint32_t s, const void* g) {
    asm volatile("cp.async.cg.shared.global [%0], [%1], 16;" :: "r"(s), "l"(g));
}
__device__ __forceinline__ void ldsm4(unsigned* r, uint32_t a) {
    asm volatile("ldmatrix.sync.aligned.m8n8.x4.shared.b16 {%0,%1,%2,%3}, [%4];"
        : "=r"(r[0]), "=r"(r[1]), "=r"(r[2]), "=r"(r[3]) : "r"(a));
}
__device__ __forceinline__ void ldsm4t(unsigned* r, uint32_t a) {
    asm volatile("ldmatrix.sync.aligned.m8n8.x4.trans.shared.b16 {%0,%1,%2,%3}, [%4];"
        : "=r"(r[0]), "=r"(r[1]), "=r"(r[2]), "=r"(r[3]) : "r"(a));
}
__device__ __forceinline__ void mma_f16(float* c, const unsigned* a, const unsigned* b) {
    asm volatile(
        "mma.sync.aligned.m16n8k16.row.col.f32.f16.f16.f32 "
        "{%0,%1,%2,%3},{%4,%5,%6,%7},{%8,%9},{%0,%1,%2,%3};"
        : "+f"(c[0]), "+f"(c[1]), "+f"(c[2]), "+f"(c[3])
        : "r"(a[0]), "r"(a[1]), "r"(a[2]), "r"(a[3]), "r"(b[0]), "r"(b[1]));
}
__device__ __forceinline__ void rot(float& a, float& b, float2 cs) {
    const float t0 = a * cs.x - b * cs.y;
    b = b * cs.x + a * cs.y;
    a = t0;
}
__device__ __forceinline__ unsigned packh2(float a, float b) {
    __half2 h = __floats2half2_rn(a, b);
    return *(unsigned*)&h;
}

// ---------------------------------------------------------------------------
// fp16 GEMM 128x128 (unchanged, proven)
// MODE 0: fp32 C   MODE 1: gelu(acc+bias)->fp16   MODE 3: rope->fp16 (QKV)
// SWAP=1: blockIdx.x indexes M (logits)
// ---------------------------------------------------------------------------
template<int MODE, int SWAP>
__global__ __launch_bounds__(256)
void gemm_f16(const __half* __restrict__ A, const __half* __restrict__ B,
              const float* __restrict__ bias, float* __restrict__ C,
              __half* __restrict__ C16, const float2* __restrict__ tab,
              int N, int K)
{
    extern __shared__ __align__(128) char smem[];
    const uint32_t sb = s2u(smem);
    const int tid = threadIdx.x, warp = tid >> 5, lane = tid & 31;
    const int bm = (SWAP ? blockIdx.x : blockIdx.y) * 128;
    const int bn = (SWAP ? blockIdx.y : blockIdx.x) * 128;
    const int moff = (warp & 3) * 32, noff = (warp >> 2) * 64;
    const int g = lane >> 2, t = lane & 3;
    const int nk = K >> 5;
    const int lrow = tid >> 2, lc = tid & 3;

    float acc[2][8][4];
#pragma unroll
    for (int mi = 0; mi < 2; mi++)
#pragma unroll
        for (int ni = 0; ni < 8; ni++)
#pragma unroll
            for (int e = 0; e < 4; e++) acc[mi][ni][e] = 0.0f;

#define LOADST(st, ks) do { \
    const uint32_t so = sb + (uint32_t)(st) * 20480u; \
    const __half* gA = A + (size_t)(bm + lrow) * K + (ks) * 32 + lc * 8; \
    const __half* gB = B + (size_t)(bn + lrow) * K + (ks) * 32 + lc * 8; \
    const uint32_t sA = so + lrow * 80 + lc * 16; \
    const uint32_t sB = sA + 10240u; \
    cp16(sA, gA); cp16(sB, gB); \
    cp16(sA + 64 * 80, gA + (size_t)64 * K); \
    cp16(sB + 64 * 80, gB + (size_t)64 * K); \
} while (0)

    LOADST(0, 0);
    asm volatile("cp.async.commit_group;" ::: "memory");
    if (nk > 1) LOADST(1, 1);
    asm volatile("cp.async.commit_group;" ::: "memory");

    const uint32_t aoff = (uint32_t)((moff + (lane & 15)) * 80 + ((lane >> 4) & 1) * 16);
    const uint32_t boff = 10240u +
        (uint32_t)((noff + (lane & 7) + ((lane >> 4) & 1) * 8) * 80 + ((lane >> 3) & 1) * 16);

    for (int ks = 0; ks < nk; ks++) {
        asm volatile("cp.async.wait_group %0;" :: "n"(1) : "memory");
        __syncthreads();
        if (ks + 2 < nk) { LOADST((ks + 2) % 3, ks + 2); }
        asm volatile("cp.async.commit_group;" ::: "memory");

        const uint32_t so = sb + (uint32_t)(ks % 3) * 20480u;
#pragma unroll
        for (int kk = 0; kk < 2; kk++) {
            unsigned a0[4], a1[4], b[4][4];
            ldsm4(a0, so + aoff + kk * 32);
            ldsm4(a1, so + aoff + 16 * 80 + kk * 32);
#pragma unroll
            for (int nj = 0; nj < 4; nj++)
                ldsm4(b[nj], so + boff + nj * 16 * 80 + kk * 32);
#pragma unroll
            for (int nj = 0; nj < 4; nj++) {
                mma_f16(acc[0][2 * nj],     a0, &b[nj][0]);
                mma_f16(acc[0][2 * nj + 1], a0, &b[nj][2]);
                mma_f16(acc[1][2 * nj],     a1, &b[nj][0]);
                mma_f16(acc[1][2 * nj + 1], a1, &b[nj][2]);
            }
        }
    }
#undef LOADST

    if (MODE == 3) {
        const int region = (bn + noff) >> 10;
        if (region < 2) {
#pragma unroll
            for (int mi = 0; mi < 2; mi++) {
                const int r0 = bm + moff + 16 * mi + g;
                const int s0 = r0 & (SEQ - 1);
#pragma unroll
                for (int ni = 0; ni < 4; ni++) {
                    const int i0 = 8 * ni + 2 * t;
                    const float2 c00 = tab[s0 * 32 + i0];
                    const float2 c01 = tab[s0 * 32 + i0 + 1];
                    const float2 c10 = tab[(s0 + 8) * 32 + i0];
                    const float2 c11 = tab[(s0 + 8) * 32 + i0 + 1];
                    rot(acc[mi][ni][0], acc[mi][ni + 4][0], c00);
                    rot(acc[mi][ni][1], acc[mi][ni + 4][1], c01);
                    rot(acc[mi][ni][2], acc[mi][ni + 4][2], c10);
                    rot(acc[mi][ni][3], acc[mi][ni + 4][3], c11);
                }
            }
        }
    }

#pragma unroll
    for (int mi = 0; mi < 2; mi++) {
        const int r0 = bm + moff + 16 * mi + g;
#pragma unroll
        for (int ni = 0; ni < 8; ni++) {
            const int c = bn + noff + 8 * ni + 2 * t;
            float v00 = acc[mi][ni][0], v01 = acc[mi][ni][1];
            float v10 = acc[mi][ni][2], v11 = acc[mi][ni][3];
            if (MODE == 1 || MODE == 3) {
                if (MODE == 1) {
                    const float b0 = bias[c], b1 = bias[c + 1];
                    v00 = gelu_exact(v00 + b0); v01 = gelu_exact(v01 + b1);
                    v10 = gelu_exact(v10 + b0); v11 = gelu_exact(v11 + b1);
                }
                *(__half2*)(C16 + (size_t)r0 * N + c)       = __floats2half2_rn(v00, v01);
                *(__half2*)(C16 + (size_t)(r0 + 8) * N + c) = __floats2half2_rn(v10, v11);
            } else {
                float2 o0; o0.x = v00; o0.y = v01;
                float2 o1; o1.x = v10; o1.y = v11;
                *(float2*)(C + (size_t)r0 * N + c) = o0;
                *(float2*)(C + (size_t)(r0 + 8) * N + c) = o1;
            }
        }
    }
}
#define GEMM_SMEM (3 * 20480)

// ---------------------------------------------------------------------------
// Split-K GEMM (unchanged)
// ---------------------------------------------------------------------------
__global__ __launch_bounds__(256)
void gemm_sk(const __half* __restrict__ A, const __half* __restrict__ B,
             float* __restrict__ P, int N, int Kfull)
{
    extern __shared__ __align__(128) char smem[];
    const uint32_t sb = s2u(smem);
    const int tid = threadIdx.x, warp = tid >> 5, lane = tid & 31;
    const int bm = blockIdx.y * 128, bn = blockIdx.x * 128;
    const int kh = blockIdx.z;
    const int Kh = Kfull >> 1;
    const int koff = kh * Kh;
    const int moff = (warp & 3) * 32, noff = (warp >> 2) * 64;
    const int g = lane >> 2, t = lane & 3;
    const int nk = Kh >> 5;
    const int lrow = tid >> 2, lc = tid & 3;

    float acc[2][8][4];
#pragma unroll
    for (int mi = 0; mi < 2; mi++)
#pragma unroll
        for (int ni = 0; ni < 8; ni++)
#pragma unroll
            for (int e = 0; e < 4; e++) acc[mi][ni][e] = 0.0f;

#define LOADSK(st, ks) do { \
    const uint32_t so = sb + (uint32_t)(st) * 20480u; \
    const __half* gA = A + (size_t)(bm + lrow) * Kfull + koff + (ks) * 32 + lc * 8; \
    const __half* gB = B + (size_t)(bn + lrow) * Kfull + koff + (ks) * 32 + lc * 8; \
    const uint32_t sA = so + lrow * 80 + lc * 16; \
    const uint32_t sB = sA + 10240u; \
    cp16(sA, gA); cp16(sB, gB); \
    cp16(sA + 64 * 80, gA + (size_t)64 * Kfull); \
    cp16(sB + 64 * 80, gB + (size_t)64 * Kfull); \
} while (0)

    LOADSK(0, 0);
    asm volatile("cp.async.commit_group;" ::: "memory");
    if (nk > 1) LOADSK(1, 1);
    asm volatile("cp.async.commit_group;" ::: "memory");

    const uint32_t aoff = (uint32_t)((moff + (lane & 15)) * 80 + ((lane >> 4) & 1) * 16);
    const uint32_t boff = 10240u +
        (uint32_t)((noff + (lane & 7) + ((lane >> 4) & 1) * 8) * 80 + ((lane >> 3) & 1) * 16);

    for (int ks = 0; ks < nk; ks++) {
        asm volatile("cp.async.wait_group %0;" :: "n"(1) : "memory");
        __syncthreads();
        if (ks + 2 < nk) { LOADSK((ks + 2) % 3, ks + 2); }
        asm volatile("cp.async.commit_group;" ::: "memory");

        const uint32_t so = sb + (uint32_t)(ks % 3) * 20480u;
#pragma unroll
        for (int kk = 0; kk < 2; kk++) {
            unsigned a0[4], a1[4], b[4][4];
            ldsm4(a0, so + aoff + kk * 32);
            ldsm4(a1, so + aoff + 16 * 80 + kk * 32);
#pragma unroll
            for (int nj = 0; nj < 4; nj++)
                ldsm4(b[nj], so + boff + nj * 16 * 80 + kk * 32);
#pragma unroll
            for (int nj = 0; nj < 4; nj++) {
                mma_f16(acc[0][2 * nj],     a0, &b[nj][0]);
                mma_f16(acc[0][2 * nj + 1], a0, &b[nj][2]);
                mma_f16(acc[1][2 * nj],     a1, &b[nj][0]);
                mma_f16(acc[1][2 * nj + 1], a1, &b[nj][2]);
            }
        }
    }
#undef LOADSK

    float* Pb = P + (size_t)kh * NROWS * N;
#pragma unroll
    for (int mi = 0; mi < 2; mi++) {
        const int r0 = bm + moff + 16 * mi + g;
#pragma unroll
        for (int ni = 0; ni < 8; ni++) {
            const int c = bn + noff + 8 * ni + 2 * t;
            float2 o0; o0.x = acc[mi][ni][0]; o0.y = acc[mi][ni][1];
            float2 o1; o1.x = acc[mi][ni][2]; o1.y = acc[mi][ni][3];
            *(float2*)(Pb + (size_t)r0 * N + c) = o0;
            *(float2*)(Pb + (size_t)(r0 + 8) * N + c) = o1;
        }
    }
}

// ---------------------------------------------------------------------------
// fused: x += p0 + p1 (+bias); then LayerNorm(x) -> fp16 (warp-per-row)
// ---------------------------------------------------------------------------
__global__ __launch_bounds__(256)
void reduce_ln(const float* __restrict__ P, const float* __restrict__ bias,
               float* __restrict__ x, const float* __restrict__ w,
               const float* __restrict__ b, __half* __restrict__ y16)
{
    const int warp = threadIdx.x >> 5, lane = threadIdx.x & 31;
    const int row = blockIdx.x * 8 + warp;
    const size_t ro = (size_t)row * (DMODEL / 4);
    const float4* p0 = (const float4*)P + ro;
    const float4* p1 = (const float4*)P + ro + (size_t)NROWS * (DMODEL / 4);
    float4* xr = (float4*)x + ro;

    float4 v[8];
    float s = 0.0f;
#pragma unroll
    for (int j = 0; j < 8; j++) {
        const int idx = lane + 32 * j;
        float4 a = p0[idx];
        const float4 c = p1[idx];
        float4 xv = xr[idx];
        a.x += c.x; a.y += c.y; a.z += c.z; a.w += c.w;
        if (bias) {
            const float4 bb = ((const float4*)bias)[idx];
            a.x += bb.x; a.y += bb.y; a.z += bb.z; a.w += bb.w;
        }
        xv.x += a.x; xv.y += a.y; xv.z += a.z; xv.w += a.w;
        xr[idx] = xv;
        v[j] = xv;
        s += xv.x + xv.y + xv.z + xv.w;
    }
#pragma unroll
    for (int o = 16; o > 0; o >>= 1) s += __shfl_xor_sync(0xffffffff, s, o);
    const float mu = s * (1.0f / DMODEL);

    float q = 0.0f;
#pragma unroll
    for (int j = 0; j < 8; j++) {
        const float a = v[j].x - mu, b2 = v[j].y - mu, c = v[j].z - mu, d = v[j].w - mu;
        q += a * a + b2 * b2 + c * c + d * d;
    }
#pragma unroll
    for (int o = 16; o > 0; o >>= 1) q += __shfl_xor_sync(0xffffffff, q, o);
    const float rs = rsqrtf(q * (1.0f / DMODEL) + 1e-5f);

    uint2* yr = (uint2*)(y16 + (size_t)row * DMODEL);
#pragma unroll
    for (int j = 0; j < 8; j++) {
        const int idx = lane + 32 * j;
        const float4 wv = ((const float4*)w)[idx];
        const float4 bv = ((const float4*)b)[idx];
        const __half2 h0 = __floats2half2_rn((v[j].x - mu) * rs * wv.x + bv.x,
                                             (v[j].y - mu) * rs * wv.y + bv.y);
        const __half2 h1 = __floats2half2_rn((v[j].z - mu) * rs * wv.z + bv.z,
                                             (v[j].w - mu) * rs * wv.w + bv.w);
        uint2 o; o.x = *(const unsigned*)&h0; o.y = *(const unsigned*)&h1;
        yr[idx] = o;
    }
}

// warp-per-row LayerNorm -> fp16 (prologue only)
__global__ __launch_bounds__(256)
void layernorm_kernel(const float* __restrict__ x, const float* __restrict__ w,
                      const float* __restrict__ b, __half* __restrict__ y16)
{
    const int warp = threadIdx.x >> 5, lane = threadIdx.x & 31;
    const int row = blockIdx.x * 8 + warp;
    const float4* xr = (const float4*)(x + (size_t)row * DMODEL);

    float4 v[8];
    float s = 0.0f;
#pragma unroll
    for (int j = 0; j < 8; j++) {
        v[j] = xr[lane + 32 * j];
        s += v[j].x + v[j].y + v[j].z + v[j].w;
    }
#pragma unroll
    for (int o = 16; o > 0; o >>= 1) s += __shfl_xor_sync(0xffffffff, s, o);
    const float mu = s * (1.0f / DMODEL);

    float q = 0.0f;
#pragma unroll
    for (int j = 0; j < 8; j++) {
        const float a = v[j].x - mu, b2 = v[j].y - mu, c = v[j].z - mu, d = v[j].w - mu;
        q += a * a + b2 * b2 + c * c + d * d;
    }
#pragma unroll
    for (int o = 16; o > 0; o >>= 1) q += __shfl_xor_sync(0xffffffff, q, o);
    const float rs = rsqrtf(q * (1.0f / DMODEL) + 1e-5f);

    uint2* yr = (uint2*)(y16 + (size_t)row * DMODEL);
#pragma unroll
    for (int j = 0; j < 8; j++) {
        const int idx = lane + 32 * j;
        const float4 wv = ((const float4*)w)[idx];
        const float4 bv = ((const float4*)b)[idx];
        const __half2 h0 = __floats2half2_rn((v[j].x - mu) * rs * wv.x + bv.x,
                                             (v[j].y - mu) * rs * wv.y + bv.y);
        const __half2 h1 = __floats2half2_rn((v[j].z - mu) * rs * wv.z + bv.z,
                                             (v[j].w - mu) * rs * wv.w + bv.w);
        uint2 o; o.x = *(const unsigned*)&h0; o.y = *(const unsigned*)&h1;
        yr[idx] = o;
    }
}

// ---------------------------------------------------------------------------
// MMA flash attention v4: split-KV for heavy query tiles.
// grid (12, NHEAD, BATCH): s<8 -> tiles 7..4 in 2 KV-splits (partials),
// s>=8 -> tiles 3..0 direct. Max 8 chunks per block.
// ---------------------------------------------------------------------------
#define ATTN_SMEM (128 * 144 + 4 * 64 * 144)
__global__ __launch_bounds__(256, 2)
void attn_mma(const __half* __restrict__ U, __half* __restrict__ O,
              float* __restrict__ Po, float* __restrict__ Pml)
{
    const int s = blockIdx.x, h = blockIdx.y, b = blockIdx.z;
    int tile, split, nspl, c_begin, c_end;
    if (s < 8) {
        tile = 7 - (s >> 1);
        split = s & 1;
        nspl = 2;
        const int nch = 2 * tile + 2, half = nch >> 1;
        c_begin = split ? half : 0;
        c_end   = split ? nch  : half;
    } else {
        tile = 11 - s;
        split = 0; nspl = 1;
        c_begin = 0; c_end = 2 * tile + 2;
    }
    const int q0 = tile * 128;

    const int tid = threadIdx.x, warp = tid >> 5, lane = tid & 31;
    const int g = lane >> 2, t = lane & 3;

    extern __shared__ __align__(128) char asm_[];
    const uint32_t qb = s2u(asm_);
    const uint32_t kb0 = qb + 128 * 144;
    const uint32_t vb0 = kb0 + 2 * 64 * 144;

    const __half* Ub = U + (size_t)(b * SEQ) * 3072 + h * 64;

    {
        const int r = tid >> 1;
        const int sg = (tid & 1) * 64;
        const __half* gq = Ub + (size_t)(q0 + r) * 3072 + sg / 2;
        const uint32_t sq = qb + r * 144 + sg;
        cp16(sq, gq); cp16(sq + 16, gq + 8);
        cp16(sq + 32, gq + 16); cp16(sq + 48, gq + 24);
    }
    asm volatile("cp.async.commit_group;" ::: "memory");
    asm volatile("cp.async.wait_group 0;" ::: "memory");
    __syncthreads();

    unsigned qf[4][4];
    {
        const uint32_t qa = qb + (16 * warp + (lane & 15)) * 144 + ((lane >> 4) & 1) * 16;
        const __half2 sc = __floats2half2_rn(0.125f, 0.125f);
#pragma unroll
        for (int kk = 0; kk < 4; kk++) {
            ldsm4(qf[kk], qa + kk * 32);
#pragma unroll
            for (int e = 0; e < 4; e++) {
                __half2 v = *(__half2*)&qf[kk][e];
                v = __hmul2(v, sc);
                qf[kk][e] = *(unsigned*)&v;
            }
        }
    }

    float o[8][4];
#pragma unroll
    for (int d = 0; d < 8; d++)
#pragma unroll
        for (int e = 0; e < 4; e++) o[d][e] = 0.0f;
    float m0 = -1e30f, m1 = -1e30f, l0 = 0.0f, l1 = 0.0f;
    const int wbase = q0 + 16 * warp;
    const int row0 = wbase + g;

#define LOADKV(ci) do { \
    const int _c0 = (ci) * 64; \
    const int _bf = (ci) & 1; \
    const int tt = tid & 127; \
    const int r = tt >> 1, sgh = (tt & 1) * 32; \
    const __half* gp = Ub + (size_t)(_c0 + r) * 3072 + ((tid >= 128) ? 2048 : 1024) + sgh; \
    const uint32_t sp = ((tid >= 128) ? vb0 : kb0) + _bf * (64 * 144) + r * 144 + sgh * 2; \
    cp16(sp, gp); cp16(sp + 16, gp + 8); \
    cp16(sp + 32, gp + 16); cp16(sp + 48, gp + 24); \
} while (0)

    LOADKV(c_begin);
    asm volatile("cp.async.commit_group;" ::: "memory");

    for (int ci = c_begin; ci < c_end; ci++) {
        const int c0 = ci * 64;
        const bool pre = (ci + 1 < c_end);
        if (pre) {
            LOADKV(ci + 1);
            asm volatile("cp.async.commit_group;" ::: "memory");
            asm volatile("cp.async.wait_group 1;" ::: "memory");
        } else {
            asm volatile("cp.async.wait_group 0;" ::: "memory");
        }
        __syncthreads();

        const uint32_t kb = kb0 + (ci & 1) * (64 * 144);
        const uint32_t vb = vb0 + (ci & 1) * (64 * 144);

        float sc[8][4];
#pragma unroll
        for (int j = 0; j < 8; j++)
#pragma unroll
            for (int e = 0; e < 4; e++) sc[j][e] = 0.0f;
#pragma unroll
        for (int kk = 0; kk < 4; kk++) {
            unsigned bf[4][4];
#pragma unroll
            for (int nj = 0; nj < 4; nj++)
                ldsm4(bf[nj], kb + (nj * 16 + (lane & 7) + ((lane >> 4) & 1) * 8) * 144
                                + ((lane >> 3) & 1) * 16 + kk * 32);
#pragma unroll
            for (int nj = 0; nj < 4; nj++) {
                mma_f16(sc[2 * nj],     qf[kk], &bf[nj][0]);
                mma_f16(sc[2 * nj + 1], qf[kk], &bf[nj][2]);
            }
        }

        if (c0 + 63 > wbase) {
#pragma unroll
            for (int j = 0; j < 8; j++) {
                const int cb = c0 + 8 * j + 2 * t;
                if (cb     > row0)     sc[j][0] = -1e30f;
                if (cb + 1 > row0)     sc[j][1] = -1e30f;
                if (cb     > row0 + 8) sc[j][2] = -1e30f;
                if (cb + 1 > row0 + 8) sc[j][3] = -1e30f;
            }
        }

        float cm0 = -1e30f, cm1 = -1e30f;
#pragma unroll
        for (int j = 0; j < 8; j++) {
            cm0 = fmaxf(cm0, fmaxf(sc[j][0], sc[j][1]));
            cm1 = fmaxf(cm1, fmaxf(sc[j][2], sc[j][3]));
        }
        cm0 = fmaxf(cm0, __shfl_xor_sync(0xffffffff, cm0, 1));
        cm0 = fmaxf(cm0, __shfl_xor_sync(0xffffffff, cm0, 2));
        cm1 = fmaxf(cm1, __shfl_xor_sync(0xffffffff, cm1, 1));
        cm1 = fmaxf(cm1, __shfl_xor_sync(0xffffffff, cm1, 2));
        const float nm0 = fmaxf(m0, cm0), nm1 = fmaxf(m1, cm1);
        const float f0 = __expf(m0 - nm0), f1 = __expf(m1 - nm1);
        m0 = nm0; m1 = nm1;

        unsigned pf[4][4];
        float sum0 = 0.0f, sum1 = 0.0f;
#pragma unroll
        for (int nj = 0; nj < 4; nj++) {
            const float pa0 = __expf(sc[2 * nj][0] - nm0), pa1 = __expf(sc[2 * nj][1] - nm0);
            const float pa2 = __expf(sc[2 * nj][2] - nm1), pa3 = __expf(sc[2 * nj][3] - nm1);
            const float pb0 = __expf(sc[2 * nj + 1][0] - nm0), pb1 = __expf(sc[2 * nj + 1][1] - nm0);
            const float pb2 = __expf(sc[2 * nj + 1][2] - nm1), pb3 = __expf(sc[2 * nj + 1][3] - nm1);
            sum0 += pa0 + pa1 + pb0 + pb1;
            sum1 += pa2 + pa3 + pb2 + pb3;
            pf[nj][0] = packh2(pa0, pa1);
            pf[nj][1] = packh2(pa2, pa3);
            pf[nj][2] = packh2(pb0, pb1);
            pf[nj][3] = packh2(pb2, pb3);
        }
        sum0 += __shfl_xor_sync(0xffffffff, sum0, 1);
        sum0 += __shfl_xor_sync(0xffffffff, sum0, 2);
        sum1 += __shfl_xor_sync(0xffffffff, sum1, 1);
        sum1 += __shfl_xor_sync(0xffffffff, sum1, 2);
        l0 = l0 * f0 + sum0;
        l1 = l1 * f1 + sum1;

#pragma unroll
        for (int d = 0; d < 8; d++) {
            o[d][0] *= f0; o[d][1] *= f0; o[d][2] *= f1; o[d][3] *= f1;
        }

#pragma unroll
        for (int kk = 0; kk < 4; kk++) {
            unsigned vf[4][4];
#pragma unroll
            for (int dj = 0; dj < 4; dj++)
                ldsm4t(vf[dj], vb + (kk * 16 + (lane & 7) + ((lane >> 3) & 1) * 8) * 144
                                 + (dj * 16 + ((lane >> 4) & 1) * 8) * 2);
#pragma unroll
            for (int dj = 0; dj < 4; dj++) {
                mma_f16(o[2 * dj],     pf[kk], &vf[dj][0]);
                mma_f16(o[2 * dj + 1], pf[kk], &vf[dj][2]);
            }
        }
        __syncthreads();
    }
#undef LOADKV

    if (nspl == 1) {
        const float il0 = 1.0f / l0, il1 = 1.0f / l1;
        __half* Ob = O + (size_t)(b * SEQ + row0) * TDIM + h * 64;
#pragma unroll
        for (int dj = 0; dj < 8; dj++) {
            const int c = 8 * dj + 2 * t;
            *(__half2*)(Ob + c)            = __floats2half2_rn(o[dj][0] * il0, o[dj][1] * il0);
            *(__half2*)(Ob + 8 * TDIM + c) = __floats2half2_rn(o[dj][2] * il1, o[dj][3] * il1);
        }
    } else {
        const size_t base = (((size_t)split * BATCH + b) * NHEAD + h) * SEQ;
        float* Ob = Po + (base + row0) * 64;
#pragma unroll
        for (int dj = 0; dj < 8; dj++) {
            const int c = 8 * dj + 2 * t;
            float2 a; a.x = o[dj][0]; a.y = o[dj][1];
            float2 d; d.x = o[dj][2]; d.y = o[dj][3];
            *(float2*)(Ob + c)          = a;
            *(float2*)(Ob + 8 * 64 + c) = d;
        }
        if (t == 0) {
            float2 ml0; ml0.x = m0; ml0.y = l0;
            float2 ml1; ml1.x = m1; ml1.y = l1;
            *(float2*)(Pml + (base + row0) * 2)     = ml0;
            *(float2*)(Pml + (base + row0 + 8) * 2) = ml1;
        }
    }
}

// combine the 2 KV-splits for rows 512..1023 -> at16 (warp per row)
__global__ __launch_bounds__(256)
void attn_comb(const float* __restrict__ Po, const float* __restrict__ Pml,
               __half* __restrict__ O)
{
    const int warp = threadIdx.x >> 5, lane = threadIdx.x & 31;
    const int rid = blockIdx.x * 8 + warp;              // 0..16383
    const int b = rid >> 13;
    const int h = (rid >> 9) & 15;
    const int r = 512 + (rid & 511);
    const size_t base0 = ((size_t)(0 * BATCH + b) * NHEAD + h) * SEQ + r;
    const size_t base1 = ((size_t)(1 * BATCH + b) * NHEAD + h) * SEQ + r;
    const float2 ml0 = *(const float2*)(Pml + base0 * 2);
    const float2 ml1 = *(const float2*)(Pml + base1 * 2);
    const float m = fmaxf(ml0.x, ml1.x);
    const float f0 = __expf(ml0.x - m), f1 = __expf(ml1.x - m);
    const float inv = 1.0f / (ml0.y * f0 + ml1.y * f1);
    const float2 a = *(const float2*)(Po + base0 * 64 + 2 * lane);
    const float2 c = *(const float2*)(Po + base1 * 64 + 2 * lane);
    *(__half2*)(O + (size_t)(b * SEQ + r) * TDIM + h * 64 + 2 * lane) =
        __floats2half2_rn((a.x * f0 + c.x * f1) * inv, (a.y * f0 + c.y * f1) * inv);
}

// ---------------------------------------------------------------------------
__global__ void conv16(const float* __restrict__ s, __half* __restrict__ d, int n4)
{
    for (int i = blockIdx.x * blockDim.x + threadIdx.x; i < n4; i += gridDim.x * blockDim.x) {
        const float4 v = ((const float4*)s)[i];
        ((__half2*)d)[2 * i]     = __floats2half2_rn(v.x, v.y);
        ((__half2*)d)[2 * i + 1] = __floats2half2_rn(v.z, v.w);
    }
}

__global__ void prep_kernel(const int* __restrict__ ids, const float* __restrict__ emb,
                            float* __restrict__ x, float2* __restrict__ tab,
                            const float* __restrict__ Wu, __half* __restrict__ wu16)
{
    if (blockIdx.x < NROWS) {
        ((float4*)(x + (size_t)blockIdx.x * DMODEL))[threadIdx.x] =
            ((const float4*)(emb + (size_t)ids[blockIdx.x] * DMODEL))[threadIdx.x];
    } else if (blockIdx.x < NROWS + 128) {
        const int idx = (blockIdx.x - NROWS) * 256 + threadIdx.x;
        const int s = idx >> 5, i = idx & 31;
        const float inv = exp2f(-(float)(2 * i) * (1.0f / 64.0f) * 13.287712379549449f);
        float sn, cs;
        sincosf((float)s * inv, &sn, &cs);
        tab[idx] = make_float2(cs, sn);
    } else {
        const int n4 = NLAYER * 3 * TDIM * DMODEL / 4;
        for (int i = (blockIdx.x - NROWS - 128) * 256 + threadIdx.x; i < n4; i += 2048 * 256) {
            const float4 v = ((const float4*)Wu)[i];
            ((__half2*)wu16)[2 * i]     = __floats2half2_rn(v.x, v.y);
            ((__half2*)wu16)[2 * i + 1] = __floats2half2_rn(v.z, v.w);
        }
    }
}

extern "C" void kernel_launch(void* const* d_in, const int* in_sizes, int n_in,
                              void* d_out, int out_size)
{
    (void)in_sizes; (void)n_in; (void)out_size;

    const int*   ids = (const int*)  d_in[0];
    const float* emb = (const float*)d_in[1];
    const float* Wu  = (const float*)d_in[2];
    const float* Wo  = (const float*)d_in[3];
    const float* n1w = (const float*)d_in[4];
    const float* n1b = (const float*)d_in[5];
    const float* n2w = (const float*)d_in[6];
    const float* n2b = (const float*)d_in[7];
    const float* f1w = (const float*)d_in[8];
    const float* f1b = (const float*)d_in[9];
    const float* f2w = (const float*)d_in[10];
    const float* f2b = (const float*)d_in[11];
    const float* fnw = (const float*)d_in[12];
    const float* fnb = (const float*)d_in[13];
    float* out = (float*)d_out;

    float *x, *part, *attp, *attml; float2* tab;
    __half *u16, *xn16, *at16, *h16, *w16;
    cudaGetSymbolAddress((void**)&x,     g_x);
    cudaGetSymbolAddress((void**)&part,  g_part);
    cudaGetSymbolAddress((void**)&attp,  g_attp);
    cudaGetSymbolAddress((void**)&attml, g_attml);
    cudaGetSymbolAddress((void**)&tab,   g_rope);
    cudaGetSymbolAddress((void**)&u16,   g_u16);
    cudaGetSymbolAddress((void**)&xn16,  g_xn16);
    cudaGetSymbolAddress((void**)&at16,  g_at16);
    cudaGetSymbolAddress((void**)&h16,   g_h16);
    cudaGetSymbolAddress((void**)&w16,   g_w16);

    cudaFuncSetAttribute((gemm_f16<0,1>), cudaFuncAttributeMaxDynamicSharedMemorySize, GEMM_SMEM);
    cudaFuncSetAttribute((gemm_f16<1,0>), cudaFuncAttributeMaxDynamicSharedMemorySize, GEMM_SMEM);
    cudaFuncSetAttribute((gemm_f16<3,0>), cudaFuncAttributeMaxDynamicSharedMemorySize, GEMM_SMEM);
    cudaFuncSetAttribute(gemm_sk,         cudaFuncAttributeMaxDynamicSharedMemorySize, GEMM_SMEM);
    cudaFuncSetAttribute(attn_mma,        cudaFuncAttributeMaxDynamicSharedMemorySize, ATTN_SMEM);

    static cudaStream_t s2 = nullptr;
    static cudaEvent_t evF = nullptr, evD = nullptr;
    if (!s2) {
        cudaStreamCreateWithFlags(&s2, cudaStreamNonBlocking);
        cudaEventCreateWithFlags(&evF, cudaEventDisableTiming);
        cudaEventCreateWithFlags(&evD, cudaEventDisableTiming);
    }

    prep_kernel<<<NROWS + 128 + 2048, 256>>>(ids, emb, x, tab, Wu, w16 + WU16);
    layernorm_kernel<<<NROWS / 8, 256>>>(x, n1w, n1b, xn16);
    conv16<<<2048, 256>>>(emb, w16 + EMB16, VOCAB * DMODEL / 4);
    gemm_f16<3,0><<<dim3(3 * TDIM / 128, NROWS / 128), 256, GEMM_SMEM>>>(
        xn16, w16 + WU16, nullptr, nullptr, u16, tab, 3 * TDIM, DMODEL);

    cudaEventRecord(evF, 0);
    cudaStreamWaitEvent(s2, evF, 0);
    conv16<<<2048, 256, 0, s2>>>(Wo,  w16 + WO16,  NLAYER * DMODEL * TDIM / 4);
    conv16<<<2048, 256, 0, s2>>>(f1w, w16 + F116,  NLAYER * FFDIM * DMODEL / 4);
    conv16<<<2048, 256, 0, s2>>>(f2w, w16 + F216,  NLAYER * DMODEL * FFDIM / 4);
    cudaEventRecord(evD, s2);

    attn_mma<<<dim3(12, NHEAD, BATCH), 256, ATTN_SMEM>>>(u16, at16, attp, attml);
    attn_comb<<<2048, 256>>>(attp, attml, at16);
    cudaStreamWaitEvent(0, evD, 0);

    for (int l = 0; l < NLAYER; l++) {
        const __half* Wu_l = w16 + WU16 + (size_t)(l + 1) * 3 * TDIM * DMODEL;
        const __half* Wo_l = w16 + WO16 + (size_t)l * DMODEL * TDIM;
        const __half* f1_l = w16 + F116 + (size_t)l * FFDIM * DMODEL;
        const __half* f2_l = w16 + F216 + (size_t)l * DMODEL * FFDIM;

        gemm_sk<<<dim3(DMODEL / 128, NROWS / 128, 2), 256, GEMM_SMEM>>>(
            at16, Wo_l, part, DMODEL, TDIM);
        reduce_ln<<<NROWS / 8, 256>>>(part, nullptr, x,
                                      n2w + l * DMODEL, n2b + l * DMODEL, xn16);

        gemm_f16<1,0><<<dim3(FFDIM / 128, NROWS / 128), 256, GEMM_SMEM>>>(
            xn16, f1_l, f1b + (size_t)l * FFDIM, nullptr, h16, nullptr, FFDIM, DMODEL);

        gemm_sk<<<dim3(DMODEL / 128, NROWS / 128, 2), 256, GEMM_SMEM>>>(
            h16, f2_l, part, DMODEL, FFDIM);
        if (l + 1 < NLAYER) {
            reduce_ln<<<NROWS / 8, 256>>>(part, f2b + (size_t)l * DMODEL, x,
                                          n1w + (l + 1) * DMODEL, n1b + (l + 1) * DMODEL, xn16);
            gemm_f16<3,0><<<dim3(3 * TDIM / 128, NROWS / 128), 256, GEMM_SMEM>>>(
                xn16, Wu_l, nullptr, nullptr, u16, tab, 3 * TDIM, DMODEL);
            attn_mma<<<dim3(12, NHEAD, BATCH), 256, ATTN_SMEM>>>(u16, at16, attp, attml);
            attn_comb<<<2048, 256>>>(attp, attml, at16);
        } else {
            reduce_ln<<<NROWS / 8, 256>>>(part, f2b + (size_t)l * DMODEL, x,
                                          fnw, fnb, xn16);
        }
    }

    gemm_f16<0,1><<<dim3(NROWS / 128, VOCAB / 128), 256, GEMM_SMEM>>>(
        xn16, w16 + EMB16, nullptr, out, nullptr, nullptr, VOCAB, DMODEL);
}

// round 17
// speedup vs baseline: 1.0871x; 1.0021x over previous
#include <cuda_runtime.h>
#include <cuda_fp16.h>
#include <math.h>
#include <stdint.h>

#define BATCH   2
#define SEQ     1024
#define NROWS   (BATCH * SEQ)
#define DMODEL  1024
#define NHEAD   16
#define HDIM    64
#define TDIM    1024
#define FFDIM   4096
#define NLAYER  8
#define VOCAB   32000

#define WU16  0
#define WO16  25165824u
#define F116  33554432u
#define F216  67108864u
#define EMB16 100663296u
#define W16_TOTAL 133431296u

__device__ float  g_x [NROWS * DMODEL];
__device__ float  g_part[2 * NROWS * DMODEL];
__device__ float  g_attp[2 * BATCH * NHEAD * SEQ * 64];
__device__ float  g_attml[2 * BATCH * NHEAD * SEQ * 2];
__device__ float2 g_rope[SEQ * 32];
__device__ __half g_u16 [NROWS * 3 * TDIM];
__device__ __half g_xn16[NROWS * DMODEL];
__device__ __half g_at16[NROWS * TDIM];
__device__ __half g_h16 [NROWS * FFDIM];
__device__ __half g_w16 [W16_TOTAL];

__device__ __forceinline__ float gelu_exact(float v) {
    return 0.5f * v * (1.0f + erff(v * 0.70710678118654752440f));
}
__device__ __forceinline__ uint32_t s2u(const void* p) {
    uint32_t a;
    asm("{ .reg .u64 t; cvta.to.shared.u64 t, %1; cvt.u32.u64 %0, t; }" : "=r"(a) : "l"(p));
    return a;
}
__device__ __forceinline__ void cp16(uint32_t s, const void* g) {
    asm volatile("cp.async.cg.shared.global [%0], [%1], 16;" :: "r"(s), "l"(g));
}
__device__ __forceinline__ void ldsm4(unsigned* r, uint32_t a) {
    asm volatile("ldmatrix.sync.aligned.m8n8.x4.shared.b16 {%0,%1,%2,%3}, [%4];"
        : "=r"(r[0]), "=r"(r[1]), "=r"(r[2]), "=r"(r[3]) : "r"(a));
}
__device__ __forceinline__ void ldsm4t(unsigned* r, uint32_t a) {
    asm volatile("ldmatrix.sync.aligned.m8n8.x4.trans.shared.b16 {%0,%1,%2,%3}, [%4];"
        : "=r"(r[0]), "=r"(r[1]), "=r"(r[2]), "=r"(r[3]) : "r"(a));
}
__device__ __forceinline__ void mma_f16(float* c, const unsigned* a, const unsigned* b) {
    asm volatile(
        "mma.sync.aligned.m16n8k16.row.col.f32.f16.f16.f32 "
        "{%0,%1,%2,%3},{%4,%5,%6,%7},{%8,%9},{%0,%1,%2,%3};"
        : "+f"(c[0]), "+f"(c[1]), "+f"(c[2]), "+f"(c[3])
        : "r"(a[0]), "r"(a[1]), "r"(a[2]), "r"(a[3]), "r"(b[0]), "r"(b[1]));
}
__device__ __forceinline__ void rot(float& a, float& b, float2 cs) {
    const float t0 = a * cs.x - b * cs.y;
    b = b * cs.x + a * cs.y;
    a = t0;
}
__device__ __forceinline__ unsigned packh2(float a, float b) {
    __half2 h = __floats2half2_rn(a, b);
    return *(unsigned*)&h;
}

// ---------------------------------------------------------------------------
// fp16 GEMM 128x128 (proven)
// MODE 0: fp32 C   MODE 1: gelu(acc+bias)->fp16   MODE 3: rope->fp16 (QKV)
// SWAP=1: blockIdx.x indexes M (logits)
// ---------------------------------------------------------------------------
template<int MODE, int SWAP>
__global__ __launch_bounds__(256)
void gemm_f16(const __half* __restrict__ A, const __half* __restrict__ B,
              const float* __restrict__ bias, float* __restrict__ C,
              __half* __restrict__ C16, const float2* __restrict__ tab,
              int N, int K)
{
    extern __shared__ __align__(128) char smem[];
    const uint32_t sb = s2u(smem);
    const int tid = threadIdx.x, warp = tid >> 5, lane = tid & 31;
    const int bm = (SWAP ? blockIdx.x : blockIdx.y) * 128;
    const int bn = (SWAP ? blockIdx.y : blockIdx.x) * 128;
    const int moff = (warp & 3) * 32, noff = (warp >> 2) * 64;
    const int g = lane >> 2, t = lane & 3;
    const int nk = K >> 5;
    const int lrow = tid >> 2, lc = tid & 3;

    float acc[2][8][4];
#pragma unroll
    for (int mi = 0; mi < 2; mi++)
#pragma unroll
        for (int ni = 0; ni < 8; ni++)
#pragma unroll
            for (int e = 0; e < 4; e++) acc[mi][ni][e] = 0.0f;

#define LOADST(st, ks) do { \
    const uint32_t so = sb + (uint32_t)(st) * 20480u; \
    const __half* gA = A + (size_t)(bm + lrow) * K + (ks) * 32 + lc * 8; \
    const __half* gB = B + (size_t)(bn + lrow) * K + (ks) * 32 + lc * 8; \
    const uint32_t sA = so + lrow * 80 + lc * 16; \
    const uint32_t sB = sA + 10240u; \
    cp16(sA, gA); cp16(sB, gB); \
    cp16(sA + 64 * 80, gA + (size_t)64 * K); \
    cp16(sB + 64 * 80, gB + (size_t)64 * K); \
} while (0)

    LOADST(0, 0);
    asm volatile("cp.async.commit_group;" ::: "memory");
    if (nk > 1) LOADST(1, 1);
    asm volatile("cp.async.commit_group;" ::: "memory");

    const uint32_t aoff = (uint32_t)((moff + (lane & 15)) * 80 + ((lane >> 4) & 1) * 16);
    const uint32_t boff = 10240u +
        (uint32_t)((noff + (lane & 7) + ((lane >> 4) & 1) * 8) * 80 + ((lane >> 3) & 1) * 16);

    for (int ks = 0; ks < nk; ks++) {
        asm volatile("cp.async.wait_group %0;" :: "n"(1) : "memory");
        __syncthreads();
        if (ks + 2 < nk) { LOADST((ks + 2) % 3, ks + 2); }
        asm volatile("cp.async.commit_group;" ::: "memory");

        const uint32_t so = sb + (uint32_t)(ks % 3) * 20480u;
#pragma unroll
        for (int kk = 0; kk < 2; kk++) {
            unsigned a0[4], a1[4], b[4][4];
            ldsm4(a0, so + aoff + kk * 32);
            ldsm4(a1, so + aoff + 16 * 80 + kk * 32);
#pragma unroll
            for (int nj = 0; nj < 4; nj++)
                ldsm4(b[nj], so + boff + nj * 16 * 80 + kk * 32);
#pragma unroll
            for (int nj = 0; nj < 4; nj++) {
                mma_f16(acc[0][2 * nj],     a0, &b[nj][0]);
                mma_f16(acc[0][2 * nj + 1], a0, &b[nj][2]);
                mma_f16(acc[1][2 * nj],     a1, &b[nj][0]);
                mma_f16(acc[1][2 * nj + 1], a1, &b[nj][2]);
            }
        }
    }
#undef LOADST

    if (MODE == 3) {
        const int region = (bn + noff) >> 10;
        if (region < 2) {
#pragma unroll
            for (int mi = 0; mi < 2; mi++) {
                const int r0 = bm + moff + 16 * mi + g;
                const int s0 = r0 & (SEQ - 1);
#pragma unroll
                for (int ni = 0; ni < 4; ni++) {
                    const int i0 = 8 * ni + 2 * t;
                    const float2 c00 = tab[s0 * 32 + i0];
                    const float2 c01 = tab[s0 * 32 + i0 + 1];
                    const float2 c10 = tab[(s0 + 8) * 32 + i0];
                    const float2 c11 = tab[(s0 + 8) * 32 + i0 + 1];
                    rot(acc[mi][ni][0], acc[mi][ni + 4][0], c00);
                    rot(acc[mi][ni][1], acc[mi][ni + 4][1], c01);
                    rot(acc[mi][ni][2], acc[mi][ni + 4][2], c10);
                    rot(acc[mi][ni][3], acc[mi][ni + 4][3], c11);
                }
            }
        }
    }

#pragma unroll
    for (int mi = 0; mi < 2; mi++) {
        const int r0 = bm + moff + 16 * mi + g;
#pragma unroll
        for (int ni = 0; ni < 8; ni++) {
            const int c = bn + noff + 8 * ni + 2 * t;
            float v00 = acc[mi][ni][0], v01 = acc[mi][ni][1];
            float v10 = acc[mi][ni][2], v11 = acc[mi][ni][3];
            if (MODE == 1 || MODE == 3) {
                if (MODE == 1) {
                    const float b0 = bias[c], b1 = bias[c + 1];
                    v00 = gelu_exact(v00 + b0); v01 = gelu_exact(v01 + b1);
                    v10 = gelu_exact(v10 + b0); v11 = gelu_exact(v11 + b1);
                }
                *(__half2*)(C16 + (size_t)r0 * N + c)       = __floats2half2_rn(v00, v01);
                *(__half2*)(C16 + (size_t)(r0 + 8) * N + c) = __floats2half2_rn(v10, v11);
            } else {
                float2 o0; o0.x = v00; o0.y = v01;
                float2 o1; o1.x = v10; o1.y = v11;
                *(float2*)(C + (size_t)r0 * N + c) = o0;
                *(float2*)(C + (size_t)(r0 + 8) * N + c) = o1;
            }
        }
    }
}
#define GEMM_SMEM (3 * 20480)

// ---------------------------------------------------------------------------
// Split-K GEMM (unchanged)
// ---------------------------------------------------------------------------
__global__ __launch_bounds__(256)
void gemm_sk(const __half* __restrict__ A, const __half* __restrict__ B,
             float* __restrict__ P, int N, int Kfull)
{
    extern __shared__ __align__(128) char smem[];
    const uint32_t sb = s2u(smem);
    const int tid = threadIdx.x, warp = tid >> 5, lane = tid & 31;
    const int bm = blockIdx.y * 128, bn = blockIdx.x * 128;
    const int kh = blockIdx.z;
    const int Kh = Kfull >> 1;
    const int koff = kh * Kh;
    const int moff = (warp & 3) * 32, noff = (warp >> 2) * 64;
    const int g = lane >> 2, t = lane & 3;
    const int nk = Kh >> 5;
    const int lrow = tid >> 2, lc = tid & 3;

    float acc[2][8][4];
#pragma unroll
    for (int mi = 0; mi < 2; mi++)
#pragma unroll
        for (int ni = 0; ni < 8; ni++)
#pragma unroll
            for (int e = 0; e < 4; e++) acc[mi][ni][e] = 0.0f;

#define LOADSK(st, ks) do { \
    const uint32_t so = sb + (uint32_t)(st) * 20480u; \
    const __half* gA = A + (size_t)(bm + lrow) * Kfull + koff + (ks) * 32 + lc * 8; \
    const __half* gB = B + (size_t)(bn + lrow) * Kfull + koff + (ks) * 32 + lc * 8; \
    const uint32_t sA = so + lrow * 80 + lc * 16; \
    const uint32_t sB = sA + 10240u; \
    cp16(sA, gA); cp16(sB, gB); \
    cp16(sA + 64 * 80, gA + (size_t)64 * Kfull); \
    cp16(sB + 64 * 80, gB + (size_t)64 * Kfull); \
} while (0)

    LOADSK(0, 0);
    asm volatile("cp.async.commit_group;" ::: "memory");
    if (nk > 1) LOADSK(1, 1);
    asm volatile("cp.async.commit_group;" ::: "memory");

    const uint32_t aoff = (uint32_t)((moff + (lane & 15)) * 80 + ((lane >> 4) & 1) * 16);
    const uint32_t boff = 10240u +
        (uint32_t)((noff + (lane & 7) + ((lane >> 4) & 1) * 8) * 80 + ((lane >> 3) & 1) * 16);

    for (int ks = 0; ks < nk; ks++) {
        asm volatile("cp.async.wait_group %0;" :: "n"(1) : "memory");
        __syncthreads();
        if (ks + 2 < nk) { LOADSK((ks + 2) % 3, ks + 2); }
        asm volatile("cp.async.commit_group;" ::: "memory");

        const uint32_t so = sb + (uint32_t)(ks % 3) * 20480u;
#pragma unroll
        for (int kk = 0; kk < 2; kk++) {
            unsigned a0[4], a1[4], b[4][4];
            ldsm4(a0, so + aoff + kk * 32);
            ldsm4(a1, so + aoff + 16 * 80 + kk * 32);
#pragma unroll
            for (int nj = 0; nj < 4; nj++)
                ldsm4(b[nj], so + boff + nj * 16 * 80 + kk * 32);
#pragma unroll
            for (int nj = 0; nj < 4; nj++) {
                mma_f16(acc[0][2 * nj],     a0, &b[nj][0]);
                mma_f16(acc[0][2 * nj + 1], a0, &b[nj][2]);
                mma_f16(acc[1][2 * nj],     a1, &b[nj][0]);
                mma_f16(acc[1][2 * nj + 1], a1, &b[nj][2]);
            }
        }
    }
#undef LOADSK

    float* Pb = P + (size_t)kh * NROWS * N;
#pragma unroll
    for (int mi = 0; mi < 2; mi++) {
        const int r0 = bm + moff + 16 * mi + g;
#pragma unroll
        for (int ni = 0; ni < 8; ni++) {
            const int c = bn + noff + 8 * ni + 2 * t;
            float2 o0; o0.x = acc[mi][ni][0]; o0.y = acc[mi][ni][1];
            float2 o1; o1.x = acc[mi][ni][2]; o1.y = acc[mi][ni][3];
            *(float2*)(Pb + (size_t)r0 * N + c) = o0;
            *(float2*)(Pb + (size_t)(r0 + 8) * N + c) = o1;
        }
    }
}

// ---------------------------------------------------------------------------
// fused: x += p0 + p1 (+bias); LayerNorm -> fp16 (warp-per-row)
// ---------------------------------------------------------------------------
__global__ __launch_bounds__(256)
void reduce_ln(const float* __restrict__ P, const float* __restrict__ bias,
               float* __restrict__ x, const float* __restrict__ w,
               const float* __restrict__ b, __half* __restrict__ y16)
{
    const int warp = threadIdx.x >> 5, lane = threadIdx.x & 31;
    const int row = blockIdx.x * 8 + warp;
    const size_t ro = (size_t)row * (DMODEL / 4);
    const float4* p0 = (const float4*)P + ro;
    const float4* p1 = (const float4*)P + ro + (size_t)NROWS * (DMODEL / 4);
    float4* xr = (float4*)x + ro;

    float4 v[8];
    float s = 0.0f;
#pragma unroll
    for (int j = 0; j < 8; j++) {
        const int idx = lane + 32 * j;
        float4 a = p0[idx];
        const float4 c = p1[idx];
        float4 xv = xr[idx];
        a.x += c.x; a.y += c.y; a.z += c.z; a.w += c.w;
        if (bias) {
            const float4 bb = ((const float4*)bias)[idx];
            a.x += bb.x; a.y += bb.y; a.z += bb.z; a.w += bb.w;
        }
        xv.x += a.x; xv.y += a.y; xv.z += a.z; xv.w += a.w;
        xr[idx] = xv;
        v[j] = xv;
        s += xv.x + xv.y + xv.z + xv.w;
    }
#pragma unroll
    for (int o = 16; o > 0; o >>= 1) s += __shfl_xor_sync(0xffffffff, s, o);
    const float mu = s * (1.0f / DMODEL);

    float q = 0.0f;
#pragma unroll
    for (int j = 0; j < 8; j++) {
        const float a = v[j].x - mu, b2 = v[j].y - mu, c = v[j].z - mu, d = v[j].w - mu;
        q += a * a + b2 * b2 + c * c + d * d;
    }
#pragma unroll
    for (int o = 16; o > 0; o >>= 1) q += __shfl_xor_sync(0xffffffff, q, o);
    const float rs = rsqrtf(q * (1.0f / DMODEL) + 1e-5f);

    uint2* yr = (uint2*)(y16 + (size_t)row * DMODEL);
#pragma unroll
    for (int j = 0; j < 8; j++) {
        const int idx = lane + 32 * j;
        const float4 wv = ((const float4*)w)[idx];
        const float4 bv = ((const float4*)b)[idx];
        const __half2 h0 = __floats2half2_rn((v[j].x - mu) * rs * wv.x + bv.x,
                                             (v[j].y - mu) * rs * wv.y + bv.y);
        const __half2 h1 = __floats2half2_rn((v[j].z - mu) * rs * wv.z + bv.z,
                                             (v[j].w - mu) * rs * wv.w + bv.w);
        uint2 o; o.x = *(const unsigned*)&h0; o.y = *(const unsigned*)&h1;
        yr[idx] = o;
    }
}

__global__ __launch_bounds__(256)
void layernorm_kernel(const float* __restrict__ x, const float* __restrict__ w,
                      const float* __restrict__ b, __half* __restrict__ y16)
{
    const int warp = threadIdx.x >> 5, lane = threadIdx.x & 31;
    const int row = blockIdx.x * 8 + warp;
    const float4* xr = (const float4*)(x + (size_t)row * DMODEL);

    float4 v[8];
    float s = 0.0f;
#pragma unroll
    for (int j = 0; j < 8; j++) {
        v[j] = xr[lane + 32 * j];
        s += v[j].x + v[j].y + v[j].z + v[j].w;
    }
#pragma unroll
    for (int o = 16; o > 0; o >>= 1) s += __shfl_xor_sync(0xffffffff, s, o);
    const float mu = s * (1.0f / DMODEL);

    float q = 0.0f;
#pragma unroll
    for (int j = 0; j < 8; j++) {
        const float a = v[j].x - mu, b2 = v[j].y - mu, c = v[j].z - mu, d = v[j].w - mu;
        q += a * a + b2 * b2 + c * c + d * d;
    }
#pragma unroll
    for (int o = 16; o > 0; o >>= 1) q += __shfl_xor_sync(0xffffffff, q, o);
    const float rs = rsqrtf(q * (1.0f / DMODEL) + 1e-5f);

    uint2* yr = (uint2*)(y16 + (size_t)row * DMODEL);
#pragma unroll
    for (int j = 0; j < 8; j++) {
        const int idx = lane + 32 * j;
        const float4 wv = ((const float4*)w)[idx];
        const float4 bv = ((const float4*)b)[idx];
        const __half2 h0 = __floats2half2_rn((v[j].x - mu) * rs * wv.x + bv.x,
                                             (v[j].y - mu) * rs * wv.y + bv.y);
        const __half2 h1 = __floats2half2_rn((v[j].z - mu) * rs * wv.z + bv.z,
                                             (v[j].w - mu) * rs * wv.w + bv.w);
        uint2 o; o.x = *(const unsigned*)&h0; o.y = *(const unsigned*)&h1;
        yr[idx] = o;
    }
}

// ---------------------------------------------------------------------------
// MMA flash attention v4 (split-KV, unchanged from R16)
// ---------------------------------------------------------------------------
#define ATTN_SMEM (128 * 144 + 4 * 64 * 144)
__global__ __launch_bounds__(256, 2)
void attn_mma(const __half* __restrict__ U, __half* __restrict__ O,
              float* __restrict__ Po, float* __restrict__ Pml)
{
    const int s = blockIdx.x, h = blockIdx.y, b = blockIdx.z;
    int tile, split, nspl, c_begin, c_end;
    if (s < 8) {
        tile = 7 - (s >> 1);
        split = s & 1;
        nspl = 2;
        const int nch = 2 * tile + 2, half = nch >> 1;
        c_begin = split ? half : 0;
        c_end   = split ? nch  : half;
    } else {
        tile = 11 - s;
        split = 0; nspl = 1;
        c_begin = 0; c_end = 2 * tile + 2;
    }
    const int q0 = tile * 128;

    const int tid = threadIdx.x, warp = tid >> 5, lane = tid & 31;
    const int g = lane >> 2, t = lane & 3;

    extern __shared__ __align__(128) char asm_[];
    const uint32_t qb = s2u(asm_);
    const uint32_t kb0 = qb + 128 * 144;
    const uint32_t vb0 = kb0 + 2 * 64 * 144;

    const __half* Ub = U + (size_t)(b * SEQ) * 3072 + h * 64;

    {
        const int r = tid >> 1;
        const int sg = (tid & 1) * 64;
        const __half* gq = Ub + (size_t)(q0 + r) * 3072 + sg / 2;
        const uint32_t sq = qb + r * 144 + sg;
        cp16(sq, gq); cp16(sq + 16, gq + 8);
        cp16(sq + 32, gq + 16); cp16(sq + 48, gq + 24);
    }
    asm volatile("cp.async.commit_group;" ::: "memory");
    asm volatile("cp.async.wait_group 0;" ::: "memory");
    __syncthreads();

    unsigned qf[4][4];
    {
        const uint32_t qa = qb + (16 * warp + (lane & 15)) * 144 + ((lane >> 4) & 1) * 16;
        const __half2 sc = __floats2half2_rn(0.125f, 0.125f);
#pragma unroll
        for (int kk = 0; kk < 4; kk++) {
            ldsm4(qf[kk], qa + kk * 32);
#pragma unroll
            for (int e = 0; e < 4; e++) {
                __half2 v = *(__half2*)&qf[kk][e];
                v = __hmul2(v, sc);
                qf[kk][e] = *(unsigned*)&v;
            }
        }
    }

    float o[8][4];
#pragma unroll
    for (int d = 0; d < 8; d++)
#pragma unroll
        for (int e = 0; e < 4; e++) o[d][e] = 0.0f;
    float m0 = -1e30f, m1 = -1e30f, l0 = 0.0f, l1 = 0.0f;
    const int wbase = q0 + 16 * warp;
    const int row0 = wbase + g;

#define LOADKV(ci) do { \
    const int _c0 = (ci) * 64; \
    const int _bf = (ci) & 1; \
    const int tt = tid & 127; \
    const int r = tt >> 1, sgh = (tt & 1) * 32; \
    const __half* gp = Ub + (size_t)(_c0 + r) * 3072 + ((tid >= 128) ? 2048 : 1024) + sgh; \
    const uint32_t sp = ((tid >= 128) ? vb0 : kb0) + _bf * (64 * 144) + r * 144 + sgh * 2; \
    cp16(sp, gp); cp16(sp + 16, gp + 8); \
    cp16(sp + 32, gp + 16); cp16(sp + 48, gp + 24); \
} while (0)

    LOADKV(c_begin);
    asm volatile("cp.async.commit_group;" ::: "memory");

    for (int ci = c_begin; ci < c_end; ci++) {
        const int c0 = ci * 64;
        const bool pre = (ci + 1 < c_end);
        if (pre) {
            LOADKV(ci + 1);
            asm volatile("cp.async.commit_group;" ::: "memory");
            asm volatile("cp.async.wait_group 1;" ::: "memory");
        } else {
            asm volatile("cp.async.wait_group 0;" ::: "memory");
        }
        __syncthreads();

        const uint32_t kb = kb0 + (ci & 1) * (64 * 144);
        const uint32_t vb = vb0 + (ci & 1) * (64 * 144);

        float sc[8][4];
#pragma unroll
        for (int j = 0; j < 8; j++)
#pragma unroll
            for (int e = 0; e < 4; e++) sc[j][e] = 0.0f;
#pragma unroll
        for (int kk = 0; kk < 4; kk++) {
            unsigned bf[4][4];
#pragma unroll
            for (int nj = 0; nj < 4; nj++)
                ldsm4(bf[nj], kb + (nj * 16 + (lane & 7) + ((lane >> 4) & 1) * 8) * 144
                                + ((lane >> 3) & 1) * 16 + kk * 32);
#pragma unroll
            for (int nj = 0; nj < 4; nj++) {
                mma_f16(sc[2 * nj],     qf[kk], &bf[nj][0]);
                mma_f16(sc[2 * nj + 1], qf[kk], &bf[nj][2]);
            }
        }

        if (c0 + 63 > wbase) {
#pragma unroll
            for (int j = 0; j < 8; j++) {
                const int cb = c0 + 8 * j + 2 * t;
                if (cb     > row0)     sc[j][0] = -1e30f;
                if (cb + 1 > row0)     sc[j][1] = -1e30f;
                if (cb     > row0 + 8) sc[j][2] = -1e30f;
                if (cb + 1 > row0 + 8) sc[j][3] = -1e30f;
            }
        }

        float cm0 = -1e30f, cm1 = -1e30f;
#pragma unroll
        for (int j = 0; j < 8; j++) {
            cm0 = fmaxf(cm0, fmaxf(sc[j][0], sc[j][1]));
            cm1 = fmaxf(cm1, fmaxf(sc[j][2], sc[j][3]));
        }
        cm0 = fmaxf(cm0, __shfl_xor_sync(0xffffffff, cm0, 1));
        cm0 = fmaxf(cm0, __shfl_xor_sync(0xffffffff, cm0, 2));
        cm1 = fmaxf(cm1, __shfl_xor_sync(0xffffffff, cm1, 1));
        cm1 = fmaxf(cm1, __shfl_xor_sync(0xffffffff, cm1, 2));
        const float nm0 = fmaxf(m0, cm0), nm1 = fmaxf(m1, cm1);
        const float f0 = __expf(m0 - nm0), f1 = __expf(m1 - nm1);
        m0 = nm0; m1 = nm1;

        unsigned pf[4][4];
        float sum0 = 0.0f, sum1 = 0.0f;
#pragma unroll
        for (int nj = 0; nj < 4; nj++) {
            const float pa0 = __expf(sc[2 * nj][0] - nm0), pa1 = __expf(sc[2 * nj][1] - nm0);
            const float pa2 = __expf(sc[2 * nj][2] - nm1), pa3 = __expf(sc[2 * nj][3] - nm1);
            const float pb0 = __expf(sc[2 * nj + 1][0] - nm0), pb1 = __expf(sc[2 * nj + 1][1] - nm0);
            const float pb2 = __expf(sc[2 * nj + 1][2] - nm1), pb3 = __expf(sc[2 * nj + 1][3] - nm1);
            sum0 += pa0 + pa1 + pb0 + pb1;
            sum1 += pa2 + pa3 + pb2 + pb3;
            pf[nj][0] = packh2(pa0, pa1);
            pf[nj][1] = packh2(pa2, pa3);
            pf[nj][2] = packh2(pb0, pb1);
            pf[nj][3] = packh2(pb2, pb3);
        }
        sum0 += __shfl_xor_sync(0xffffffff, sum0, 1);
        sum0 += __shfl_xor_sync(0xffffffff, sum0, 2);
        sum1 += __shfl_xor_sync(0xffffffff, sum1, 1);
        sum1 += __shfl_xor_sync(0xffffffff, sum1, 2);
        l0 = l0 * f0 + sum0;
        l1 = l1 * f1 + sum1;

#pragma unroll
        for (int d = 0; d < 8; d++) {
            o[d][0] *= f0; o[d][1] *= f0; o[d][2] *= f1; o[d][3] *= f1;
        }

#pragma unroll
        for (int kk = 0; kk < 4; kk++) {
            unsigned vf[4][4];
#pragma unroll
            for (int dj = 0; dj < 4; dj++)
                ldsm4t(vf[dj], vb + (kk * 16 + (lane & 7) + ((lane >> 3) & 1) * 8) * 144
                                 + (dj * 16 + ((lane >> 4) & 1) * 8) * 2);
#pragma unroll
            for (int dj = 0; dj < 4; dj++) {
                mma_f16(o[2 * dj],     pf[kk], &vf[dj][0]);
                mma_f16(o[2 * dj + 1], pf[kk], &vf[dj][2]);
            }
        }
        __syncthreads();
    }
#undef LOADKV

    if (nspl == 1) {
        const float il0 = 1.0f / l0, il1 = 1.0f / l1;
        __half* Ob = O + (size_t)(b * SEQ + row0) * TDIM + h * 64;
#pragma unroll
        for (int dj = 0; dj < 8; dj++) {
            const int c = 8 * dj + 2 * t;
            *(__half2*)(Ob + c)            = __floats2half2_rn(o[dj][0] * il0, o[dj][1] * il0);
            *(__half2*)(Ob + 8 * TDIM + c) = __floats2half2_rn(o[dj][2] * il1, o[dj][3] * il1);
        }
    } else {
        const size_t base = (((size_t)split * BATCH + b) * NHEAD + h) * SEQ;
        float* Ob = Po + (base + row0) * 64;
#pragma unroll
        for (int dj = 0; dj < 8; dj++) {
            const int c = 8 * dj + 2 * t;
            float2 a; a.x = o[dj][0]; a.y = o[dj][1];
            float2 d; d.x = o[dj][2]; d.y = o[dj][3];
            *(float2*)(Ob + c)          = a;
            *(float2*)(Ob + 8 * 64 + c) = d;
        }
        if (t == 0) {
            float2 ml0; ml0.x = m0; ml0.y = l0;
            float2 ml1; ml1.x = m1; ml1.y = l1;
            *(float2*)(Pml + (base + row0) * 2)     = ml0;
            *(float2*)(Pml + (base + row0 + 8) * 2) = ml1;
        }
    }
}

__global__ __launch_bounds__(256)
void attn_comb(const float* __restrict__ Po, const float* __restrict__ Pml,
               __half* __restrict__ O)
{
    const int warp = threadIdx.x >> 5, lane = threadIdx.x & 31;
    const int rid = blockIdx.x * 8 + warp;
    const int b = rid >> 13;
    const int h = (rid >> 9) & 15;
    const int r = 512 + (rid & 511);
    const size_t base0 = ((size_t)(0 * BATCH + b) * NHEAD + h) * SEQ + r;
    const size_t base1 = ((size_t)(1 * BATCH + b) * NHEAD + h) * SEQ + r;
    const float2 ml0 = *(const float2*)(Pml + base0 * 2);
    const float2 ml1 = *(const float2*)(Pml + base1 * 2);
    const float m = fmaxf(ml0.x, ml1.x);
    const float f0 = __expf(ml0.x - m), f1 = __expf(ml1.x - m);
    const float inv = 1.0f / (ml0.y * f0 + ml1.y * f1);
    const float2 a = *(const float2*)(Po + base0 * 64 + 2 * lane);
    const float2 c = *(const float2*)(Po + base1 * 64 + 2 * lane);
    *(__half2*)(O + (size_t)(b * SEQ + r) * TDIM + h * 64 + 2 * lane) =
        __floats2half2_rn((a.x * f0 + c.x * f1) * inv, (a.y * f0 + c.y * f1) * inv);
}

// ---------------------------------------------------------------------------
__global__ void conv16(const float* __restrict__ s, __half* __restrict__ d, int n4)
{
    for (int i = blockIdx.x * blockDim.x + threadIdx.x; i < n4; i += gridDim.x * blockDim.x) {
        const float4 v = ((const float4*)s)[i];
        ((__half2*)d)[2 * i]     = __floats2half2_rn(v.x, v.y);
        ((__half2*)d)[2 * i + 1] = __floats2half2_rn(v.z, v.w);
    }
}

__global__ void prep_kernel(const int* __restrict__ ids, const float* __restrict__ emb,
                            float* __restrict__ x, float2* __restrict__ tab,
                            const float* __restrict__ Wu, __half* __restrict__ wu16)
{
    if (blockIdx.x < NROWS) {
        ((float4*)(x + (size_t)blockIdx.x * DMODEL))[threadIdx.x] =
            ((const float4*)(emb + (size_t)ids[blockIdx.x] * DMODEL))[threadIdx.x];
    } else if (blockIdx.x < NROWS + 128) {
        const int idx = (blockIdx.x - NROWS) * 256 + threadIdx.x;
        const int s = idx >> 5, i = idx & 31;
        const float inv = exp2f(-(float)(2 * i) * (1.0f / 64.0f) * 13.287712379549449f);
        float sn, cs;
        sincosf((float)s * inv, &sn, &cs);
        tab[idx] = make_float2(cs, sn);
    } else {
        const int n4 = NLAYER * 3 * TDIM * DMODEL / 4;
        for (int i = (blockIdx.x - NROWS - 128) * 256 + threadIdx.x; i < n4; i += 2048 * 256) {
            const float4 v = ((const float4*)Wu)[i];
            ((__half2*)wu16)[2 * i]     = __floats2half2_rn(v.x, v.y);
            ((__half2*)wu16)[2 * i + 1] = __floats2half2_rn(v.z, v.w);
        }
    }
}

extern "C" void kernel_launch(void* const* d_in, const int* in_sizes, int n_in,
                              void* d_out, int out_size)
{
    (void)in_sizes; (void)n_in; (void)out_size;

    const int*   ids = (const int*)  d_in[0];
    const float* emb = (const float*)d_in[1];
    const float* Wu  = (const float*)d_in[2];
    const float* Wo  = (const float*)d_in[3];
    const float* n1w = (const float*)d_in[4];
    const float* n1b = (const float*)d_in[5];
    const float* n2w = (const float*)d_in[6];
    const float* n2b = (const float*)d_in[7];
    const float* f1w = (const float*)d_in[8];
    const float* f1b = (const float*)d_in[9];
    const float* f2w = (const float*)d_in[10];
    const float* f2b = (const float*)d_in[11];
    const float* fnw = (const float*)d_in[12];
    const float* fnb = (const float*)d_in[13];
    float* out = (float*)d_out;

    float *x, *part, *attp, *attml; float2* tab;
    __half *u16, *xn16, *at16, *h16, *w16;
    cudaGetSymbolAddress((void**)&x,     g_x);
    cudaGetSymbolAddress((void**)&part,  g_part);
    cudaGetSymbolAddress((void**)&attp,  g_attp);
    cudaGetSymbolAddress((void**)&attml, g_attml);
    cudaGetSymbolAddress((void**)&tab,   g_rope);
    cudaGetSymbolAddress((void**)&u16,   g_u16);
    cudaGetSymbolAddress((void**)&xn16,  g_xn16);
    cudaGetSymbolAddress((void**)&at16,  g_at16);
    cudaGetSymbolAddress((void**)&h16,   g_h16);
    cudaGetSymbolAddress((void**)&w16,   g_w16);

    cudaFuncSetAttribute((gemm_f16<0,1>), cudaFuncAttributeMaxDynamicSharedMemorySize, GEMM_SMEM);
    cudaFuncSetAttribute((gemm_f16<1,0>), cudaFuncAttributeMaxDynamicSharedMemorySize, GEMM_SMEM);
    cudaFuncSetAttribute((gemm_f16<3,0>), cudaFuncAttributeMaxDynamicSharedMemorySize, GEMM_SMEM);
    cudaFuncSetAttribute(gemm_sk,         cudaFuncAttributeMaxDynamicSharedMemorySize, GEMM_SMEM);
    cudaFuncSetAttribute(attn_mma,        cudaFuncAttributeMaxDynamicSharedMemorySize, ATTN_SMEM);

    static cudaStream_t s2 = nullptr;
    static cudaEvent_t evF = nullptr, evD = nullptr;
    if (!s2) {
        cudaStreamCreateWithFlags(&s2, cudaStreamNonBlocking);
        cudaEventCreateWithFlags(&evF, cudaEventDisableTiming);
        cudaEventCreateWithFlags(&evD, cudaEventDisableTiming);
    }

    // main: prep(1), LN(2), QKV(3), attn(4 = ncu anchor), comb(5)
    prep_kernel<<<NROWS + 128 + 2048, 256>>>(ids, emb, x, tab, Wu, w16 + WU16);
    layernorm_kernel<<<NROWS / 8, 256>>>(x, n1w, n1b, xn16);
    gemm_f16<3,0><<<dim3(3 * TDIM / 128, NROWS / 128), 256, GEMM_SMEM>>>(
        xn16, w16 + WU16, nullptr, nullptr, u16, tab, 3 * TDIM, DMODEL);
    cudaEventRecord(evF, 0);
    attn_mma<<<dim3(12, NHEAD, BATCH), 256, ATTN_SMEM>>>(u16, at16, attp, attml);
    attn_comb<<<2048, 256>>>(attp, attml, at16);

    // side stream: all remaining weight conversions (emb included) overlap attn
    cudaStreamWaitEvent(s2, evF, 0);
    conv16<<<2048, 256, 0, s2>>>(Wo,  w16 + WO16,  NLAYER * DMODEL * TDIM / 4);
    conv16<<<2048, 256, 0, s2>>>(f1w, w16 + F116,  NLAYER * FFDIM * DMODEL / 4);
    conv16<<<2048, 256, 0, s2>>>(f2w, w16 + F216,  NLAYER * DMODEL * FFDIM / 4);
    conv16<<<2048, 256, 0, s2>>>(emb, w16 + EMB16, VOCAB * DMODEL / 4);
    cudaEventRecord(evD, s2);
    cudaStreamWaitEvent(0, evD, 0);

    for (int l = 0; l < NLAYER; l++) {
        const __half* Wu_l = w16 + WU16 + (size_t)(l + 1) * 3 * TDIM * DMODEL;
        const __half* Wo_l = w16 + WO16 + (size_t)l * DMODEL * TDIM;
        const __half* f1_l = w16 + F116 + (size_t)l * FFDIM * DMODEL;
        const __half* f2_l = w16 + F216 + (size_t)l * DMODEL * FFDIM;

        gemm_sk<<<dim3(DMODEL / 128, NROWS / 128, 2), 256, GEMM_SMEM>>>(
            at16, Wo_l, part, DMODEL, TDIM);
        reduce_ln<<<NROWS / 8, 256>>>(part, nullptr, x,
                                      n2w + l * DMODEL, n2b + l * DMODEL, xn16);

        gemm_f16<1,0><<<dim3(FFDIM / 128, NROWS / 128), 256, GEMM_SMEM>>>(
            xn16, f1_l, f1b + (size_t)l * FFDIM, nullptr, h16, nullptr, FFDIM, DMODEL);

        gemm_sk<<<dim3(DMODEL / 128, NROWS / 128, 2), 256, GEMM_SMEM>>>(
            h16, f2_l, part, DMODEL, FFDIM);
        if (l + 1 < NLAYER) {
            reduce_ln<<<NROWS / 8, 256>>>(part, f2b + (size_t)l * DMODEL, x,
                                          n1w + (l + 1) * DMODEL, n1b + (l + 1) * DMODEL, xn16);
            gemm_f16<3,0><<<dim3(3 * TDIM / 128, NROWS / 128), 256, GEMM_SMEM>>>(
                xn16, Wu_l, nullptr, nullptr, u16, tab, 3 * TDIM, DMODEL);
            attn_mma<<<dim3(12, NHEAD, BATCH), 256, ATTN_SMEM>>>(u16, at16, attp, attml);
            attn_comb<<<2048, 256>>>(attp, attml, at16);
        } else {
            reduce_ln<<<NROWS / 8, 256>>>(part, f2b + (size_t)l * DMODEL, x,
                                          fnw, fnb, xn16);
        }
    }

    gemm_f16<0,1><<<dim3(NROWS / 128, VOCAB / 128), 256, GEMM_SMEM>>>(
        xn16, w16 + EMB16, nullptr, out, nullptr, nullptr, VOCAB, DMODEL);
}